// round 1
// baseline (speedup 1.0000x reference)
#include <cuda_runtime.h>
#include <math.h>

#define LSEQ 256
#define EDIM 128
#define NH 4
#define CD 32
#define RROWS (LSEQ*LSEQ)   // 65536

// ---------------- scratch (device globals; no allocs allowed) ----------------
__device__ float g_x [RROWS*EDIM];
__device__ float g_q [RROWS*EDIM];   // pre-scaled by C^-0.5  (the "v-indexed" operand)
__device__ float g_k [RROWS*EDIM];   // the "q-indexed" operand
__device__ float g_v [RROWS*EDIM];
__device__ float g_fu[RROWS*EDIM];   // sigmoid(x@Wfu + bfu)
__device__ float g_mb[NH*RROWS];     // mb[h][q*256+v] = mask[q,v] + bias[q,v,h]
__device__ float g_ao[RROWS*EDIM];   // gated attention output
__device__ float g_W [EDIM*512];     // packed Wq|Wk|Wv|Wfu

// ---------------- kernel: pack weights ----------------
__global__ void pack_w_kernel(const float* __restrict__ Wq, const float* __restrict__ Wk,
                              const float* __restrict__ Wv, const float* __restrict__ Wfu)
{
    int idx = blockIdx.x * blockDim.x + threadIdx.x;   // E*512 total
    int k = idx >> 9, n = idx & 511;
    const float* src = (n < 128) ? Wq : (n < 256) ? Wk : (n < 384) ? Wv : Wfu;
    g_W[idx] = src[k * 128 + (n & 127)];
}

// ---------------- kernel: layernorm + pair_bias(+mask) ----------------
__global__ void __launch_bounds__(128) ln_kernel(
    const float* __restrict__ pr, const float* __restrict__ mask,
    const float* __restrict__ gamma, const float* __restrict__ beta,
    const float* __restrict__ Wb)
{
    int r = blockIdx.x;           // row over (i,j)
    int t = threadIdx.x;          // 0..127 = E index
    float v = pr[(size_t)r * EDIM + t];

    float s = v, s2 = v * v;
    #pragma unroll
    for (int o = 16; o; o >>= 1) {
        s  += __shfl_xor_sync(0xffffffffu, s,  o);
        s2 += __shfl_xor_sync(0xffffffffu, s2, o);
    }
    __shared__ float sh[8];
    int w = t >> 5, lane = t & 31;
    if (lane == 0) { sh[w] = s; sh[4 + w] = s2; }
    __syncthreads();
    s  = sh[0] + sh[1] + sh[2] + sh[3];
    s2 = sh[4] + sh[5] + sh[6] + sh[7];
    float mu  = s * (1.0f / EDIM);
    float var = s2 * (1.0f / EDIM) - mu * mu;
    float x = (v - mu) * rsqrtf(var + 1e-5f) * gamma[t] + beta[t];
    g_x[(size_t)r * EDIM + t] = x;

    // pair_bias: 4 dot products of length 128
    float b0 = x * Wb[t * 4 + 0];
    float b1 = x * Wb[t * 4 + 1];
    float b2 = x * Wb[t * 4 + 2];
    float b3 = x * Wb[t * 4 + 3];
    #pragma unroll
    for (int o = 16; o; o >>= 1) {
        b0 += __shfl_xor_sync(0xffffffffu, b0, o);
        b1 += __shfl_xor_sync(0xffffffffu, b1, o);
        b2 += __shfl_xor_sync(0xffffffffu, b2, o);
        b3 += __shfl_xor_sync(0xffffffffu, b3, o);
    }
    __shared__ float shb[16];
    if (lane == 0) { shb[w*4+0]=b0; shb[w*4+1]=b1; shb[w*4+2]=b2; shb[w*4+3]=b3; }
    __syncthreads();
    if (t < 4) {
        float b = shb[t] + shb[4 + t] + shb[8 + t] + shb[12 + t];
        g_mb[t * RROWS + r] = mask[r] + b;
    }
}

// ---------------- kernel: projection GEMM [65536x128]x[128x512] ----------------
// blockIdx.x = m-tile (128 rows), blockIdx.y = n-tile (selects q/k/v/fu)
__global__ void __launch_bounds__(256) gemm_proj_kernel(const float* __restrict__ bfu)
{
    extern __shared__ float sm[];
    float* Ast = sm;                 // [k=128][m=128]  (A transposed)
    float* Bs  = sm + 128 * 128;     // [k=128][n=128]

    int m0 = blockIdx.x * 128;
    int nt = blockIdx.y;             // 0:q 1:k 2:v 3:fu
    int n0 = nt * 128;
    int tid = threadIdx.x;

    // load A (g_x) transposed into smem
    {
        int r = tid & 127, kc0 = tid >> 7;
        #pragma unroll
        for (int c = kc0; c < 32; c += 2) {
            float4 a = *(const float4*)&g_x[(size_t)(m0 + r) * EDIM + c * 4];
            Ast[(c * 4 + 0) * 128 + r] = a.x;
            Ast[(c * 4 + 1) * 128 + r] = a.y;
            Ast[(c * 4 + 2) * 128 + r] = a.z;
            Ast[(c * 4 + 3) * 128 + r] = a.w;
        }
    }
    // load B tile
    {
        int n4 = tid & 31, k0 = tid >> 5;
        #pragma unroll
        for (int k = k0; k < 128; k += 8)
            *(float4*)&Bs[k * 128 + n4 * 4] = *(const float4*)&g_W[k * 512 + n0 + n4 * 4];
    }
    __syncthreads();

    int tx = tid & 15, ty = tid >> 4;
    float acc[8][8];
    #pragma unroll
    for (int i = 0; i < 8; i++)
        #pragma unroll
        for (int j = 0; j < 8; j++) acc[i][j] = 0.0f;

    #pragma unroll 8
    for (int k = 0; k < 128; k++) {
        float4 a0 = *(float4*)&Ast[k * 128 + ty * 4];
        float4 a1 = *(float4*)&Ast[k * 128 + 64 + ty * 4];
        float4 b0 = *(float4*)&Bs [k * 128 + tx * 4];
        float4 b1 = *(float4*)&Bs [k * 128 + 64 + tx * 4];
        float av[8] = {a0.x,a0.y,a0.z,a0.w,a1.x,a1.y,a1.z,a1.w};
        float bv[8] = {b0.x,b0.y,b0.z,b0.w,b1.x,b1.y,b1.z,b1.w};
        #pragma unroll
        for (int i = 0; i < 8; i++)
            #pragma unroll
            for (int j = 0; j < 8; j++) acc[i][j] += av[i] * bv[j];
    }

    float* dst = (nt == 0) ? g_q : (nt == 1) ? g_k : (nt == 2) ? g_v : g_fu;
    const float qscale = 0.17677669529663687f;   // 32^-0.5
    #pragma unroll
    for (int i = 0; i < 8; i++) {
        int m = m0 + ((i < 4) ? (ty * 4 + i) : (64 + ty * 4 + i - 4));
        #pragma unroll
        for (int j = 0; j < 8; j++) {
            int n = (j < 4) ? (tx * 4 + j) : (64 + tx * 4 + j - 4);
            float vv = acc[i][j];
            if (nt == 0) vv *= qscale;
            if (nt == 3) vv = 1.0f / (1.0f + __expf(-(vv + bfu[n])));
            dst[(size_t)m * EDIM + n] = vv;
        }
    }
}

// ---------------- kernel: attention per (s,h) ----------------
// block = 256 threads; smem: KK[256][32], QQT[32][256], VV[256][32], PT[8 warps][2][256]
__global__ void __launch_bounds__(256) attn_kernel()
{
    extern __shared__ float sm[];
    float* KK  = sm;                     // 8192
    float* QQT = KK  + 256 * 32;         // 8192
    float* VV  = QQT + 32 * 256;         // 8192
    float* PT  = VV  + 256 * 32;         // 8 * 2 * 256 = 4096

    int s = blockIdx.x >> 2;
    int h = blockIdx.x & 3;
    int tid = threadIdx.x;
    size_t base = (size_t)s * 256 * EDIM + h * CD;

    // load K rows and V rows (h-slice, 32 floats each)
    {
        int c4 = tid & 7, r0 = tid >> 3;
        for (int rr = r0; rr < 256; rr += 32) {
            *(float4*)&KK[rr * 32 + c4 * 4] = *(const float4*)&g_k[base + (size_t)rr * EDIM + c4 * 4];
            *(float4*)&VV[rr * 32 + c4 * 4] = *(const float4*)&g_v[base + (size_t)rr * EDIM + c4 * 4];
        }
    }
    // load Q (v-indexed, pre-scaled) transposed: QQT[c][vi]
    {
        int vi = tid;
        #pragma unroll
        for (int c4 = 0; c4 < 8; c4++) {
            float4 q4 = *(const float4*)&g_q[base + (size_t)vi * EDIM + c4 * 4];
            QQT[(c4 * 4 + 0) * 256 + vi] = q4.x;
            QQT[(c4 * 4 + 1) * 256 + vi] = q4.y;
            QQT[(c4 * 4 + 2) * 256 + vi] = q4.z;
            QQT[(c4 * 4 + 3) * 256 + vi] = q4.w;
        }
    }
    __syncthreads();

    int lane = tid & 31, wy = tid >> 5;          // warp owns 2 query rows per chunk
    const float* mb = g_mb + (size_t)h * RROWS;
    float* PTw = PT + wy * 512;                  // warp-private [2][256]

    for (int q0 = 0; q0 < 256; q0 += 16) {
        int qi0 = q0 + wy * 2, qi1 = qi0 + 1;

        // scores: vi = t*32 + lane, t in 0..7
        float sc0[8], sc1[8];
        #pragma unroll
        for (int t = 0; t < 8; t++) { sc0[t] = 0.0f; sc1[t] = 0.0f; }
        #pragma unroll
        for (int c = 0; c < 32; c++) {
            float k0 = KK[qi0 * 32 + c];
            float k1 = KK[qi1 * 32 + c];
            #pragma unroll
            for (int t = 0; t < 8; t++) {
                float qv = QQT[c * 256 + t * 32 + lane];
                sc0[t] += k0 * qv;
                sc1[t] += k1 * qv;
            }
        }
        #pragma unroll
        for (int t = 0; t < 8; t++) {
            sc0[t] += mb[qi0 * 256 + t * 32 + lane];
            sc1[t] += mb[qi1 * 256 + t * 32 + lane];
        }

        // warp-local softmax over 256 keys per row
        float mx0 = -1e30f, mx1 = -1e30f;
        #pragma unroll
        for (int t = 0; t < 8; t++) { mx0 = fmaxf(mx0, sc0[t]); mx1 = fmaxf(mx1, sc1[t]); }
        #pragma unroll
        for (int o = 16; o; o >>= 1) {
            mx0 = fmaxf(mx0, __shfl_xor_sync(0xffffffffu, mx0, o));
            mx1 = fmaxf(mx1, __shfl_xor_sync(0xffffffffu, mx1, o));
        }
        float sum0 = 0.0f, sum1 = 0.0f;
        #pragma unroll
        for (int t = 0; t < 8; t++) {
            sc0[t] = __expf(sc0[t] - mx0); sum0 += sc0[t];
            sc1[t] = __expf(sc1[t] - mx1); sum1 += sc1[t];
        }
        #pragma unroll
        for (int o = 16; o; o >>= 1) {
            sum0 += __shfl_xor_sync(0xffffffffu, sum0, o);
            sum1 += __shfl_xor_sync(0xffffffffu, sum1, o);
        }
        float inv0 = 1.0f / sum0, inv1 = 1.0f / sum1;

        #pragma unroll
        for (int t = 0; t < 8; t++) {
            PTw[0 * 256 + t * 32 + lane] = sc0[t] * inv0;
            PTw[1 * 256 + t * 32 + lane] = sc1[t] * inv1;
        }
        __syncwarp();

        // AV: out[qi][c], thread: c = lane
        float o0 = 0.0f, o1 = 0.0f;
        #pragma unroll 8
        for (int vi = 0; vi < 256; vi++) {
            float vvv = VV[vi * 32 + lane];
            o0 += PTw[vi] * vvv;
            o1 += PTw[256 + vi] * vvv;
        }

        size_t i0 = base + (size_t)qi0 * EDIM + lane;
        size_t i1 = base + (size_t)qi1 * EDIM + lane;
        g_ao[i0] = o0 * g_fu[i0];
        g_ao[i1] = o1 * g_fu[i1];
        __syncwarp();
    }
}

// ---------------- kernel: output GEMM [65536x128]x[128x128] + bo ----------------
__global__ void __launch_bounds__(256) gemm_out_kernel(
    const float* __restrict__ Wo, const float* __restrict__ bo, float* __restrict__ out)
{
    extern __shared__ float sm[];
    float* Ast = sm;
    float* Bs  = sm + 128 * 128;

    int m0 = blockIdx.x * 128;
    int tid = threadIdx.x;

    {
        int r = tid & 127, kc0 = tid >> 7;
        #pragma unroll
        for (int c = kc0; c < 32; c += 2) {
            float4 a = *(const float4*)&g_ao[(size_t)(m0 + r) * EDIM + c * 4];
            Ast[(c * 4 + 0) * 128 + r] = a.x;
            Ast[(c * 4 + 1) * 128 + r] = a.y;
            Ast[(c * 4 + 2) * 128 + r] = a.z;
            Ast[(c * 4 + 3) * 128 + r] = a.w;
        }
    }
    {
        int n4 = tid & 31, k0 = tid >> 5;
        #pragma unroll
        for (int k = k0; k < 128; k += 8)
            *(float4*)&Bs[k * 128 + n4 * 4] = *(const float4*)&Wo[k * 128 + n4 * 4];
    }
    __syncthreads();

    int tx = tid & 15, ty = tid >> 4;
    float acc[8][8];
    #pragma unroll
    for (int i = 0; i < 8; i++)
        #pragma unroll
        for (int j = 0; j < 8; j++) acc[i][j] = 0.0f;

    #pragma unroll 8
    for (int k = 0; k < 128; k++) {
        float4 a0 = *(float4*)&Ast[k * 128 + ty * 4];
        float4 a1 = *(float4*)&Ast[k * 128 + 64 + ty * 4];
        float4 b0 = *(float4*)&Bs [k * 128 + tx * 4];
        float4 b1 = *(float4*)&Bs [k * 128 + 64 + tx * 4];
        float av[8] = {a0.x,a0.y,a0.z,a0.w,a1.x,a1.y,a1.z,a1.w};
        float bv[8] = {b0.x,b0.y,b0.z,b0.w,b1.x,b1.y,b1.z,b1.w};
        #pragma unroll
        for (int i = 0; i < 8; i++)
            #pragma unroll
            for (int j = 0; j < 8; j++) acc[i][j] += av[i] * bv[j];
    }

    #pragma unroll
    for (int i = 0; i < 8; i++) {
        int m = m0 + ((i < 4) ? (ty * 4 + i) : (64 + ty * 4 + i - 4));
        #pragma unroll
        for (int j = 0; j < 8; j++) {
            int n = (j < 4) ? (tx * 4 + j) : (64 + tx * 4 + j - 4);
            out[(size_t)m * EDIM + n] = acc[i][j] + bo[n];
        }
    }
}

// ---------------- host launch ----------------
extern "C" void kernel_launch(void* const* d_in, const int* in_sizes, int n_in,
                              void* d_out, int out_size)
{
    const float* pair_rep = (const float*)d_in[0];
    const float* mask     = (const float*)d_in[1];
    const float* gamma    = (const float*)d_in[2];
    const float* beta     = (const float*)d_in[3];
    const float* Wq       = (const float*)d_in[4];
    const float* Wk       = (const float*)d_in[5];
    const float* Wv       = (const float*)d_in[6];
    const float* Wb       = (const float*)d_in[7];
    const float* Wfu      = (const float*)d_in[8];
    const float* bfu      = (const float*)d_in[9];
    const float* Wo       = (const float*)d_in[10];
    const float* bo       = (const float*)d_in[11];
    float* out = (float*)d_out;

    const int GEMM_SMEM = 2 * 128 * 128 * (int)sizeof(float);          // 128 KB
    const int ATTN_SMEM = (3 * 256 * 32 + 8 * 2 * 256) * (int)sizeof(float); // 112 KB
    cudaFuncSetAttribute(gemm_proj_kernel, cudaFuncAttributeMaxDynamicSharedMemorySize, GEMM_SMEM);
    cudaFuncSetAttribute(gemm_out_kernel,  cudaFuncAttributeMaxDynamicSharedMemorySize, GEMM_SMEM);
    cudaFuncSetAttribute(attn_kernel,      cudaFuncAttributeMaxDynamicSharedMemorySize, ATTN_SMEM);

    pack_w_kernel<<<(EDIM * 512) / 256, 256>>>(Wq, Wk, Wv, Wfu);
    ln_kernel<<<RROWS, 128>>>(pair_rep, mask, gamma, beta, Wb);
    gemm_proj_kernel<<<dim3(RROWS / 128, 4), 256, GEMM_SMEM>>>(bfu);
    attn_kernel<<<LSEQ * NH, 256, ATTN_SMEM>>>();
    gemm_out_kernel<<<RROWS / 128, 256, GEMM_SMEM>>>(Wo, bo, out);
}

// round 2
// speedup vs baseline: 1.0376x; 1.0376x over previous
#include <cuda_runtime.h>
#include <math.h>

#define LSEQ 256
#define EDIM 128
#define NH 4
#define CD 32
#define RROWS (LSEQ*LSEQ)   // 65536

// ---------------- scratch (device globals; no allocs allowed) ----------------
__device__ float g_x [RROWS*EDIM];
__device__ float g_q [RROWS*EDIM];   // pre-scaled by C^-0.5  (the "v-indexed" operand)
__device__ float g_k [RROWS*EDIM];   // the "q-indexed" operand
__device__ float g_v [RROWS*EDIM];
__device__ float g_fu[RROWS*EDIM];   // sigmoid(x@Wfu + bfu)
__device__ float g_mb[NH*RROWS];     // mb[h][q*256+v] = mask[q,v] + bias[q,v,h]
__device__ float g_ao[RROWS*EDIM];   // gated attention output
__device__ float g_W [EDIM*512];     // packed Wq|Wk|Wv|Wfu

// ---------------- kernel: pack weights ----------------
__global__ void pack_w_kernel(const float* __restrict__ Wq, const float* __restrict__ Wk,
                              const float* __restrict__ Wv, const float* __restrict__ Wfu)
{
    int idx = blockIdx.x * blockDim.x + threadIdx.x;   // E*512 total
    int k = idx >> 9, n = idx & 511;
    const float* src = (n < 128) ? Wq : (n < 256) ? Wk : (n < 384) ? Wv : Wfu;
    g_W[idx] = src[k * 128 + (n & 127)];
}

// ---------------- kernel: layernorm + pair_bias(+mask) ----------------
__global__ void __launch_bounds__(128) ln_kernel(
    const float* __restrict__ pr, const float* __restrict__ mask,
    const float* __restrict__ gamma, const float* __restrict__ beta,
    const float* __restrict__ Wb)
{
    int r = blockIdx.x;           // row over (i,j)
    int t = threadIdx.x;          // 0..127 = E index
    float v = pr[(size_t)r * EDIM + t];

    float s = v, s2 = v * v;
    #pragma unroll
    for (int o = 16; o; o >>= 1) {
        s  += __shfl_xor_sync(0xffffffffu, s,  o);
        s2 += __shfl_xor_sync(0xffffffffu, s2, o);
    }
    __shared__ float sh[8];
    int w = t >> 5, lane = t & 31;
    if (lane == 0) { sh[w] = s; sh[4 + w] = s2; }
    __syncthreads();
    s  = sh[0] + sh[1] + sh[2] + sh[3];
    s2 = sh[4] + sh[5] + sh[6] + sh[7];
    float mu  = s * (1.0f / EDIM);
    float var = s2 * (1.0f / EDIM) - mu * mu;
    float x = (v - mu) * rsqrtf(var + 1e-5f) * gamma[t] + beta[t];
    g_x[(size_t)r * EDIM + t] = x;

    // pair_bias: 4 dot products of length 128
    float b0 = x * Wb[t * 4 + 0];
    float b1 = x * Wb[t * 4 + 1];
    float b2 = x * Wb[t * 4 + 2];
    float b3 = x * Wb[t * 4 + 3];
    #pragma unroll
    for (int o = 16; o; o >>= 1) {
        b0 += __shfl_xor_sync(0xffffffffu, b0, o);
        b1 += __shfl_xor_sync(0xffffffffu, b1, o);
        b2 += __shfl_xor_sync(0xffffffffu, b2, o);
        b3 += __shfl_xor_sync(0xffffffffu, b3, o);
    }
    __shared__ float shb[16];
    if (lane == 0) { shb[w*4+0]=b0; shb[w*4+1]=b1; shb[w*4+2]=b2; shb[w*4+3]=b3; }
    __syncthreads();
    if (t < 4) {
        float b = shb[t] + shb[4 + t] + shb[8 + t] + shb[12 + t];
        g_mb[t * RROWS + r] = mask[r] + b;
    }
}

// ---------------- kernel: projection GEMM [65536x128]x[128x512] ----------------
__global__ void __launch_bounds__(256) gemm_proj_kernel(const float* __restrict__ bfu)
{
    extern __shared__ float sm[];
    float* Ast = sm;                 // [k=128][m=128]  (A transposed)
    float* Bs  = sm + 128 * 128;     // [k=128][n=128]

    int m0 = blockIdx.x * 128;
    int nt = blockIdx.y;             // 0:q 1:k 2:v 3:fu
    int n0 = nt * 128;
    int tid = threadIdx.x;

    {
        int r = tid & 127, kc0 = tid >> 7;
        #pragma unroll
        for (int c = kc0; c < 32; c += 2) {
            float4 a = *(const float4*)&g_x[(size_t)(m0 + r) * EDIM + c * 4];
            Ast[(c * 4 + 0) * 128 + r] = a.x;
            Ast[(c * 4 + 1) * 128 + r] = a.y;
            Ast[(c * 4 + 2) * 128 + r] = a.z;
            Ast[(c * 4 + 3) * 128 + r] = a.w;
        }
    }
    {
        int n4 = tid & 31, k0 = tid >> 5;
        #pragma unroll
        for (int k = k0; k < 128; k += 8)
            *(float4*)&Bs[k * 128 + n4 * 4] = *(const float4*)&g_W[k * 512 + n0 + n4 * 4];
    }
    __syncthreads();

    int tx = tid & 15, ty = tid >> 4;
    float acc[8][8];
    #pragma unroll
    for (int i = 0; i < 8; i++)
        #pragma unroll
        for (int j = 0; j < 8; j++) acc[i][j] = 0.0f;

    #pragma unroll 8
    for (int k = 0; k < 128; k++) {
        float4 a0 = *(float4*)&Ast[k * 128 + ty * 4];
        float4 a1 = *(float4*)&Ast[k * 128 + 64 + ty * 4];
        float4 b0 = *(float4*)&Bs [k * 128 + tx * 4];
        float4 b1 = *(float4*)&Bs [k * 128 + 64 + tx * 4];
        float av[8] = {a0.x,a0.y,a0.z,a0.w,a1.x,a1.y,a1.z,a1.w};
        float bv[8] = {b0.x,b0.y,b0.z,b0.w,b1.x,b1.y,b1.z,b1.w};
        #pragma unroll
        for (int i = 0; i < 8; i++)
            #pragma unroll
            for (int j = 0; j < 8; j++) acc[i][j] += av[i] * bv[j];
    }

    float* dst = (nt == 0) ? g_q : (nt == 1) ? g_k : (nt == 2) ? g_v : g_fu;
    const float qscale = 0.17677669529663687f;   // 32^-0.5
    #pragma unroll
    for (int i = 0; i < 8; i++) {
        int m = m0 + ((i < 4) ? (ty * 4 + i) : (64 + ty * 4 + i - 4));
        #pragma unroll
        for (int j = 0; j < 8; j++) {
            int n = (j < 4) ? (tx * 4 + j) : (64 + tx * 4 + j - 4);
            float vv = acc[i][j];
            if (nt == 0) vv *= qscale;
            if (nt == 3) vv = 1.0f / (1.0f + __expf(-(vv + bfu[n])));
            dst[(size_t)m * EDIM + n] = vv;
        }
    }
}

// ---------------- kernel: attention per (s,h), register-tiled ----------------
// 256 threads. smem: Kt[32][256], Qt[32][256], V[256][32], P[64][256] = 160 KB.
// Scores done in 64-query chunks as a 64x256x32 register-tiled GEMM (8x8/thread),
// warp-local softmax (warp = 8 query rows x all 256 keys), P warp-private,
// AV as 8x32-per-warp register GEMM with float4 P broadcasts.
__global__ void __launch_bounds__(256, 1) attn_kernel()
{
    extern __shared__ float sm[];
    float* Kt = sm;                  // [c=32][q=256]
    float* Qt = Kt + 32 * 256;       // [c=32][v=256]
    float* VV = Qt + 32 * 256;       // [v=256][c=32]
    float* P  = VV + 256 * 32;       // [64][256]

    int s = blockIdx.x >> 2;
    int h = blockIdx.x & 3;
    int tid = threadIdx.x;
    size_t base = (size_t)s * 256 * EDIM + h * CD;

    // K, Q transposed into smem (thread = one row; scalar STS conflict-free)
    {
        int r = tid;
        #pragma unroll
        for (int c4 = 0; c4 < 8; c4++) {
            float4 k4 = *(const float4*)&g_k[base + (size_t)r * EDIM + c4 * 4];
            Kt[(c4 * 4 + 0) * 256 + r] = k4.x;
            Kt[(c4 * 4 + 1) * 256 + r] = k4.y;
            Kt[(c4 * 4 + 2) * 256 + r] = k4.z;
            Kt[(c4 * 4 + 3) * 256 + r] = k4.w;
            float4 q4 = *(const float4*)&g_q[base + (size_t)r * EDIM + c4 * 4];
            Qt[(c4 * 4 + 0) * 256 + r] = q4.x;
            Qt[(c4 * 4 + 1) * 256 + r] = q4.y;
            Qt[(c4 * 4 + 2) * 256 + r] = q4.z;
            Qt[(c4 * 4 + 3) * 256 + r] = q4.w;
        }
    }
    // V direct (row-major [256][32]); c4-major thread map keeps STS coalesced
    {
        int c4 = tid & 7, r0 = tid >> 3;
        #pragma unroll
        for (int rr = r0; rr < 256; rr += 32)
            *(float4*)&VV[rr * 32 + c4 * 4] = *(const float4*)&g_v[base + (size_t)rr * EDIM + c4 * 4];
    }
    __syncthreads();

    int tx = tid & 31;       // key/value dim: v in {tx*4+j, 128+tx*4+j}
    int ty = tid >> 5;       // warp id = query group
    const float* mb = g_mb + (size_t)h * RROWS;

    // this warp's 8 chunk-local query rows: ty*4+i (i<4) and 32+ty*4+(i-4)
    for (int q0 = 0; q0 < 256; q0 += 64) {
        float acc[8][8];
        #pragma unroll
        for (int i = 0; i < 8; i++)
            #pragma unroll
            for (int j = 0; j < 8; j++) acc[i][j] = 0.0f;

        // scores GEMM: 64x256x32
        #pragma unroll 4
        for (int c = 0; c < 32; c++) {
            float4 a0 = *(float4*)&Kt[c * 256 + q0 + ty * 4];        // broadcast
            float4 a1 = *(float4*)&Kt[c * 256 + q0 + 32 + ty * 4];   // broadcast
            float4 b0 = *(float4*)&Qt[c * 256 + tx * 4];
            float4 b1 = *(float4*)&Qt[c * 256 + 128 + tx * 4];
            float av[8] = {a0.x,a0.y,a0.z,a0.w,a1.x,a1.y,a1.z,a1.w};
            float bv[8] = {b0.x,b0.y,b0.z,b0.w,b1.x,b1.y,b1.z,b1.w};
            #pragma unroll
            for (int i = 0; i < 8; i++)
                #pragma unroll
                for (int j = 0; j < 8; j++) acc[i][j] += av[i] * bv[j];
        }

        // add mask+bias, softmax per row (warp-local), stage P
        #pragma unroll
        for (int i = 0; i < 8; i++) {
            int lq = (i < 4) ? (ty * 4 + i) : (32 + ty * 4 + (i - 4));
            int qi = q0 + lq;
            const float* mrow = mb + (size_t)qi * 256;
            float4 m0 = __ldg((const float4*)&mrow[tx * 4]);
            float4 m1 = __ldg((const float4*)&mrow[128 + tx * 4]);
            acc[i][0] += m0.x; acc[i][1] += m0.y; acc[i][2] += m0.z; acc[i][3] += m0.w;
            acc[i][4] += m1.x; acc[i][5] += m1.y; acc[i][6] += m1.z; acc[i][7] += m1.w;

            float mx = acc[i][0];
            #pragma unroll
            for (int j = 1; j < 8; j++) mx = fmaxf(mx, acc[i][j]);
            #pragma unroll
            for (int o = 16; o; o >>= 1) mx = fmaxf(mx, __shfl_xor_sync(0xffffffffu, mx, o));
            float sum = 0.0f;
            #pragma unroll
            for (int j = 0; j < 8; j++) { acc[i][j] = __expf(acc[i][j] - mx); sum += acc[i][j]; }
            #pragma unroll
            for (int o = 16; o; o >>= 1) sum += __shfl_xor_sync(0xffffffffu, sum, o);
            float inv = 1.0f / sum;

            float4 p0 = make_float4(acc[i][0]*inv, acc[i][1]*inv, acc[i][2]*inv, acc[i][3]*inv);
            float4 p1 = make_float4(acc[i][4]*inv, acc[i][5]*inv, acc[i][6]*inv, acc[i][7]*inv);
            *(float4*)&P[lq * 256 + tx * 4] = p0;
            *(float4*)&P[lq * 256 + 128 + tx * 4] = p1;
        }
        __syncwarp();

        // AV: per warp out[8 rows][32 cols], lane = c
        int lane = tx;
        float o[8];
        #pragma unroll
        for (int i = 0; i < 8; i++) o[i] = 0.0f;

        #pragma unroll 4
        for (int vi = 0; vi < 256; vi += 4) {
            float v0 = VV[(vi + 0) * 32 + lane];
            float v1 = VV[(vi + 1) * 32 + lane];
            float v2 = VV[(vi + 2) * 32 + lane];
            float v3 = VV[(vi + 3) * 32 + lane];
            #pragma unroll
            for (int i = 0; i < 8; i++) {
                int lq = (i < 4) ? (ty * 4 + i) : (32 + ty * 4 + (i - 4));
                float4 p = *(float4*)&P[lq * 256 + vi];   // broadcast
                o[i] += p.x * v0 + p.y * v1 + p.z * v2 + p.w * v3;
            }
        }

        // gate with fu and store
        #pragma unroll
        for (int i = 0; i < 8; i++) {
            int lq = (i < 4) ? (ty * 4 + i) : (32 + ty * 4 + (i - 4));
            size_t idx = base + (size_t)(q0 + lq) * EDIM + lane;
            g_ao[idx] = o[i] * g_fu[idx];
        }
        __syncwarp();
    }
}

// ---------------- kernel: output GEMM [65536x128]x[128x128] + bo ----------------
__global__ void __launch_bounds__(256) gemm_out_kernel(
    const float* __restrict__ Wo, const float* __restrict__ bo, float* __restrict__ out)
{
    extern __shared__ float sm[];
    float* Ast = sm;
    float* Bs  = sm + 128 * 128;

    int m0 = blockIdx.x * 128;
    int tid = threadIdx.x;

    {
        int r = tid & 127, kc0 = tid >> 7;
        #pragma unroll
        for (int c = kc0; c < 32; c += 2) {
            float4 a = *(const float4*)&g_ao[(size_t)(m0 + r) * EDIM + c * 4];
            Ast[(c * 4 + 0) * 128 + r] = a.x;
            Ast[(c * 4 + 1) * 128 + r] = a.y;
            Ast[(c * 4 + 2) * 128 + r] = a.z;
            Ast[(c * 4 + 3) * 128 + r] = a.w;
        }
    }
    {
        int n4 = tid & 31, k0 = tid >> 5;
        #pragma unroll
        for (int k = k0; k < 128; k += 8)
            *(float4*)&Bs[k * 128 + n4 * 4] = *(const float4*)&Wo[k * 128 + n4 * 4];
    }
    __syncthreads();

    int tx = tid & 15, ty = tid >> 4;
    float acc[8][8];
    #pragma unroll
    for (int i = 0; i < 8; i++)
        #pragma unroll
        for (int j = 0; j < 8; j++) acc[i][j] = 0.0f;

    #pragma unroll 8
    for (int k = 0; k < 128; k++) {
        float4 a0 = *(float4*)&Ast[k * 128 + ty * 4];
        float4 a1 = *(float4*)&Ast[k * 128 + 64 + ty * 4];
        float4 b0 = *(float4*)&Bs [k * 128 + tx * 4];
        float4 b1 = *(float4*)&Bs [k * 128 + 64 + tx * 4];
        float av[8] = {a0.x,a0.y,a0.z,a0.w,a1.x,a1.y,a1.z,a1.w};
        float bv[8] = {b0.x,b0.y,b0.z,b0.w,b1.x,b1.y,b1.z,b1.w};
        #pragma unroll
        for (int i = 0; i < 8; i++)
            #pragma unroll
            for (int j = 0; j < 8; j++) acc[i][j] += av[i] * bv[j];
    }

    #pragma unroll
    for (int i = 0; i < 8; i++) {
        int m = m0 + ((i < 4) ? (ty * 4 + i) : (64 + ty * 4 + i - 4));
        #pragma unroll
        for (int j = 0; j < 8; j++) {
            int n = (j < 4) ? (tx * 4 + j) : (64 + tx * 4 + j - 4);
            out[(size_t)m * EDIM + n] = acc[i][j] + bo[n];
        }
    }
}

// ---------------- host launch ----------------
extern "C" void kernel_launch(void* const* d_in, const int* in_sizes, int n_in,
                              void* d_out, int out_size)
{
    const float* pair_rep = (const float*)d_in[0];
    const float* mask     = (const float*)d_in[1];
    const float* gamma    = (const float*)d_in[2];
    const float* beta     = (const float*)d_in[3];
    const float* Wq       = (const float*)d_in[4];
    const float* Wk       = (const float*)d_in[5];
    const float* Wv       = (const float*)d_in[6];
    const float* Wb       = (const float*)d_in[7];
    const float* Wfu      = (const float*)d_in[8];
    const float* bfu      = (const float*)d_in[9];
    const float* Wo       = (const float*)d_in[10];
    const float* bo       = (const float*)d_in[11];
    float* out = (float*)d_out;

    const int GEMM_SMEM = 2 * 128 * 128 * (int)sizeof(float);                 // 128 KB
    const int ATTN_SMEM = (2 * 32 * 256 + 256 * 32 + 64 * 256) * (int)sizeof(float); // 160 KB
    cudaFuncSetAttribute(gemm_proj_kernel, cudaFuncAttributeMaxDynamicSharedMemorySize, GEMM_SMEM);
    cudaFuncSetAttribute(gemm_out_kernel,  cudaFuncAttributeMaxDynamicSharedMemorySize, GEMM_SMEM);
    cudaFuncSetAttribute(attn_kernel,      cudaFuncAttributeMaxDynamicSharedMemorySize, ATTN_SMEM);

    pack_w_kernel<<<(EDIM * 512) / 256, 256>>>(Wq, Wk, Wv, Wfu);
    ln_kernel<<<RROWS, 128>>>(pair_rep, mask, gamma, beta, Wb);
    gemm_proj_kernel<<<dim3(RROWS / 128, 4), 256, GEMM_SMEM>>>(bfu);
    attn_kernel<<<LSEQ * NH, 256, ATTN_SMEM>>>();
    gemm_out_kernel<<<RROWS / 128, 256, GEMM_SMEM>>>(Wo, bo, out);
}

// round 5
// speedup vs baseline: 1.1404x; 1.0990x over previous
#include <cuda_runtime.h>
#include <math.h>

#define LSEQ 256
#define EDIM 128
#define NH 4
#define CD 32
#define RROWS (LSEQ*LSEQ)   // 65536

// ---------------- scratch (device globals; no allocs allowed) ----------------
__device__ float g_x [RROWS*EDIM];
__device__ float g_q [RROWS*EDIM];   // pre-scaled by C^-0.5  (the "v-indexed" operand)
__device__ float g_k [RROWS*EDIM];   // the "q-indexed" operand
__device__ float g_v [RROWS*EDIM];
__device__ float g_fu[RROWS*EDIM];   // sigmoid(x@Wfu + bfu)
__device__ float g_mb[NH*RROWS];     // mb[h][q*256+v] = mask[q,v] + bias[q,v,h]
__device__ float g_ao[RROWS*EDIM];   // gated attention output
__device__ float g_W [EDIM*512];     // packed Wq|Wk|Wv|Wfu

// ---------------- kernel: pack weights ----------------
__global__ void pack_w_kernel(const float* __restrict__ Wq, const float* __restrict__ Wk,
                              const float* __restrict__ Wv, const float* __restrict__ Wfu)
{
    int idx = blockIdx.x * blockDim.x + threadIdx.x;   // E*512 total
    int k = idx >> 9, n = idx & 511;
    const float* src = (n < 128) ? Wq : (n < 256) ? Wk : (n < 384) ? Wv : Wfu;
    g_W[idx] = src[k * 128 + (n & 127)];
}

// ---------------- kernel: layernorm + pair_bias(+mask) ----------------
__global__ void __launch_bounds__(128) ln_kernel(
    const float* __restrict__ pr, const float* __restrict__ mask,
    const float* __restrict__ gamma, const float* __restrict__ beta,
    const float* __restrict__ Wb)
{
    int r = blockIdx.x;           // row over (i,j)
    int t = threadIdx.x;          // 0..127 = E index
    float v = pr[(size_t)r * EDIM + t];

    float s = v, s2 = v * v;
    #pragma unroll
    for (int o = 16; o; o >>= 1) {
        s  += __shfl_xor_sync(0xffffffffu, s,  o);
        s2 += __shfl_xor_sync(0xffffffffu, s2, o);
    }
    __shared__ float sh[8];
    int w = t >> 5, lane = t & 31;
    if (lane == 0) { sh[w] = s; sh[4 + w] = s2; }
    __syncthreads();
    s  = sh[0] + sh[1] + sh[2] + sh[3];
    s2 = sh[4] + sh[5] + sh[6] + sh[7];
    float mu  = s * (1.0f / EDIM);
    float var = s2 * (1.0f / EDIM) - mu * mu;
    float x = (v - mu) * rsqrtf(var + 1e-5f) * gamma[t] + beta[t];
    g_x[(size_t)r * EDIM + t] = x;

    // pair_bias: 4 dot products of length 128
    float b0 = x * Wb[t * 4 + 0];
    float b1 = x * Wb[t * 4 + 1];
    float b2 = x * Wb[t * 4 + 2];
    float b3 = x * Wb[t * 4 + 3];
    #pragma unroll
    for (int o = 16; o; o >>= 1) {
        b0 += __shfl_xor_sync(0xffffffffu, b0, o);
        b1 += __shfl_xor_sync(0xffffffffu, b1, o);
        b2 += __shfl_xor_sync(0xffffffffu, b2, o);
        b3 += __shfl_xor_sync(0xffffffffu, b3, o);
    }
    __shared__ float shb[16];
    if (lane == 0) { shb[w*4+0]=b0; shb[w*4+1]=b1; shb[w*4+2]=b2; shb[w*4+3]=b3; }
    __syncthreads();
    if (t < 4) {
        float b = shb[t] + shb[4 + t] + shb[8 + t] + shb[12 + t];
        g_mb[t * RROWS + r] = mask[r] + b;
    }
}

// ---------------- kernel: projection GEMM [65536x128]x[128x512], 512 thr ----------------
__global__ void __launch_bounds__(512) gemm_proj_kernel(const float* __restrict__ bfu)
{
    extern __shared__ float sm[];
    float* Ast = sm;                 // [k=128][m=128]  (A transposed)
    float* Bs  = sm + 128 * 128;     // [k=128][n=128]

    int m0 = blockIdx.x * 128;
    int nt = blockIdx.y;             // 0:q 1:k 2:v 3:fu
    int n0 = nt * 128;
    int tid = threadIdx.x;

    {
        int r = tid & 127, kc0 = tid >> 7;
        #pragma unroll
        for (int c = kc0; c < 32; c += 4) {
            float4 a = *(const float4*)&g_x[(size_t)(m0 + r) * EDIM + c * 4];
            Ast[(c * 4 + 0) * 128 + r] = a.x;
            Ast[(c * 4 + 1) * 128 + r] = a.y;
            Ast[(c * 4 + 2) * 128 + r] = a.z;
            Ast[(c * 4 + 3) * 128 + r] = a.w;
        }
    }
    {
        int n4 = tid & 31, k0 = tid >> 5;
        #pragma unroll
        for (int k = k0; k < 128; k += 16)
            *(float4*)&Bs[k * 128 + n4 * 4] = *(const float4*)&g_W[k * 512 + n0 + n4 * 4];
    }
    __syncthreads();

    int tx = tid & 15, ty = tid >> 4;   // ty 0..31 -> 4 m-rows each
    float acc[4][8];
    #pragma unroll
    for (int i = 0; i < 4; i++)
        #pragma unroll
        for (int j = 0; j < 8; j++) acc[i][j] = 0.0f;

    #pragma unroll 8
    for (int k = 0; k < 128; k++) {
        float4 a0 = *(float4*)&Ast[k * 128 + ty * 4];          // broadcast within warp halves
        float4 b0 = *(float4*)&Bs [k * 128 + tx * 4];
        float4 b1 = *(float4*)&Bs [k * 128 + 64 + tx * 4];
        float av[4] = {a0.x,a0.y,a0.z,a0.w};
        float bv[8] = {b0.x,b0.y,b0.z,b0.w,b1.x,b1.y,b1.z,b1.w};
        #pragma unroll
        for (int i = 0; i < 4; i++)
            #pragma unroll
            for (int j = 0; j < 8; j++) acc[i][j] += av[i] * bv[j];
    }

    float* dst = (nt == 0) ? g_q : (nt == 1) ? g_k : (nt == 2) ? g_v : g_fu;
    const float qscale = 0.17677669529663687f;   // 32^-0.5
    #pragma unroll
    for (int i = 0; i < 4; i++) {
        int m = m0 + ty * 4 + i;
        #pragma unroll
        for (int j = 0; j < 8; j++) {
            int n = (j < 4) ? (tx * 4 + j) : (64 + tx * 4 + j - 4);
            float vv = acc[i][j];
            if (nt == 0) vv *= qscale;
            if (nt == 3) vv = 1.0f / (1.0f + __expf(-(vv + bfu[n])));
            dst[(size_t)m * EDIM + n] = vv;
        }
    }
}

// ---------------- kernel: attention per (s,h), 512 threads / 16 warps ----------------
// smem: Kt[32][256], Qt[32][256], V[256][32], P[64][256] = 160 KB, 1 block/SM.
// 64-query chunks; warp owns 4 query rows (acc[4][8]); warp-local softmax;
// mb prefetched to registers before the score GEMM.
__global__ void __launch_bounds__(512, 1) attn_kernel()
{
    extern __shared__ float sm[];
    float* Kt = sm;                  // [c=32][q=256]
    float* Qt = Kt + 32 * 256;       // [c=32][v=256]
    float* VV = Qt + 32 * 256;       // [v=256][c=32]
    float* P  = VV + 256 * 32;       // [64][256]

    int s = blockIdx.x >> 2;
    int h = blockIdx.x & 3;
    int tid = threadIdx.x;
    size_t base = (size_t)s * 256 * EDIM + h * CD;

    // threads 0..255 transpose K rows, 256..511 transpose Q rows
    {
        int r = tid & 255;
        const float* src = (tid < 256) ? g_k : g_q;
        float* dstT = (tid < 256) ? Kt : Qt;
        #pragma unroll
        for (int c4 = 0; c4 < 8; c4++) {
            float4 a4 = *(const float4*)&src[base + (size_t)r * EDIM + c4 * 4];
            dstT[(c4 * 4 + 0) * 256 + r] = a4.x;
            dstT[(c4 * 4 + 1) * 256 + r] = a4.y;
            dstT[(c4 * 4 + 2) * 256 + r] = a4.z;
            dstT[(c4 * 4 + 3) * 256 + r] = a4.w;
        }
    }
    // V direct (row-major [256][32])
    {
        int c4 = tid & 7, r0 = tid >> 3;
        #pragma unroll
        for (int rr = r0; rr < 256; rr += 64)
            *(float4*)&VV[rr * 32 + c4 * 4] = *(const float4*)&g_v[base + (size_t)rr * EDIM + c4 * 4];
    }
    __syncthreads();

    int tx = tid & 31;       // key/value lane
    int wy = tid >> 5;       // warp id 0..15 -> 4 query rows per chunk
    const float* mb = g_mb + (size_t)h * RROWS;

    for (int q0 = 0; q0 < 256; q0 += 64) {
        // prefetch mask+bias for this warp's 4 rows (hide L2 latency under GEMM)
        float4 mreg[4][2];
        #pragma unroll
        for (int i = 0; i < 4; i++) {
            const float* mrow = mb + (size_t)(q0 + wy * 4 + i) * 256;
            mreg[i][0] = __ldg((const float4*)&mrow[tx * 4]);
            mreg[i][1] = __ldg((const float4*)&mrow[128 + tx * 4]);
        }

        float acc[4][8];
        #pragma unroll
        for (int i = 0; i < 4; i++)
            #pragma unroll
            for (int j = 0; j < 8; j++) acc[i][j] = 0.0f;

        // scores GEMM: rows q0+wy*4..+3 x 256 keys x 32 c
        #pragma unroll 4
        for (int c = 0; c < 32; c++) {
            float4 a0 = *(float4*)&Kt[c * 256 + q0 + wy * 4];     // broadcast
            float4 b0 = *(float4*)&Qt[c * 256 + tx * 4];
            float4 b1 = *(float4*)&Qt[c * 256 + 128 + tx * 4];
            float av[4] = {a0.x,a0.y,a0.z,a0.w};
            float bv[8] = {b0.x,b0.y,b0.z,b0.w,b1.x,b1.y,b1.z,b1.w};
            #pragma unroll
            for (int i = 0; i < 4; i++)
                #pragma unroll
                for (int j = 0; j < 8; j++) acc[i][j] += av[i] * bv[j];
        }

        // mask+bias, warp-local softmax, stage P
        #pragma unroll
        for (int i = 0; i < 4; i++) {
            int lq = wy * 4 + i;
            acc[i][0] += mreg[i][0].x; acc[i][1] += mreg[i][0].y;
            acc[i][2] += mreg[i][0].z; acc[i][3] += mreg[i][0].w;
            acc[i][4] += mreg[i][1].x; acc[i][5] += mreg[i][1].y;
            acc[i][6] += mreg[i][1].z; acc[i][7] += mreg[i][1].w;

            float mx = acc[i][0];
            #pragma unroll
            for (int j = 1; j < 8; j++) mx = fmaxf(mx, acc[i][j]);
            #pragma unroll
            for (int o = 16; o; o >>= 1) mx = fmaxf(mx, __shfl_xor_sync(0xffffffffu, mx, o));
            float sum = 0.0f;
            #pragma unroll
            for (int j = 0; j < 8; j++) { acc[i][j] = __expf(acc[i][j] - mx); sum += acc[i][j]; }
            #pragma unroll
            for (int o = 16; o; o >>= 1) sum += __shfl_xor_sync(0xffffffffu, sum, o);
            float inv = 1.0f / sum;

            *(float4*)&P[lq * 256 + tx * 4] =
                make_float4(acc[i][0]*inv, acc[i][1]*inv, acc[i][2]*inv, acc[i][3]*inv);
            *(float4*)&P[lq * 256 + 128 + tx * 4] =
                make_float4(acc[i][4]*inv, acc[i][5]*inv, acc[i][6]*inv, acc[i][7]*inv);
        }
        __syncwarp();

        // AV: 4 rows x 32 cols per warp, lane = c
        float o[4] = {0.0f, 0.0f, 0.0f, 0.0f};
        #pragma unroll 4
        for (int vi = 0; vi < 256; vi += 4) {
            float v0 = VV[(vi + 0) * 32 + tx];
            float v1 = VV[(vi + 1) * 32 + tx];
            float v2 = VV[(vi + 2) * 32 + tx];
            float v3 = VV[(vi + 3) * 32 + tx];
            #pragma unroll
            for (int i = 0; i < 4; i++) {
                float4 p = *(float4*)&P[(wy * 4 + i) * 256 + vi];   // broadcast
                o[i] += p.x * v0 + p.y * v1 + p.z * v2 + p.w * v3;
            }
        }

        #pragma unroll
        for (int i = 0; i < 4; i++) {
            size_t idx = base + (size_t)(q0 + wy * 4 + i) * EDIM + tx;
            g_ao[idx] = o[i] * g_fu[idx];
        }
        __syncwarp();
    }
}

// ---------------- kernel: output GEMM [65536x128]x[128x128] + bo, 512 thr ----------------
__global__ void __launch_bounds__(512) gemm_out_kernel(
    const float* __restrict__ Wo, const float* __restrict__ bo, float* __restrict__ out)
{
    extern __shared__ float sm[];
    float* Ast = sm;
    float* Bs  = sm + 128 * 128;

    int m0 = blockIdx.x * 128;
    int tid = threadIdx.x;

    {
        int r = tid & 127, kc0 = tid >> 7;
        #pragma unroll
        for (int c = kc0; c < 32; c += 4) {
            float4 a = *(const float4*)&g_ao[(size_t)(m0 + r) * EDIM + c * 4];
            Ast[(c * 4 + 0) * 128 + r] = a.x;
            Ast[(c * 4 + 1) * 128 + r] = a.y;
            Ast[(c * 4 + 2) * 128 + r] = a.z;
            Ast[(c * 4 + 3) * 128 + r] = a.w;
        }
    }
    {
        int n4 = tid & 31, k0 = tid >> 5;
        #pragma unroll
        for (int k = k0; k < 128; k += 16)
            *(float4*)&Bs[k * 128 + n4 * 4] = *(const float4*)&Wo[k * 128 + n4 * 4];
    }
    __syncthreads();

    int tx = tid & 15, ty = tid >> 4;
    float acc[4][8];
    #pragma unroll
    for (int i = 0; i < 4; i++)
        #pragma unroll
        for (int j = 0; j < 8; j++) acc[i][j] = 0.0f;

    #pragma unroll 8
    for (int k = 0; k < 128; k++) {
        float4 a0 = *(float4*)&Ast[k * 128 + ty * 4];
        float4 b0 = *(float4*)&Bs [k * 128 + tx * 4];
        float4 b1 = *(float4*)&Bs [k * 128 + 64 + tx * 4];
        float av[4] = {a0.x,a0.y,a0.z,a0.w};
        float bv[8] = {b0.x,b0.y,b0.z,b0.w,b1.x,b1.y,b1.z,b1.w};
        #pragma unroll
        for (int i = 0; i < 4; i++)
            #pragma unroll
            for (int j = 0; j < 8; j++) acc[i][j] += av[i] * bv[j];
    }

    #pragma unroll
    for (int i = 0; i < 4; i++) {
        int m = m0 + ty * 4 + i;
        #pragma unroll
        for (int j = 0; j < 8; j++) {
            int n = (j < 4) ? (tx * 4 + j) : (64 + tx * 4 + j - 4);
            out[(size_t)m * EDIM + n] = acc[i][j] + bo[n];
        }
    }
}

// ---------------- host launch ----------------
extern "C" void kernel_launch(void* const* d_in, const int* in_sizes, int n_in,
                              void* d_out, int out_size)
{
    const float* pair_rep = (const float*)d_in[0];
    const float* mask     = (const float*)d_in[1];
    const float* gamma    = (const float*)d_in[2];
    const float* beta     = (const float*)d_in[3];
    const float* Wq       = (const float*)d_in[4];
    const float* Wk       = (const float*)d_in[5];
    const float* Wv       = (const float*)d_in[6];
    const float* Wb       = (const float*)d_in[7];
    const float* Wfu      = (const float*)d_in[8];
    const float* bfu      = (const float*)d_in[9];
    const float* Wo       = (const float*)d_in[10];
    const float* bo       = (const float*)d_in[11];
    float* out = (float*)d_out;

    const int GEMM_SMEM = 2 * 128 * 128 * (int)sizeof(float);                 // 128 KB
    const int ATTN_SMEM = (2 * 32 * 256 + 256 * 32 + 64 * 256) * (int)sizeof(float); // 160 KB
    cudaFuncSetAttribute(gemm_proj_kernel, cudaFuncAttributeMaxDynamicSharedMemorySize, GEMM_SMEM);
    cudaFuncSetAttribute(gemm_out_kernel,  cudaFuncAttributeMaxDynamicSharedMemorySize, GEMM_SMEM);
    cudaFuncSetAttribute(attn_kernel,      cudaFuncAttributeMaxDynamicSharedMemorySize, ATTN_SMEM);

    pack_w_kernel<<<(EDIM * 512) / 256, 256>>>(Wq, Wk, Wv, Wfu);
    ln_kernel<<<RROWS, 128>>>(pair_rep, mask, gamma, beta, Wb);
    gemm_proj_kernel<<<dim3(RROWS / 128, 4), 512, GEMM_SMEM>>>(bfu);
    attn_kernel<<<LSEQ * NH, 512, ATTN_SMEM>>>();
    gemm_out_kernel<<<RROWS / 128, 512, GEMM_SMEM>>>(Wo, bo, out);
}

// round 9
// speedup vs baseline: 1.5054x; 1.3201x over previous
#include <cuda_runtime.h>
#include <cuda_bf16.h>
#include <stdint.h>
#include <math.h>

#define LSEQ 256
#define EDIM 128
#define NH 4
#define CD 32
#define RROWS (LSEQ*LSEQ)   // 65536

// ---------------- scratch (device globals; no allocs allowed) ----------------
__device__ float g_x [RROWS*EDIM];
__device__ float g_q [RROWS*EDIM];   // pre-scaled by C^-0.5  (the "v-indexed" operand)
__device__ float g_k [RROWS*EDIM];   // the "q-indexed" operand
__device__ float g_v [RROWS*EDIM];
__device__ float g_fu[RROWS*EDIM];   // sigmoid(x@Wfu + bfu)
__device__ float g_mb[NH*RROWS];     // mb[h][q*256+v] = mask[q,v] + bias[q,v,h]
__device__ float g_ao[RROWS*EDIM];   // gated attention output
// packed+transposed+bf16-split weights: [n][k] layout (col-major B for mma)
__device__ __nv_bfloat16 g_Wt_hi [512*128];  // Wq|Wk|Wv|Wfu transposed
__device__ __nv_bfloat16 g_Wt_lo [512*128];
__device__ __nv_bfloat16 g_Wot_hi[128*128];  // Wo transposed
__device__ __nv_bfloat16 g_Wot_lo[128*128];

// ---------------- mma helper ----------------
#define MMA_BF16(d, a, b) \
    asm volatile("mma.sync.aligned.m16n8k16.row.col.f32.bf16.bf16.f32 " \
        "{%0,%1,%2,%3}, {%4,%5,%6,%7}, {%8,%9}, {%0,%1,%2,%3};" \
        : "+f"(d[0]), "+f"(d[1]), "+f"(d[2]), "+f"(d[3]) \
        : "r"(a[0]), "r"(a[1]), "r"(a[2]), "r"(a[3]), "r"(b[0]), "r"(b[1]))

// ---------------- kernel: pack + transpose + bf16-split weights ----------------
__global__ void pack_w_kernel(const float* __restrict__ Wq, const float* __restrict__ Wk,
                              const float* __restrict__ Wv, const float* __restrict__ Wfu,
                              const float* __restrict__ Wo)
{
    int idx = blockIdx.x * blockDim.x + threadIdx.x;   // 512*128 + 128*128 total
    if (idx < 512 * 128) {
        int n = idx >> 7, k = idx & 127;
        const float* src = (n < 128) ? Wq : (n < 256) ? Wk : (n < 384) ? Wv : Wfu;
        float v = src[k * 128 + (n & 127)];
        __nv_bfloat16 h = __float2bfloat16_rn(v);
        g_Wt_hi[idx] = h;
        g_Wt_lo[idx] = __float2bfloat16_rn(v - __bfloat162float(h));
    } else {
        int j = idx - 512 * 128;
        int n = j >> 7, k = j & 127;
        float v = Wo[k * 128 + n];
        __nv_bfloat16 h = __float2bfloat16_rn(v);
        g_Wot_hi[j] = h;
        g_Wot_lo[j] = __float2bfloat16_rn(v - __bfloat162float(h));
    }
}

// ---------------- kernel: layernorm + pair_bias(+mask) ----------------
__global__ void __launch_bounds__(128) ln_kernel(
    const float* __restrict__ pr, const float* __restrict__ mask,
    const float* __restrict__ gamma, const float* __restrict__ beta,
    const float* __restrict__ Wb)
{
    int r = blockIdx.x;
    int t = threadIdx.x;
    float v = pr[(size_t)r * EDIM + t];

    float s = v, s2 = v * v;
    #pragma unroll
    for (int o = 16; o; o >>= 1) {
        s  += __shfl_xor_sync(0xffffffffu, s,  o);
        s2 += __shfl_xor_sync(0xffffffffu, s2, o);
    }
    __shared__ float sh[8];
    int w = t >> 5, lane = t & 31;
    if (lane == 0) { sh[w] = s; sh[4 + w] = s2; }
    __syncthreads();
    s  = sh[0] + sh[1] + sh[2] + sh[3];
    s2 = sh[4] + sh[5] + sh[6] + sh[7];
    float mu  = s * (1.0f / EDIM);
    float var = s2 * (1.0f / EDIM) - mu * mu;
    float x = (v - mu) * rsqrtf(var + 1e-5f) * gamma[t] + beta[t];
    g_x[(size_t)r * EDIM + t] = x;

    float b0 = x * Wb[t * 4 + 0];
    float b1 = x * Wb[t * 4 + 1];
    float b2 = x * Wb[t * 4 + 2];
    float b3 = x * Wb[t * 4 + 3];
    #pragma unroll
    for (int o = 16; o; o >>= 1) {
        b0 += __shfl_xor_sync(0xffffffffu, b0, o);
        b1 += __shfl_xor_sync(0xffffffffu, b1, o);
        b2 += __shfl_xor_sync(0xffffffffu, b2, o);
        b3 += __shfl_xor_sync(0xffffffffu, b3, o);
    }
    __shared__ float shb[16];
    if (lane == 0) { shb[w*4+0]=b0; shb[w*4+1]=b1; shb[w*4+2]=b2; shb[w*4+3]=b3; }
    __syncthreads();
    if (t < 4) {
        float b = shb[t] + shb[4 + t] + shb[8 + t] + shb[12 + t];
        g_mb[t * RROWS + r] = mask[r] + b;
    }
}

// ---------------- conversion helper: 8 floats -> hi/lo bf16 granules ----------------
__device__ __forceinline__ void split8(const float* fs, uint4& hi, uint4& lo)
{
    uint32_t h[4], l[4];
    #pragma unroll
    for (int j = 0; j < 4; j++) {
        __nv_bfloat162 h2 = __floats2bfloat162_rn(fs[2*j], fs[2*j+1]);
        float r0 = fs[2*j]   - __bfloat162float(__low2bfloat16(h2));
        float r1 = fs[2*j+1] - __bfloat162float(__high2bfloat16(h2));
        __nv_bfloat162 l2 = __floats2bfloat162_rn(r0, r1);
        h[j] = *(uint32_t*)&h2;
        l[j] = *(uint32_t*)&l2;
    }
    hi = make_uint4(h[0], h[1], h[2], h[3]);
    lo = make_uint4(l[0], l[1], l[2], l[3]);
}

// swizzled byte offset for row r (256B pitch), 16B granule c
#define SWOFF(r, c) ((r) * 256 + ((((c) ^ ((r) & 7))) << 4))

// ---------------- kernel: projection GEMM via bf16-split tensor cores ----------------
// grid = 512 m-tiles; block 512 thr / 16 warps; warp tile 32x32; K=128 fully in smem.
// Internal loop over 4 n-tiles (q,k,v,fu) reusing the converted A tile.
__global__ void __launch_bounds__(512, 1) gemm_proj_kernel(const float* __restrict__ bfu)
{
    extern __shared__ char smem[];
    char* As_hi = smem;
    char* As_lo = smem + 32768;
    char* Bs_hi = smem + 65536;
    char* Bs_lo = smem + 98304;

    int m0 = blockIdx.x * 128;
    int tid = threadIdx.x;
    int cg = tid & 15, rb = tid >> 4;

    // convert A tile (g_x) to hi/lo bf16, swizzled [m][k]
    #pragma unroll
    for (int i = 0; i < 4; i++) {
        int r = rb + i * 32;
        const float* src = &g_x[(size_t)(m0 + r) * EDIM + cg * 8];
        float4 f0 = *(const float4*)src;
        float4 f1 = *(const float4*)(src + 4);
        float fs[8] = {f0.x,f0.y,f0.z,f0.w,f1.x,f1.y,f1.z,f1.w};
        uint4 hi, lo;
        split8(fs, hi, lo);
        int off = SWOFF(r, cg);
        *(uint4*)(As_hi + off) = hi;
        *(uint4*)(As_lo + off) = lo;
    }

    int w = tid >> 5, l = tid & 31;
    int mw = (w & 3) * 32, nw = (w >> 2) * 32;
    int g = l >> 2, c4 = (l & 3) * 4;
    const float qscale = 0.17677669529663687f;

    for (int nt = 0; nt < 4; nt++) {
        __syncthreads();   // A ready (1st iter) / prior mma done before Bs overwrite
        #pragma unroll
        for (int i = 0; i < 4; i++) {
            int r = rb + i * 32;
            int off = SWOFF(r, cg);
            size_t gi = (size_t)(nt * 128 + r) * 128 + cg * 8;
            *(uint4*)(Bs_hi + off) = *(const uint4*)(g_Wt_hi + gi);
            *(uint4*)(Bs_lo + off) = *(const uint4*)(g_Wt_lo + gi);
        }
        __syncthreads();

        float acc[2][4][4];
        #pragma unroll
        for (int mt = 0; mt < 2; mt++)
            #pragma unroll
            for (int n4 = 0; n4 < 4; n4++)
                #pragma unroll
                for (int j = 0; j < 4; j++) acc[mt][n4][j] = 0.0f;

        #pragma unroll
        for (int ks = 0; ks < 8; ks++) {
            uint32_t ah[2][4], al[2][4], bh[4][2], bl[4][2];
            #pragma unroll
            for (int mt = 0; mt < 2; mt++) {
                int r0 = mw + mt * 16 + g, r1 = r0 + 8;
                int ga = ks * 2, gb = ks * 2 + 1;
                int o0 = SWOFF(r0, ga) + c4, o1 = SWOFF(r1, ga) + c4;
                int o2 = SWOFF(r0, gb) + c4, o3 = SWOFF(r1, gb) + c4;
                ah[mt][0] = *(uint32_t*)(As_hi + o0); ah[mt][1] = *(uint32_t*)(As_hi + o1);
                ah[mt][2] = *(uint32_t*)(As_hi + o2); ah[mt][3] = *(uint32_t*)(As_hi + o3);
                al[mt][0] = *(uint32_t*)(As_lo + o0); al[mt][1] = *(uint32_t*)(As_lo + o1);
                al[mt][2] = *(uint32_t*)(As_lo + o2); al[mt][3] = *(uint32_t*)(As_lo + o3);
            }
            #pragma unroll
            for (int n4 = 0; n4 < 4; n4++) {
                int n = nw + n4 * 8 + g;
                int o0 = SWOFF(n, ks * 2) + c4, o1 = SWOFF(n, ks * 2 + 1) + c4;
                bh[n4][0] = *(uint32_t*)(Bs_hi + o0); bh[n4][1] = *(uint32_t*)(Bs_hi + o1);
                bl[n4][0] = *(uint32_t*)(Bs_lo + o0); bl[n4][1] = *(uint32_t*)(Bs_lo + o1);
            }
            #pragma unroll
            for (int mt = 0; mt < 2; mt++)
                #pragma unroll
                for (int n4 = 0; n4 < 4; n4++) {
                    MMA_BF16(acc[mt][n4], ah[mt], bh[n4]);
                    MMA_BF16(acc[mt][n4], ah[mt], bl[n4]);
                    MMA_BF16(acc[mt][n4], al[mt], bh[n4]);
                }
        }

        float* dst = (nt == 0) ? g_q : (nt == 1) ? g_k : (nt == 2) ? g_v : g_fu;
        #pragma unroll
        for (int mt = 0; mt < 2; mt++)
            #pragma unroll
            for (int n4 = 0; n4 < 4; n4++) {
                int m = m0 + mw + mt * 16 + g;
                int ncol = nw + n4 * 8 + (l & 3) * 2;
                float v0 = acc[mt][n4][0], v1 = acc[mt][n4][1];
                float v2 = acc[mt][n4][2], v3 = acc[mt][n4][3];
                if (nt == 0) { v0 *= qscale; v1 *= qscale; v2 *= qscale; v3 *= qscale; }
                if (nt == 3) {
                    float bf0 = bfu[ncol], bf1 = bfu[ncol + 1];
                    v0 = 1.0f / (1.0f + __expf(-(v0 + bf0)));
                    v1 = 1.0f / (1.0f + __expf(-(v1 + bf1)));
                    v2 = 1.0f / (1.0f + __expf(-(v2 + bf0)));
                    v3 = 1.0f / (1.0f + __expf(-(v3 + bf1)));
                }
                *(float2*)&dst[(size_t)m * EDIM + ncol]       = make_float2(v0, v1);
                *(float2*)&dst[(size_t)(m + 8) * EDIM + ncol] = make_float2(v2, v3);
            }
    }
}

// ---------------- kernel: output GEMM via bf16-split tensor cores ----------------
__global__ void __launch_bounds__(512, 1) gemm_out_kernel(
    const float* __restrict__ bo, float* __restrict__ out)
{
    extern __shared__ char smem[];
    char* As_hi = smem;
    char* As_lo = smem + 32768;
    char* Bs_hi = smem + 65536;
    char* Bs_lo = smem + 98304;

    int m0 = blockIdx.x * 128;
    int tid = threadIdx.x;
    int cg = tid & 15, rb = tid >> 4;

    #pragma unroll
    for (int i = 0; i < 4; i++) {
        int r = rb + i * 32;
        const float* src = &g_ao[(size_t)(m0 + r) * EDIM + cg * 8];
        float4 f0 = *(const float4*)src;
        float4 f1 = *(const float4*)(src + 4);
        float fs[8] = {f0.x,f0.y,f0.z,f0.w,f1.x,f1.y,f1.z,f1.w};
        uint4 hi, lo;
        split8(fs, hi, lo);
        int off = SWOFF(r, cg);
        *(uint4*)(As_hi + off) = hi;
        *(uint4*)(As_lo + off) = lo;

        size_t gi = (size_t)r * 128 + cg * 8;
        *(uint4*)(Bs_hi + off) = *(const uint4*)(g_Wot_hi + gi);
        *(uint4*)(Bs_lo + off) = *(const uint4*)(g_Wot_lo + gi);
    }
    __syncthreads();

    int w = tid >> 5, l = tid & 31;
    int mw = (w & 3) * 32, nw = (w >> 2) * 32;
    int g = l >> 2, c4 = (l & 3) * 4;

    float acc[2][4][4];
    #pragma unroll
    for (int mt = 0; mt < 2; mt++)
        #pragma unroll
        for (int n4 = 0; n4 < 4; n4++)
            #pragma unroll
            for (int j = 0; j < 4; j++) acc[mt][n4][j] = 0.0f;

    #pragma unroll
    for (int ks = 0; ks < 8; ks++) {
        uint32_t ah[2][4], al[2][4], bh[4][2], bl[4][2];
        #pragma unroll
        for (int mt = 0; mt < 2; mt++) {
            int r0 = mw + mt * 16 + g, r1 = r0 + 8;
            int ga = ks * 2, gb = ks * 2 + 1;
            int o0 = SWOFF(r0, ga) + c4, o1 = SWOFF(r1, ga) + c4;
            int o2 = SWOFF(r0, gb) + c4, o3 = SWOFF(r1, gb) + c4;
            ah[mt][0] = *(uint32_t*)(As_hi + o0); ah[mt][1] = *(uint32_t*)(As_hi + o1);
            ah[mt][2] = *(uint32_t*)(As_hi + o2); ah[mt][3] = *(uint32_t*)(As_hi + o3);
            al[mt][0] = *(uint32_t*)(As_lo + o0); al[mt][1] = *(uint32_t*)(As_lo + o1);
            al[mt][2] = *(uint32_t*)(As_lo + o2); al[mt][3] = *(uint32_t*)(As_lo + o3);
        }
        #pragma unroll
        for (int n4 = 0; n4 < 4; n4++) {
            int n = nw + n4 * 8 + g;
            int o0 = SWOFF(n, ks * 2) + c4, o1 = SWOFF(n, ks * 2 + 1) + c4;
            bh[n4][0] = *(uint32_t*)(Bs_hi + o0); bh[n4][1] = *(uint32_t*)(Bs_hi + o1);
            bl[n4][0] = *(uint32_t*)(Bs_lo + o0); bl[n4][1] = *(uint32_t*)(Bs_lo + o1);
        }
        #pragma unroll
        for (int mt = 0; mt < 2; mt++)
            #pragma unroll
            for (int n4 = 0; n4 < 4; n4++) {
                MMA_BF16(acc[mt][n4], ah[mt], bh[n4]);
                MMA_BF16(acc[mt][n4], ah[mt], bl[n4]);
                MMA_BF16(acc[mt][n4], al[mt], bh[n4]);
            }
    }

    #pragma unroll
    for (int mt = 0; mt < 2; mt++)
        #pragma unroll
        for (int n4 = 0; n4 < 4; n4++) {
            int m = m0 + mw + mt * 16 + g;
            int ncol = nw + n4 * 8 + (l & 3) * 2;
            float b0 = bo[ncol], b1 = bo[ncol + 1];
            *(float2*)&out[(size_t)m * EDIM + ncol] =
                make_float2(acc[mt][n4][0] + b0, acc[mt][n4][1] + b1);
            *(float2*)&out[(size_t)(m + 8) * EDIM + ncol] =
                make_float2(acc[mt][n4][2] + b0, acc[mt][n4][3] + b1);
        }
}

// ---------------- kernel: attention per (s,h), 512 threads / 16 warps ----------------
__global__ void __launch_bounds__(512, 1) attn_kernel()
{
    extern __shared__ float sm[];
    float* Kt = sm;                  // [c=32][q=256]
    float* Qt = Kt + 32 * 256;       // [c=32][v=256]
    float* VV = Qt + 32 * 256;       // [v=256][c=32]
    float* P  = VV + 256 * 32;       // [64][256]

    int s = blockIdx.x >> 2;
    int h = blockIdx.x & 3;
    int tid = threadIdx.x;
    size_t base = (size_t)s * 256 * EDIM + h * CD;

    {
        int r = tid & 255;
        const float* src = (tid < 256) ? g_k : g_q;
        float* dstT = (tid < 256) ? Kt : Qt;
        #pragma unroll
        for (int c4 = 0; c4 < 8; c4++) {
            float4 a4 = *(const float4*)&src[base + (size_t)r * EDIM + c4 * 4];
            dstT[(c4 * 4 + 0) * 256 + r] = a4.x;
            dstT[(c4 * 4 + 1) * 256 + r] = a4.y;
            dstT[(c4 * 4 + 2) * 256 + r] = a4.z;
            dstT[(c4 * 4 + 3) * 256 + r] = a4.w;
        }
    }
    {
        int c4 = tid & 7, r0 = tid >> 3;
        #pragma unroll
        for (int rr = r0; rr < 256; rr += 64)
            *(float4*)&VV[rr * 32 + c4 * 4] = *(const float4*)&g_v[base + (size_t)rr * EDIM + c4 * 4];
    }
    __syncthreads();

    int tx = tid & 31;
    int wy = tid >> 5;
    const float* mb = g_mb + (size_t)h * RROWS;

    for (int q0 = 0; q0 < 256; q0 += 64) {
        float4 mreg[4][2];
        #pragma unroll
        for (int i = 0; i < 4; i++) {
            const float* mrow = mb + (size_t)(q0 + wy * 4 + i) * 256;
            mreg[i][0] = __ldg((const float4*)&mrow[tx * 4]);
            mreg[i][1] = __ldg((const float4*)&mrow[128 + tx * 4]);
        }

        float acc[4][8];
        #pragma unroll
        for (int i = 0; i < 4; i++)
            #pragma unroll
            for (int j = 0; j < 8; j++) acc[i][j] = 0.0f;

        #pragma unroll 4
        for (int c = 0; c < 32; c++) {
            float4 a0 = *(float4*)&Kt[c * 256 + q0 + wy * 4];
            float4 b0 = *(float4*)&Qt[c * 256 + tx * 4];
            float4 b1 = *(float4*)&Qt[c * 256 + 128 + tx * 4];
            float av[4] = {a0.x,a0.y,a0.z,a0.w};
            float bv[8] = {b0.x,b0.y,b0.z,b0.w,b1.x,b1.y,b1.z,b1.w};
            #pragma unroll
            for (int i = 0; i < 4; i++)
                #pragma unroll
                for (int j = 0; j < 8; j++) acc[i][j] += av[i] * bv[j];
        }

        #pragma unroll
        for (int i = 0; i < 4; i++) {
            int lq = wy * 4 + i;
            acc[i][0] += mreg[i][0].x; acc[i][1] += mreg[i][0].y;
            acc[i][2] += mreg[i][0].z; acc[i][3] += mreg[i][0].w;
            acc[i][4] += mreg[i][1].x; acc[i][5] += mreg[i][1].y;
            acc[i][6] += mreg[i][1].z; acc[i][7] += mreg[i][1].w;

            float mx = acc[i][0];
            #pragma unroll
            for (int j = 1; j < 8; j++) mx = fmaxf(mx, acc[i][j]);
            #pragma unroll
            for (int o = 16; o; o >>= 1) mx = fmaxf(mx, __shfl_xor_sync(0xffffffffu, mx, o));
            float sum = 0.0f;
            #pragma unroll
            for (int j = 0; j < 8; j++) { acc[i][j] = __expf(acc[i][j] - mx); sum += acc[i][j]; }
            #pragma unroll
            for (int o = 16; o; o >>= 1) sum += __shfl_xor_sync(0xffffffffu, sum, o);
            float inv = 1.0f / sum;

            *(float4*)&P[lq * 256 + tx * 4] =
                make_float4(acc[i][0]*inv, acc[i][1]*inv, acc[i][2]*inv, acc[i][3]*inv);
            *(float4*)&P[lq * 256 + 128 + tx * 4] =
                make_float4(acc[i][4]*inv, acc[i][5]*inv, acc[i][6]*inv, acc[i][7]*inv);
        }
        __syncwarp();

        float o[4] = {0.0f, 0.0f, 0.0f, 0.0f};
        #pragma unroll 4
        for (int vi = 0; vi < 256; vi += 4) {
            float v0 = VV[(vi + 0) * 32 + tx];
            float v1 = VV[(vi + 1) * 32 + tx];
            float v2 = VV[(vi + 2) * 32 + tx];
            float v3 = VV[(vi + 3) * 32 + tx];
            #pragma unroll
            for (int i = 0; i < 4; i++) {
                float4 p = *(float4*)&P[(wy * 4 + i) * 256 + vi];
                o[i] += p.x * v0 + p.y * v1 + p.z * v2 + p.w * v3;
            }
        }

        #pragma unroll
        for (int i = 0; i < 4; i++) {
            size_t idx = base + (size_t)(q0 + wy * 4 + i) * EDIM + tx;
            g_ao[idx] = o[i] * g_fu[idx];
        }
        __syncwarp();
    }
}

// ---------------- host launch ----------------
extern "C" void kernel_launch(void* const* d_in, const int* in_sizes, int n_in,
                              void* d_out, int out_size)
{
    const float* pair_rep = (const float*)d_in[0];
    const float* mask     = (const float*)d_in[1];
    const float* gamma    = (const float*)d_in[2];
    const float* beta     = (const float*)d_in[3];
    const float* Wq       = (const float*)d_in[4];
    const float* Wk       = (const float*)d_in[5];
    const float* Wv       = (const float*)d_in[6];
    const float* Wb       = (const float*)d_in[7];
    const float* Wfu      = (const float*)d_in[8];
    const float* bfu      = (const float*)d_in[9];
    const float* Wo       = (const float*)d_in[10];
    const float* bo       = (const float*)d_in[11];
    float* out = (float*)d_out;

    const int GEMM_SMEM = 128 * 1024;                                           // 128 KB
    const int ATTN_SMEM = (2 * 32 * 256 + 256 * 32 + 64 * 256) * (int)sizeof(float); // 160 KB
    cudaFuncSetAttribute(gemm_proj_kernel, cudaFuncAttributeMaxDynamicSharedMemorySize, GEMM_SMEM);
    cudaFuncSetAttribute(gemm_out_kernel,  cudaFuncAttributeMaxDynamicSharedMemorySize, GEMM_SMEM);
    cudaFuncSetAttribute(attn_kernel,      cudaFuncAttributeMaxDynamicSharedMemorySize, ATTN_SMEM);

    pack_w_kernel<<<(512 * 128 + 128 * 128) / 256, 256>>>(Wq, Wk, Wv, Wfu, Wo);
    ln_kernel<<<RROWS, 128>>>(pair_rep, mask, gamma, beta, Wb);
    gemm_proj_kernel<<<RROWS / 128, 512, GEMM_SMEM>>>(bfu);
    attn_kernel<<<LSEQ * NH, 512, ATTN_SMEM>>>();
    gemm_out_kernel<<<RROWS / 128, 512, GEMM_SMEM>>>(bo, out);
}

// round 10
// speedup vs baseline: 1.9709x; 1.3093x over previous
#include <cuda_runtime.h>
#include <cuda_bf16.h>
#include <stdint.h>
#include <math.h>

#define LSEQ 256
#define EDIM 128
#define NH 4
#define CD 32
#define RROWS (LSEQ*LSEQ)   // 65536

// ---------------- scratch (device globals; no allocs allowed) ----------------
__device__ float g_x [RROWS*EDIM];
__device__ float g_q [RROWS*EDIM];   // pre-scaled by C^-0.5  (the "v-indexed" operand)
__device__ float g_k [RROWS*EDIM];   // the "q-indexed" operand
__device__ float g_v [RROWS*EDIM];
__device__ float g_fu[RROWS*EDIM];   // sigmoid(x@Wfu + bfu)
__device__ float g_mb[NH*RROWS];     // mb[h][q*256+v] = mask[q,v] + bias[q,v,h]
__device__ float g_ao[RROWS*EDIM];   // gated attention output
// packed+transposed+bf16-split weights: [n][k] layout (col-major B for mma)
__device__ __nv_bfloat16 g_Wt_hi [512*128];
__device__ __nv_bfloat16 g_Wt_lo [512*128];
__device__ __nv_bfloat16 g_Wot_hi[128*128];
__device__ __nv_bfloat16 g_Wot_lo[128*128];

// ---------------- mma helper ----------------
#define MMA_BF16(d, a, b) \
    asm volatile("mma.sync.aligned.m16n8k16.row.col.f32.bf16.bf16.f32 " \
        "{%0,%1,%2,%3}, {%4,%5,%6,%7}, {%8,%9}, {%0,%1,%2,%3};" \
        : "+f"(d[0]), "+f"(d[1]), "+f"(d[2]), "+f"(d[3]) \
        : "r"(a[0]), "r"(a[1]), "r"(a[2]), "r"(a[3]), "r"(b[0]), "r"(b[1]))

// ---------------- kernel: pack + transpose + bf16-split weights ----------------
__global__ void pack_w_kernel(const float* __restrict__ Wq, const float* __restrict__ Wk,
                              const float* __restrict__ Wv, const float* __restrict__ Wfu,
                              const float* __restrict__ Wo)
{
    int idx = blockIdx.x * blockDim.x + threadIdx.x;
    if (idx < 512 * 128) {
        int n = idx >> 7, k = idx & 127;
        const float* src = (n < 128) ? Wq : (n < 256) ? Wk : (n < 384) ? Wv : Wfu;
        float v = src[k * 128 + (n & 127)];
        __nv_bfloat16 h = __float2bfloat16_rn(v);
        g_Wt_hi[idx] = h;
        g_Wt_lo[idx] = __float2bfloat16_rn(v - __bfloat162float(h));
    } else {
        int j = idx - 512 * 128;
        int n = j >> 7, k = j & 127;
        float v = Wo[k * 128 + n];
        __nv_bfloat16 h = __float2bfloat16_rn(v);
        g_Wot_hi[j] = h;
        g_Wot_lo[j] = __float2bfloat16_rn(v - __bfloat162float(h));
    }
}

// ---------------- kernel: layernorm + pair_bias(+mask) ----------------
__global__ void __launch_bounds__(128) ln_kernel(
    const float* __restrict__ pr, const float* __restrict__ mask,
    const float* __restrict__ gamma, const float* __restrict__ beta,
    const float* __restrict__ Wb)
{
    int r = blockIdx.x;
    int t = threadIdx.x;
    float v = pr[(size_t)r * EDIM + t];

    float s = v, s2 = v * v;
    #pragma unroll
    for (int o = 16; o; o >>= 1) {
        s  += __shfl_xor_sync(0xffffffffu, s,  o);
        s2 += __shfl_xor_sync(0xffffffffu, s2, o);
    }
    __shared__ float sh[8];
    int w = t >> 5, lane = t & 31;
    if (lane == 0) { sh[w] = s; sh[4 + w] = s2; }
    __syncthreads();
    s  = sh[0] + sh[1] + sh[2] + sh[3];
    s2 = sh[4] + sh[5] + sh[6] + sh[7];
    float mu  = s * (1.0f / EDIM);
    float var = s2 * (1.0f / EDIM) - mu * mu;
    float x = (v - mu) * rsqrtf(var + 1e-5f) * gamma[t] + beta[t];
    g_x[(size_t)r * EDIM + t] = x;

    float b0 = x * Wb[t * 4 + 0];
    float b1 = x * Wb[t * 4 + 1];
    float b2 = x * Wb[t * 4 + 2];
    float b3 = x * Wb[t * 4 + 3];
    #pragma unroll
    for (int o = 16; o; o >>= 1) {
        b0 += __shfl_xor_sync(0xffffffffu, b0, o);
        b1 += __shfl_xor_sync(0xffffffffu, b1, o);
        b2 += __shfl_xor_sync(0xffffffffu, b2, o);
        b3 += __shfl_xor_sync(0xffffffffu, b3, o);
    }
    __shared__ float shb[16];
    if (lane == 0) { shb[w*4+0]=b0; shb[w*4+1]=b1; shb[w*4+2]=b2; shb[w*4+3]=b3; }
    __syncthreads();
    if (t < 4) {
        float b = shb[t] + shb[4 + t] + shb[8 + t] + shb[12 + t];
        g_mb[t * RROWS + r] = mask[r] + b;
    }
}

// ---------------- conversion helper: 8 floats -> hi/lo bf16 granules ----------------
__device__ __forceinline__ void split8(const float* fs, uint4& hi, uint4& lo)
{
    uint32_t h[4], l[4];
    #pragma unroll
    for (int j = 0; j < 4; j++) {
        __nv_bfloat162 h2 = __floats2bfloat162_rn(fs[2*j], fs[2*j+1]);
        float r0 = fs[2*j]   - __bfloat162float(__low2bfloat16(h2));
        float r1 = fs[2*j+1] - __bfloat162float(__high2bfloat16(h2));
        __nv_bfloat162 l2 = __floats2bfloat162_rn(r0, r1);
        h[j] = *(uint32_t*)&h2;
        l[j] = *(uint32_t*)&l2;
    }
    hi = make_uint4(h[0], h[1], h[2], h[3]);
    lo = make_uint4(l[0], l[1], l[2], l[3]);
}

// swizzled byte offset for row r (256B pitch), 16B granule c
#define SWOFF(r, c) ((r) * 256 + ((((c) ^ ((r) & 7))) << 4))

// ---------------- kernel: projection GEMM via bf16-split tensor cores ----------------
__global__ void __launch_bounds__(512, 1) gemm_proj_kernel(const float* __restrict__ bfu)
{
    extern __shared__ char smem[];
    char* As_hi = smem;
    char* As_lo = smem + 32768;
    char* Bs_hi = smem + 65536;
    char* Bs_lo = smem + 98304;

    int m0 = blockIdx.x * 128;
    int tid = threadIdx.x;
    int cg = tid & 15, rb = tid >> 4;

    #pragma unroll
    for (int i = 0; i < 4; i++) {
        int r = rb + i * 32;
        const float* src = &g_x[(size_t)(m0 + r) * EDIM + cg * 8];
        float4 f0 = *(const float4*)src;
        float4 f1 = *(const float4*)(src + 4);
        float fs[8] = {f0.x,f0.y,f0.z,f0.w,f1.x,f1.y,f1.z,f1.w};
        uint4 hi, lo;
        split8(fs, hi, lo);
        int off = SWOFF(r, cg);
        *(uint4*)(As_hi + off) = hi;
        *(uint4*)(As_lo + off) = lo;
    }

    int w = tid >> 5, l = tid & 31;
    int mw = (w & 3) * 32, nw = (w >> 2) * 32;
    int g = l >> 2, c4 = (l & 3) * 4;
    const float qscale = 0.17677669529663687f;

    for (int nt = 0; nt < 4; nt++) {
        __syncthreads();
        #pragma unroll
        for (int i = 0; i < 4; i++) {
            int r = rb + i * 32;
            int off = SWOFF(r, cg);
            size_t gi = (size_t)(nt * 128 + r) * 128 + cg * 8;
            *(uint4*)(Bs_hi + off) = *(const uint4*)(g_Wt_hi + gi);
            *(uint4*)(Bs_lo + off) = *(const uint4*)(g_Wt_lo + gi);
        }
        __syncthreads();

        float acc[2][4][4];
        #pragma unroll
        for (int mt = 0; mt < 2; mt++)
            #pragma unroll
            for (int n4 = 0; n4 < 4; n4++)
                #pragma unroll
                for (int j = 0; j < 4; j++) acc[mt][n4][j] = 0.0f;

        #pragma unroll
        for (int ks = 0; ks < 8; ks++) {
            uint32_t ah[2][4], al[2][4], bh[4][2], bl[4][2];
            #pragma unroll
            for (int mt = 0; mt < 2; mt++) {
                int r0 = mw + mt * 16 + g, r1 = r0 + 8;
                int ga = ks * 2, gb = ks * 2 + 1;
                int o0 = SWOFF(r0, ga) + c4, o1 = SWOFF(r1, ga) + c4;
                int o2 = SWOFF(r0, gb) + c4, o3 = SWOFF(r1, gb) + c4;
                ah[mt][0] = *(uint32_t*)(As_hi + o0); ah[mt][1] = *(uint32_t*)(As_hi + o1);
                ah[mt][2] = *(uint32_t*)(As_hi + o2); ah[mt][3] = *(uint32_t*)(As_hi + o3);
                al[mt][0] = *(uint32_t*)(As_lo + o0); al[mt][1] = *(uint32_t*)(As_lo + o1);
                al[mt][2] = *(uint32_t*)(As_lo + o2); al[mt][3] = *(uint32_t*)(As_lo + o3);
            }
            #pragma unroll
            for (int n4 = 0; n4 < 4; n4++) {
                int n = nw + n4 * 8 + g;
                int o0 = SWOFF(n, ks * 2) + c4, o1 = SWOFF(n, ks * 2 + 1) + c4;
                bh[n4][0] = *(uint32_t*)(Bs_hi + o0); bh[n4][1] = *(uint32_t*)(Bs_hi + o1);
                bl[n4][0] = *(uint32_t*)(Bs_lo + o0); bl[n4][1] = *(uint32_t*)(Bs_lo + o1);
            }
            #pragma unroll
            for (int mt = 0; mt < 2; mt++)
                #pragma unroll
                for (int n4 = 0; n4 < 4; n4++) {
                    MMA_BF16(acc[mt][n4], ah[mt], bh[n4]);
                    MMA_BF16(acc[mt][n4], ah[mt], bl[n4]);
                    MMA_BF16(acc[mt][n4], al[mt], bh[n4]);
                }
        }

        float* dst = (nt == 0) ? g_q : (nt == 1) ? g_k : (nt == 2) ? g_v : g_fu;
        #pragma unroll
        for (int mt = 0; mt < 2; mt++)
            #pragma unroll
            for (int n4 = 0; n4 < 4; n4++) {
                int m = m0 + mw + mt * 16 + g;
                int ncol = nw + n4 * 8 + (l & 3) * 2;
                float v0 = acc[mt][n4][0], v1 = acc[mt][n4][1];
                float v2 = acc[mt][n4][2], v3 = acc[mt][n4][3];
                if (nt == 0) { v0 *= qscale; v1 *= qscale; v2 *= qscale; v3 *= qscale; }
                if (nt == 3) {
                    float bf0 = bfu[ncol], bf1 = bfu[ncol + 1];
                    v0 = 1.0f / (1.0f + __expf(-(v0 + bf0)));
                    v1 = 1.0f / (1.0f + __expf(-(v1 + bf1)));
                    v2 = 1.0f / (1.0f + __expf(-(v2 + bf0)));
                    v3 = 1.0f / (1.0f + __expf(-(v3 + bf1)));
                }
                *(float2*)&dst[(size_t)m * EDIM + ncol]       = make_float2(v0, v1);
                *(float2*)&dst[(size_t)(m + 8) * EDIM + ncol] = make_float2(v2, v3);
            }
    }
}

// ---------------- kernel: output GEMM via bf16-split tensor cores ----------------
__global__ void __launch_bounds__(512, 1) gemm_out_kernel(
    const float* __restrict__ bo, float* __restrict__ out)
{
    extern __shared__ char smem[];
    char* As_hi = smem;
    char* As_lo = smem + 32768;
    char* Bs_hi = smem + 65536;
    char* Bs_lo = smem + 98304;

    int m0 = blockIdx.x * 128;
    int tid = threadIdx.x;
    int cg = tid & 15, rb = tid >> 4;

    #pragma unroll
    for (int i = 0; i < 4; i++) {
        int r = rb + i * 32;
        const float* src = &g_ao[(size_t)(m0 + r) * EDIM + cg * 8];
        float4 f0 = *(const float4*)src;
        float4 f1 = *(const float4*)(src + 4);
        float fs[8] = {f0.x,f0.y,f0.z,f0.w,f1.x,f1.y,f1.z,f1.w};
        uint4 hi, lo;
        split8(fs, hi, lo);
        int off = SWOFF(r, cg);
        *(uint4*)(As_hi + off) = hi;
        *(uint4*)(As_lo + off) = lo;

        size_t gi = (size_t)r * 128 + cg * 8;
        *(uint4*)(Bs_hi + off) = *(const uint4*)(g_Wot_hi + gi);
        *(uint4*)(Bs_lo + off) = *(const uint4*)(g_Wot_lo + gi);
    }
    __syncthreads();

    int w = tid >> 5, l = tid & 31;
    int mw = (w & 3) * 32, nw = (w >> 2) * 32;
    int g = l >> 2, c4 = (l & 3) * 4;

    float acc[2][4][4];
    #pragma unroll
    for (int mt = 0; mt < 2; mt++)
        #pragma unroll
        for (int n4 = 0; n4 < 4; n4++)
            #pragma unroll
            for (int j = 0; j < 4; j++) acc[mt][n4][j] = 0.0f;

    #pragma unroll
    for (int ks = 0; ks < 8; ks++) {
        uint32_t ah[2][4], al[2][4], bh[4][2], bl[4][2];
        #pragma unroll
        for (int mt = 0; mt < 2; mt++) {
            int r0 = mw + mt * 16 + g, r1 = r0 + 8;
            int ga = ks * 2, gb = ks * 2 + 1;
            int o0 = SWOFF(r0, ga) + c4, o1 = SWOFF(r1, ga) + c4;
            int o2 = SWOFF(r0, gb) + c4, o3 = SWOFF(r1, gb) + c4;
            ah[mt][0] = *(uint32_t*)(As_hi + o0); ah[mt][1] = *(uint32_t*)(As_hi + o1);
            ah[mt][2] = *(uint32_t*)(As_hi + o2); ah[mt][3] = *(uint32_t*)(As_hi + o3);
            al[mt][0] = *(uint32_t*)(As_lo + o0); al[mt][1] = *(uint32_t*)(As_lo + o1);
            al[mt][2] = *(uint32_t*)(As_lo + o2); al[mt][3] = *(uint32_t*)(As_lo + o3);
        }
        #pragma unroll
        for (int n4 = 0; n4 < 4; n4++) {
            int n = nw + n4 * 8 + g;
            int o0 = SWOFF(n, ks * 2) + c4, o1 = SWOFF(n, ks * 2 + 1) + c4;
            bh[n4][0] = *(uint32_t*)(Bs_hi + o0); bh[n4][1] = *(uint32_t*)(Bs_hi + o1);
            bl[n4][0] = *(uint32_t*)(Bs_lo + o0); bl[n4][1] = *(uint32_t*)(Bs_lo + o1);
        }
        #pragma unroll
        for (int mt = 0; mt < 2; mt++)
            #pragma unroll
            for (int n4 = 0; n4 < 4; n4++) {
                MMA_BF16(acc[mt][n4], ah[mt], bh[n4]);
                MMA_BF16(acc[mt][n4], ah[mt], bl[n4]);
                MMA_BF16(acc[mt][n4], al[mt], bh[n4]);
            }
    }

    #pragma unroll
    for (int mt = 0; mt < 2; mt++)
        #pragma unroll
        for (int n4 = 0; n4 < 4; n4++) {
            int m = m0 + mw + mt * 16 + g;
            int ncol = nw + n4 * 8 + (l & 3) * 2;
            float b0 = bo[ncol], b1 = bo[ncol + 1];
            *(float2*)&out[(size_t)m * EDIM + ncol] =
                make_float2(acc[mt][n4][0] + b0, acc[mt][n4][1] + b1);
            *(float2*)&out[(size_t)(m + 8) * EDIM + ncol] =
                make_float2(acc[mt][n4][2] + b0, acc[mt][n4][3] + b1);
        }
}

// ---------------- kernel: tensor-core attention per (s,h) ----------------
// 512 thr / 16 warps. smem: K/Q bf16 hi/lo [256][32] (64B pitch, 4-granule XOR),
// Vt bf16 hi/lo [32][256] (512B pitch, 8-granule XOR), P bf16 hi/lo [64][256],
// rowmax/rowsum [64][4]. Total ~162 KB.
__global__ void __launch_bounds__(512, 1) attn_kernel()
{
    extern __shared__ char sm[];
    char* KH  = sm;
    char* KL  = sm + 16384;
    char* QH  = sm + 32768;
    char* QL  = sm + 49152;
    char* VTH = sm + 65536;
    char* VTL = sm + 81920;
    char* PH  = sm + 98304;
    char* PL  = sm + 131072;
    float* rmax = (float*)(sm + 163840);   // [64][4]
    float* rsum = (float*)(sm + 164864);   // [64][4]

    int s = blockIdx.x >> 2;
    int h = blockIdx.x & 3;
    int tid = threadIdx.x;
    size_t base = (size_t)s * 256 * EDIM + h * CD;

    // prep K/Q: bf16 hi/lo split, [r][32] 64B pitch, granule swizzle gr^(r&3)
    {
        int r = tid & 255;
        const float* src = ((tid < 256) ? g_k : g_q) + base + (size_t)r * EDIM;
        char* DH = (tid < 256) ? KH : QH;
        char* DL = (tid < 256) ? KL : QL;
        #pragma unroll
        for (int w16 = 0; w16 < 16; w16++) {
            float2 f = *(const float2*)(src + w16 * 2);
            __nv_bfloat162 hi2 = __floats2bfloat162_rn(f.x, f.y);
            float rx = f.x - __bfloat162float(__low2bfloat16(hi2));
            float ry = f.y - __bfloat162float(__high2bfloat16(hi2));
            __nv_bfloat162 lo2 = __floats2bfloat162_rn(rx, ry);
            int gr = w16 >> 2;
            int off = r * 64 + ((gr ^ (r & 3)) << 4) + (w16 & 3) * 4;
            *(uint32_t*)(DH + off) = *(uint32_t*)&hi2;
            *(uint32_t*)(DL + off) = *(uint32_t*)&lo2;
        }
    }
    // prep Vt: [c][v] bf16 hi/lo, 512B pitch, granule swizzle gr^(c&7)
    {
        int r = tid & 255, half = tid >> 8;
        const float* src = g_v + base + (size_t)r * EDIM + half * 16;
        #pragma unroll
        for (int j4 = 0; j4 < 4; j4++) {
            float4 f = *(const float4*)(src + j4 * 4);
            float vals[4] = {f.x, f.y, f.z, f.w};
            #pragma unroll
            for (int jj = 0; jj < 4; jj++) {
                int c = half * 16 + j4 * 4 + jj;
                float v = vals[jj];
                __nv_bfloat16 hb = __float2bfloat16_rn(v);
                __nv_bfloat16 lb = __float2bfloat16_rn(v - __bfloat162float(hb));
                int off = c * 512 + (((r >> 3) ^ (c & 7)) << 4) + ((r >> 1) & 3) * 4 + (r & 1) * 2;
                *(__nv_bfloat16*)(VTH + off) = hb;
                *(__nv_bfloat16*)(VTL + off) = lb;
            }
        }
    }
    __syncthreads();

    int w = tid >> 5, l = tid & 31;
    int g = l >> 2, l3 = l & 3;
    int wm = w >> 2, wn = w & 3;   // scores: rows wm*16+, cols wn*64+; AV: rows wm*16+, cols wn*8+
    const float* mb = g_mb + (size_t)h * RROWS;

    for (int c0 = 0; c0 < 256; c0 += 64) {
        // ---- scores: 16x64 warp tile over 64x256, k=32 (2 ksteps), 3-term split ----
        float acc[8][4];
        #pragma unroll
        for (int nf = 0; nf < 8; nf++)
            #pragma unroll
            for (int j = 0; j < 4; j++) acc[nf][j] = 0.0f;

        int r0 = c0 + wm * 16 + g, r1 = r0 + 8;
        #pragma unroll
        for (int ks = 0; ks < 2; ks++) {
            int ga = ks * 2, gb = ks * 2 + 1;
            uint32_t ah[4], al[4];
            int oa0 = r0 * 64 + ((ga ^ (r0 & 3)) << 4) + l3 * 4;
            int oa1 = r1 * 64 + ((ga ^ (r1 & 3)) << 4) + l3 * 4;
            int oa2 = r0 * 64 + ((gb ^ (r0 & 3)) << 4) + l3 * 4;
            int oa3 = r1 * 64 + ((gb ^ (r1 & 3)) << 4) + l3 * 4;
            ah[0] = *(uint32_t*)(KH + oa0); ah[1] = *(uint32_t*)(KH + oa1);
            ah[2] = *(uint32_t*)(KH + oa2); ah[3] = *(uint32_t*)(KH + oa3);
            al[0] = *(uint32_t*)(KL + oa0); al[1] = *(uint32_t*)(KL + oa1);
            al[2] = *(uint32_t*)(KL + oa2); al[3] = *(uint32_t*)(KL + oa3);
            #pragma unroll
            for (int nf = 0; nf < 8; nf++) {
                int n = wn * 64 + nf * 8 + g;
                int ob0 = n * 64 + ((ga ^ (n & 3)) << 4) + l3 * 4;
                int ob1 = n * 64 + ((gb ^ (n & 3)) << 4) + l3 * 4;
                uint32_t bh[2], bl[2];
                bh[0] = *(uint32_t*)(QH + ob0); bh[1] = *(uint32_t*)(QH + ob1);
                bl[0] = *(uint32_t*)(QL + ob0); bl[1] = *(uint32_t*)(QL + ob1);
                MMA_BF16(acc[nf], ah, bh);
                MMA_BF16(acc[nf], ah, bl);
                MMA_BF16(acc[nf], al, bh);
            }
        }

        // ---- add mask+bias ----
        #pragma unroll
        for (int nf = 0; nf < 8; nf++) {
            int vi = wn * 64 + nf * 8 + l3 * 2;
            float2 m0 = __ldg((const float2*)&mb[(size_t)r0 * 256 + vi]);
            float2 m1 = __ldg((const float2*)&mb[(size_t)r1 * 256 + vi]);
            acc[nf][0] += m0.x; acc[nf][1] += m0.y;
            acc[nf][2] += m1.x; acc[nf][3] += m1.y;
        }

        // ---- softmax (cross-warp over 4 column warps) ----
        int lrA = wm * 16 + g, lrB = lrA + 8;
        float mA = -1e30f, mB = -1e30f;
        #pragma unroll
        for (int nf = 0; nf < 8; nf++) {
            mA = fmaxf(mA, fmaxf(acc[nf][0], acc[nf][1]));
            mB = fmaxf(mB, fmaxf(acc[nf][2], acc[nf][3]));
        }
        mA = fmaxf(mA, __shfl_xor_sync(0xffffffffu, mA, 1));
        mA = fmaxf(mA, __shfl_xor_sync(0xffffffffu, mA, 2));
        mB = fmaxf(mB, __shfl_xor_sync(0xffffffffu, mB, 1));
        mB = fmaxf(mB, __shfl_xor_sync(0xffffffffu, mB, 2));
        if (l3 == 0) { rmax[lrA * 4 + wn] = mA; rmax[lrB * 4 + wn] = mB; }
        __syncthreads();
        mA = fmaxf(fmaxf(rmax[lrA*4+0], rmax[lrA*4+1]), fmaxf(rmax[lrA*4+2], rmax[lrA*4+3]));
        mB = fmaxf(fmaxf(rmax[lrB*4+0], rmax[lrB*4+1]), fmaxf(rmax[lrB*4+2], rmax[lrB*4+3]));

        float sA = 0.0f, sB = 0.0f;
        #pragma unroll
        for (int nf = 0; nf < 8; nf++) {
            acc[nf][0] = __expf(acc[nf][0] - mA); sA += acc[nf][0];
            acc[nf][1] = __expf(acc[nf][1] - mA); sA += acc[nf][1];
            acc[nf][2] = __expf(acc[nf][2] - mB); sB += acc[nf][2];
            acc[nf][3] = __expf(acc[nf][3] - mB); sB += acc[nf][3];
        }
        sA += __shfl_xor_sync(0xffffffffu, sA, 1);
        sA += __shfl_xor_sync(0xffffffffu, sA, 2);
        sB += __shfl_xor_sync(0xffffffffu, sB, 1);
        sB += __shfl_xor_sync(0xffffffffu, sB, 2);
        if (l3 == 0) { rsum[lrA * 4 + wn] = sA; rsum[lrB * 4 + wn] = sB; }
        __syncthreads();
        float invA = 1.0f / (rsum[lrA*4+0] + rsum[lrA*4+1] + rsum[lrA*4+2] + rsum[lrA*4+3]);
        float invB = 1.0f / (rsum[lrB*4+0] + rsum[lrB*4+1] + rsum[lrB*4+2] + rsum[lrB*4+3]);

        // ---- write P (bf16 hi/lo) to smem in mma-A layout ----
        #pragma unroll
        for (int nf = 0; nf < 8; nf++) {
            int gr = wn * 8 + nf;
            float pa0 = acc[nf][0] * invA, pa1 = acc[nf][1] * invA;
            float pb0 = acc[nf][2] * invB, pb1 = acc[nf][3] * invB;
            __nv_bfloat162 hA = __floats2bfloat162_rn(pa0, pa1);
            __nv_bfloat162 lA = __floats2bfloat162_rn(
                pa0 - __bfloat162float(__low2bfloat16(hA)),
                pa1 - __bfloat162float(__high2bfloat16(hA)));
            __nv_bfloat162 hB = __floats2bfloat162_rn(pb0, pb1);
            __nv_bfloat162 lB = __floats2bfloat162_rn(
                pb0 - __bfloat162float(__low2bfloat16(hB)),
                pb1 - __bfloat162float(__high2bfloat16(hB)));
            int offA = lrA * 512 + ((gr ^ (lrA & 7)) << 4) + l3 * 4;
            int offB = lrB * 512 + ((gr ^ (lrB & 7)) << 4) + l3 * 4;
            *(uint32_t*)(PH + offA) = *(uint32_t*)&hA;
            *(uint32_t*)(PL + offA) = *(uint32_t*)&lA;
            *(uint32_t*)(PH + offB) = *(uint32_t*)&hB;
            *(uint32_t*)(PL + offB) = *(uint32_t*)&lB;
        }
        __syncthreads();

        // ---- AV: 16x8 warp tile over 64x32, k=256 (16 ksteps), 3-term split ----
        float o[4] = {0.0f, 0.0f, 0.0f, 0.0f};
        #pragma unroll
        for (int ks = 0; ks < 16; ks++) {
            int ga = ks * 2, gb = ks * 2 + 1;
            uint32_t ah[4], al[4], bh[2], bl[2];
            int oa0 = lrA * 512 + ((ga ^ (lrA & 7)) << 4) + l3 * 4;
            int oa1 = lrB * 512 + ((ga ^ (lrB & 7)) << 4) + l3 * 4;
            int oa2 = lrA * 512 + ((gb ^ (lrA & 7)) << 4) + l3 * 4;
            int oa3 = lrB * 512 + ((gb ^ (lrB & 7)) << 4) + l3 * 4;
            ah[0] = *(uint32_t*)(PH + oa0); ah[1] = *(uint32_t*)(PH + oa1);
            ah[2] = *(uint32_t*)(PH + oa2); ah[3] = *(uint32_t*)(PH + oa3);
            al[0] = *(uint32_t*)(PL + oa0); al[1] = *(uint32_t*)(PL + oa1);
            al[2] = *(uint32_t*)(PL + oa2); al[3] = *(uint32_t*)(PL + oa3);
            int n = wn * 8 + g;
            int ob0 = n * 512 + ((ga ^ (n & 7)) << 4) + l3 * 4;
            int ob1 = n * 512 + ((gb ^ (n & 7)) << 4) + l3 * 4;
            bh[0] = *(uint32_t*)(VTH + ob0); bh[1] = *(uint32_t*)(VTH + ob1);
            bl[0] = *(uint32_t*)(VTL + ob0); bl[1] = *(uint32_t*)(VTL + ob1);
            MMA_BF16(o, ah, bh);
            MMA_BF16(o, ah, bl);
            MMA_BF16(o, al, bh);
        }

        // ---- gate with fu, store ----
        {
            int cc = wn * 8 + l3 * 2;
            size_t iA = base + (size_t)r0 * EDIM + cc;
            size_t iB = base + (size_t)r1 * EDIM + cc;
            float2 fA = *(const float2*)&g_fu[iA];
            float2 fB = *(const float2*)&g_fu[iB];
            *(float2*)&g_ao[iA] = make_float2(o[0] * fA.x, o[1] * fA.y);
            *(float2*)&g_ao[iB] = make_float2(o[2] * fB.x, o[3] * fB.y);
        }
        __syncthreads();
    }
}

// ---------------- host launch ----------------
extern "C" void kernel_launch(void* const* d_in, const int* in_sizes, int n_in,
                              void* d_out, int out_size)
{
    const float* pair_rep = (const float*)d_in[0];
    const float* mask     = (const float*)d_in[1];
    const float* gamma    = (const float*)d_in[2];
    const float* beta     = (const float*)d_in[3];
    const float* Wq       = (const float*)d_in[4];
    const float* Wk       = (const float*)d_in[5];
    const float* Wv       = (const float*)d_in[6];
    const float* Wb       = (const float*)d_in[7];
    const float* Wfu      = (const float*)d_in[8];
    const float* bfu      = (const float*)d_in[9];
    const float* Wo       = (const float*)d_in[10];
    const float* bo       = (const float*)d_in[11];
    float* out = (float*)d_out;

    const int GEMM_SMEM = 128 * 1024;
    const int ATTN_SMEM = 165888;   // 162 KB
    cudaFuncSetAttribute(gemm_proj_kernel, cudaFuncAttributeMaxDynamicSharedMemorySize, GEMM_SMEM);
    cudaFuncSetAttribute(gemm_out_kernel,  cudaFuncAttributeMaxDynamicSharedMemorySize, GEMM_SMEM);
    cudaFuncSetAttribute(attn_kernel,      cudaFuncAttributeMaxDynamicSharedMemorySize, ATTN_SMEM);

    pack_w_kernel<<<(512 * 128 + 128 * 128) / 256, 256>>>(Wq, Wk, Wv, Wfu, Wo);
    ln_kernel<<<RROWS, 128>>>(pair_rep, mask, gamma, beta, Wb);
    gemm_proj_kernel<<<RROWS / 128, 512, GEMM_SMEM>>>(bfu);
    attn_kernel<<<LSEQ * NH, 512, ATTN_SMEM>>>();
    gemm_out_kernel<<<RROWS / 128, 512, GEMM_SMEM>>>(bo, out);
}

// round 11
// speedup vs baseline: 1.9906x; 1.0100x over previous
#include <cuda_runtime.h>
#include <cuda_bf16.h>
#include <stdint.h>
#include <math.h>

#define LSEQ 256
#define EDIM 128
#define NH 4
#define CD 32
#define RROWS (LSEQ*LSEQ)   // 65536

// ---------------- scratch (device globals; no allocs allowed) ----------------
__device__ float g_x [RROWS*EDIM];
__device__ float g_q [RROWS*EDIM];   // pre-scaled by C^-0.5  (the "v-indexed" operand)
__device__ float g_k [RROWS*EDIM];   // the "q-indexed" operand
__device__ float g_v [RROWS*EDIM];
__device__ float g_fu[RROWS*EDIM];   // sigmoid(x@Wfu + bfu)
__device__ float g_mb[NH*RROWS];     // mb[h][q*256+v] = mask[q,v] + bias[q,v,h]
__device__ float g_ao[RROWS*EDIM];   // gated attention output
// packed+transposed+bf16-split weights: [n][k] layout (col-major B for mma)
__device__ __nv_bfloat16 g_Wt_hi [512*128];
__device__ __nv_bfloat16 g_Wt_lo [512*128];
__device__ __nv_bfloat16 g_Wot_hi[128*128];
__device__ __nv_bfloat16 g_Wot_lo[128*128];

// ---------------- mma / ldmatrix helpers ----------------
#define MMA_BF16(d, a, b) \
    asm volatile("mma.sync.aligned.m16n8k16.row.col.f32.bf16.bf16.f32 " \
        "{%0,%1,%2,%3}, {%4,%5,%6,%7}, {%8,%9}, {%0,%1,%2,%3};" \
        : "+f"(d[0]), "+f"(d[1]), "+f"(d[2]), "+f"(d[3]) \
        : "r"(a[0]), "r"(a[1]), "r"(a[2]), "r"(a[3]), "r"(b[0]), "r"(b[1]))

#define LDSM_X4(d0, d1, d2, d3, a) \
    asm volatile("ldmatrix.sync.aligned.m8n8.x4.shared.b16 {%0,%1,%2,%3}, [%4];" \
        : "=r"(d0), "=r"(d1), "=r"(d2), "=r"(d3) : "r"(a))

// ---------------- kernel: pack + transpose + bf16-split weights ----------------
__global__ void pack_w_kernel(const float* __restrict__ Wq, const float* __restrict__ Wk,
                              const float* __restrict__ Wv, const float* __restrict__ Wfu,
                              const float* __restrict__ Wo)
{
    int idx = blockIdx.x * blockDim.x + threadIdx.x;
    if (idx < 512 * 128) {
        int n = idx >> 7, k = idx & 127;
        const float* src = (n < 128) ? Wq : (n < 256) ? Wk : (n < 384) ? Wv : Wfu;
        float v = src[k * 128 + (n & 127)];
        __nv_bfloat16 h = __float2bfloat16_rn(v);
        g_Wt_hi[idx] = h;
        g_Wt_lo[idx] = __float2bfloat16_rn(v - __bfloat162float(h));
    } else {
        int j = idx - 512 * 128;
        int n = j >> 7, k = j & 127;
        float v = Wo[k * 128 + n];
        __nv_bfloat16 h = __float2bfloat16_rn(v);
        g_Wot_hi[j] = h;
        g_Wot_lo[j] = __float2bfloat16_rn(v - __bfloat162float(h));
    }
}

// ---------------- kernel: layernorm + pair_bias(+mask) ----------------
__global__ void __launch_bounds__(128) ln_kernel(
    const float* __restrict__ pr, const float* __restrict__ mask,
    const float* __restrict__ gamma, const float* __restrict__ beta,
    const float* __restrict__ Wb)
{
    int r = blockIdx.x;
    int t = threadIdx.x;
    float v = pr[(size_t)r * EDIM + t];

    float s = v, s2 = v * v;
    #pragma unroll
    for (int o = 16; o; o >>= 1) {
        s  += __shfl_xor_sync(0xffffffffu, s,  o);
        s2 += __shfl_xor_sync(0xffffffffu, s2, o);
    }
    __shared__ float sh[8];
    int w = t >> 5, lane = t & 31;
    if (lane == 0) { sh[w] = s; sh[4 + w] = s2; }
    __syncthreads();
    s  = sh[0] + sh[1] + sh[2] + sh[3];
    s2 = sh[4] + sh[5] + sh[6] + sh[7];
    float mu  = s * (1.0f / EDIM);
    float var = s2 * (1.0f / EDIM) - mu * mu;
    float x = (v - mu) * rsqrtf(var + 1e-5f) * gamma[t] + beta[t];
    g_x[(size_t)r * EDIM + t] = x;

    float b0 = x * Wb[t * 4 + 0];
    float b1 = x * Wb[t * 4 + 1];
    float b2 = x * Wb[t * 4 + 2];
    float b3 = x * Wb[t * 4 + 3];
    #pragma unroll
    for (int o = 16; o; o >>= 1) {
        b0 += __shfl_xor_sync(0xffffffffu, b0, o);
        b1 += __shfl_xor_sync(0xffffffffu, b1, o);
        b2 += __shfl_xor_sync(0xffffffffu, b2, o);
        b3 += __shfl_xor_sync(0xffffffffu, b3, o);
    }
    __shared__ float shb[16];
    if (lane == 0) { shb[w*4+0]=b0; shb[w*4+1]=b1; shb[w*4+2]=b2; shb[w*4+3]=b3; }
    __syncthreads();
    if (t < 4) {
        float b = shb[t] + shb[4 + t] + shb[8 + t] + shb[12 + t];
        g_mb[t * RROWS + r] = mask[r] + b;
    }
}

// ---------------- conversion helper: 8 floats -> hi/lo bf16 granules ----------------
__device__ __forceinline__ void split8(const float* fs, uint4& hi, uint4& lo)
{
    uint32_t h[4], l[4];
    #pragma unroll
    for (int j = 0; j < 4; j++) {
        __nv_bfloat162 h2 = __floats2bfloat162_rn(fs[2*j], fs[2*j+1]);
        float r0 = fs[2*j]   - __bfloat162float(__low2bfloat16(h2));
        float r1 = fs[2*j+1] - __bfloat162float(__high2bfloat16(h2));
        __nv_bfloat162 l2 = __floats2bfloat162_rn(r0, r1);
        h[j] = *(uint32_t*)&h2;
        l[j] = *(uint32_t*)&l2;
    }
    hi = make_uint4(h[0], h[1], h[2], h[3]);
    lo = make_uint4(l[0], l[1], l[2], l[3]);
}

// swizzled byte offset for row r (256B pitch), 16B granule c
#define SWOFF(r, c) ((r) * 256 + ((((c) ^ ((r) & 7))) << 4))

// ---------------- kernel: projection GEMM via bf16-split tensor cores ----------------
__global__ void __launch_bounds__(512, 1) gemm_proj_kernel(const float* __restrict__ bfu)
{
    extern __shared__ char smem[];
    char* As_hi = smem;
    char* As_lo = smem + 32768;
    char* Bs_hi = smem + 65536;
    char* Bs_lo = smem + 98304;

    int m0 = blockIdx.x * 128;
    int tid = threadIdx.x;
    int cg = tid & 15, rb = tid >> 4;

    #pragma unroll
    for (int i = 0; i < 4; i++) {
        int r = rb + i * 32;
        const float* src = &g_x[(size_t)(m0 + r) * EDIM + cg * 8];
        float4 f0 = *(const float4*)src;
        float4 f1 = *(const float4*)(src + 4);
        float fs[8] = {f0.x,f0.y,f0.z,f0.w,f1.x,f1.y,f1.z,f1.w};
        uint4 hi, lo;
        split8(fs, hi, lo);
        int off = SWOFF(r, cg);
        *(uint4*)(As_hi + off) = hi;
        *(uint4*)(As_lo + off) = lo;
    }

    int w = tid >> 5, l = tid & 31;
    int mw = (w & 3) * 32, nw = (w >> 2) * 32;
    int g = l >> 2, c4 = (l & 3) * 4;
    const float qscale = 0.17677669529663687f;

    for (int nt = 0; nt < 4; nt++) {
        __syncthreads();
        #pragma unroll
        for (int i = 0; i < 4; i++) {
            int r = rb + i * 32;
            int off = SWOFF(r, cg);
            size_t gi = (size_t)(nt * 128 + r) * 128 + cg * 8;
            *(uint4*)(Bs_hi + off) = *(const uint4*)(g_Wt_hi + gi);
            *(uint4*)(Bs_lo + off) = *(const uint4*)(g_Wt_lo + gi);
        }
        __syncthreads();

        float acc[2][4][4];
        #pragma unroll
        for (int mt = 0; mt < 2; mt++)
            #pragma unroll
            for (int n4 = 0; n4 < 4; n4++)
                #pragma unroll
                for (int j = 0; j < 4; j++) acc[mt][n4][j] = 0.0f;

        #pragma unroll
        for (int ks = 0; ks < 8; ks++) {
            uint32_t ah[2][4], al[2][4], bh[4][2], bl[4][2];
            #pragma unroll
            for (int mt = 0; mt < 2; mt++) {
                int r0 = mw + mt * 16 + g, r1 = r0 + 8;
                int ga = ks * 2, gb = ks * 2 + 1;
                int o0 = SWOFF(r0, ga) + c4, o1 = SWOFF(r1, ga) + c4;
                int o2 = SWOFF(r0, gb) + c4, o3 = SWOFF(r1, gb) + c4;
                ah[mt][0] = *(uint32_t*)(As_hi + o0); ah[mt][1] = *(uint32_t*)(As_hi + o1);
                ah[mt][2] = *(uint32_t*)(As_hi + o2); ah[mt][3] = *(uint32_t*)(As_hi + o3);
                al[mt][0] = *(uint32_t*)(As_lo + o0); al[mt][1] = *(uint32_t*)(As_lo + o1);
                al[mt][2] = *(uint32_t*)(As_lo + o2); al[mt][3] = *(uint32_t*)(As_lo + o3);
            }
            #pragma unroll
            for (int n4 = 0; n4 < 4; n4++) {
                int n = nw + n4 * 8 + g;
                int o0 = SWOFF(n, ks * 2) + c4, o1 = SWOFF(n, ks * 2 + 1) + c4;
                bh[n4][0] = *(uint32_t*)(Bs_hi + o0); bh[n4][1] = *(uint32_t*)(Bs_hi + o1);
                bl[n4][0] = *(uint32_t*)(Bs_lo + o0); bl[n4][1] = *(uint32_t*)(Bs_lo + o1);
            }
            #pragma unroll
            for (int mt = 0; mt < 2; mt++)
                #pragma unroll
                for (int n4 = 0; n4 < 4; n4++) {
                    MMA_BF16(acc[mt][n4], ah[mt], bh[n4]);
                    MMA_BF16(acc[mt][n4], ah[mt], bl[n4]);
                    MMA_BF16(acc[mt][n4], al[mt], bh[n4]);
                }
        }

        float* dst = (nt == 0) ? g_q : (nt == 1) ? g_k : (nt == 2) ? g_v : g_fu;
        #pragma unroll
        for (int mt = 0; mt < 2; mt++)
            #pragma unroll
            for (int n4 = 0; n4 < 4; n4++) {
                int m = m0 + mw + mt * 16 + g;
                int ncol = nw + n4 * 8 + (l & 3) * 2;
                float v0 = acc[mt][n4][0], v1 = acc[mt][n4][1];
                float v2 = acc[mt][n4][2], v3 = acc[mt][n4][3];
                if (nt == 0) { v0 *= qscale; v1 *= qscale; v2 *= qscale; v3 *= qscale; }
                if (nt == 3) {
                    float bf0 = bfu[ncol], bf1 = bfu[ncol + 1];
                    v0 = 1.0f / (1.0f + __expf(-(v0 + bf0)));
                    v1 = 1.0f / (1.0f + __expf(-(v1 + bf1)));
                    v2 = 1.0f / (1.0f + __expf(-(v2 + bf0)));
                    v3 = 1.0f / (1.0f + __expf(-(v3 + bf1)));
                }
                *(float2*)&dst[(size_t)m * EDIM + ncol]       = make_float2(v0, v1);
                *(float2*)&dst[(size_t)(m + 8) * EDIM + ncol] = make_float2(v2, v3);
            }
    }
}

// ---------------- kernel: output GEMM via bf16-split tensor cores ----------------
__global__ void __launch_bounds__(512, 1) gemm_out_kernel(
    const float* __restrict__ bo, float* __restrict__ out)
{
    extern __shared__ char smem[];
    char* As_hi = smem;
    char* As_lo = smem + 32768;
    char* Bs_hi = smem + 65536;
    char* Bs_lo = smem + 98304;

    int m0 = blockIdx.x * 128;
    int tid = threadIdx.x;
    int cg = tid & 15, rb = tid >> 4;

    #pragma unroll
    for (int i = 0; i < 4; i++) {
        int r = rb + i * 32;
        const float* src = &g_ao[(size_t)(m0 + r) * EDIM + cg * 8];
        float4 f0 = *(const float4*)src;
        float4 f1 = *(const float4*)(src + 4);
        float fs[8] = {f0.x,f0.y,f0.z,f0.w,f1.x,f1.y,f1.z,f1.w};
        uint4 hi, lo;
        split8(fs, hi, lo);
        int off = SWOFF(r, cg);
        *(uint4*)(As_hi + off) = hi;
        *(uint4*)(As_lo + off) = lo;

        size_t gi = (size_t)r * 128 + cg * 8;
        *(uint4*)(Bs_hi + off) = *(const uint4*)(g_Wot_hi + gi);
        *(uint4*)(Bs_lo + off) = *(const uint4*)(g_Wot_lo + gi);
    }
    __syncthreads();

    int w = tid >> 5, l = tid & 31;
    int mw = (w & 3) * 32, nw = (w >> 2) * 32;
    int g = l >> 2, c4 = (l & 3) * 4;

    float acc[2][4][4];
    #pragma unroll
    for (int mt = 0; mt < 2; mt++)
        #pragma unroll
        for (int n4 = 0; n4 < 4; n4++)
            #pragma unroll
            for (int j = 0; j < 4; j++) acc[mt][n4][j] = 0.0f;

    #pragma unroll
    for (int ks = 0; ks < 8; ks++) {
        uint32_t ah[2][4], al[2][4], bh[4][2], bl[4][2];
        #pragma unroll
        for (int mt = 0; mt < 2; mt++) {
            int r0 = mw + mt * 16 + g, r1 = r0 + 8;
            int ga = ks * 2, gb = ks * 2 + 1;
            int o0 = SWOFF(r0, ga) + c4, o1 = SWOFF(r1, ga) + c4;
            int o2 = SWOFF(r0, gb) + c4, o3 = SWOFF(r1, gb) + c4;
            ah[mt][0] = *(uint32_t*)(As_hi + o0); ah[mt][1] = *(uint32_t*)(As_hi + o1);
            ah[mt][2] = *(uint32_t*)(As_hi + o2); ah[mt][3] = *(uint32_t*)(As_hi + o3);
            al[mt][0] = *(uint32_t*)(As_lo + o0); al[mt][1] = *(uint32_t*)(As_lo + o1);
            al[mt][2] = *(uint32_t*)(As_lo + o2); al[mt][3] = *(uint32_t*)(As_lo + o3);
        }
        #pragma unroll
        for (int n4 = 0; n4 < 4; n4++) {
            int n = nw + n4 * 8 + g;
            int o0 = SWOFF(n, ks * 2) + c4, o1 = SWOFF(n, ks * 2 + 1) + c4;
            bh[n4][0] = *(uint32_t*)(Bs_hi + o0); bh[n4][1] = *(uint32_t*)(Bs_hi + o1);
            bl[n4][0] = *(uint32_t*)(Bs_lo + o0); bl[n4][1] = *(uint32_t*)(Bs_lo + o1);
        }
        #pragma unroll
        for (int mt = 0; mt < 2; mt++)
            #pragma unroll
            for (int n4 = 0; n4 < 4; n4++) {
                MMA_BF16(acc[mt][n4], ah[mt], bh[n4]);
                MMA_BF16(acc[mt][n4], ah[mt], bl[n4]);
                MMA_BF16(acc[mt][n4], al[mt], bh[n4]);
            }
    }

    #pragma unroll
    for (int mt = 0; mt < 2; mt++)
        #pragma unroll
        for (int n4 = 0; n4 < 4; n4++) {
            int m = m0 + mw + mt * 16 + g;
            int ncol = nw + n4 * 8 + (l & 3) * 2;
            float b0 = bo[ncol], b1 = bo[ncol + 1];
            *(float2*)&out[(size_t)m * EDIM + ncol] =
                make_float2(acc[mt][n4][0] + b0, acc[mt][n4][1] + b1);
            *(float2*)&out[(size_t)(m + 8) * EDIM + ncol] =
                make_float2(acc[mt][n4][2] + b0, acc[mt][n4][3] + b1);
        }
}

// ---------------- kernel: tensor-core attention per (s,h), ldmatrix frag loads ----------------
// smem layout identical to R10: K/Q hi/lo [256][32] (64B pitch, granule^(r&3)),
// Vt hi/lo [32][256] (512B pitch, granule^(c&7)), P hi/lo [64][256], rmax/rsum.
__global__ void __launch_bounds__(512, 1) attn_kernel()
{
    extern __shared__ char sm[];
    char* KH  = sm;
    char* KL  = sm + 16384;
    char* QH  = sm + 32768;
    char* QL  = sm + 49152;
    char* VTH = sm + 65536;
    char* VTL = sm + 81920;
    char* PH  = sm + 98304;
    char* PL  = sm + 131072;
    float* rmax = (float*)(sm + 163840);   // [64][4]
    float* rsum = (float*)(sm + 164864);   // [64][4]

    int s = blockIdx.x >> 2;
    int h = blockIdx.x & 3;
    int tid = threadIdx.x;
    size_t base = (size_t)s * 256 * EDIM + h * CD;

    // prep K/Q: bf16 hi/lo split, [r][32] 64B pitch, granule swizzle gr^(r&3)
    {
        int r = tid & 255;
        const float* src = ((tid < 256) ? g_k : g_q) + base + (size_t)r * EDIM;
        char* DH = (tid < 256) ? KH : QH;
        char* DL = (tid < 256) ? KL : QL;
        #pragma unroll
        for (int w16 = 0; w16 < 16; w16++) {
            float2 f = *(const float2*)(src + w16 * 2);
            __nv_bfloat162 hi2 = __floats2bfloat162_rn(f.x, f.y);
            float rx = f.x - __bfloat162float(__low2bfloat16(hi2));
            float ry = f.y - __bfloat162float(__high2bfloat16(hi2));
            __nv_bfloat162 lo2 = __floats2bfloat162_rn(rx, ry);
            int gr = w16 >> 2;
            int off = r * 64 + ((gr ^ (r & 3)) << 4) + (w16 & 3) * 4;
            *(uint32_t*)(DH + off) = *(uint32_t*)&hi2;
            *(uint32_t*)(DL + off) = *(uint32_t*)&lo2;
        }
    }
    // prep Vt: [c][v] bf16 hi/lo, 512B pitch, granule swizzle gr^(c&7)
    {
        int r = tid & 255, half = tid >> 8;
        const float* src = g_v + base + (size_t)r * EDIM + half * 16;
        #pragma unroll
        for (int j4 = 0; j4 < 4; j4++) {
            float4 f = *(const float4*)(src + j4 * 4);
            float vals[4] = {f.x, f.y, f.z, f.w};
            #pragma unroll
            for (int jj = 0; jj < 4; jj++) {
                int c = half * 16 + j4 * 4 + jj;
                float v = vals[jj];
                __nv_bfloat16 hb = __float2bfloat16_rn(v);
                __nv_bfloat16 lb = __float2bfloat16_rn(v - __bfloat162float(hb));
                int off = c * 512 + (((r >> 3) ^ (c & 7)) << 4) + ((r >> 1) & 3) * 4 + (r & 1) * 2;
                *(__nv_bfloat16*)(VTH + off) = hb;
                *(__nv_bfloat16*)(VTL + off) = lb;
            }
        }
    }
    __syncthreads();

    // shared-space bases for ldmatrix
    uint32_t kh_s  = (uint32_t)__cvta_generic_to_shared(KH);
    uint32_t kl_s  = (uint32_t)__cvta_generic_to_shared(KL);
    uint32_t qh_s  = (uint32_t)__cvta_generic_to_shared(QH);
    uint32_t ql_s  = (uint32_t)__cvta_generic_to_shared(QL);
    uint32_t vth_s = (uint32_t)__cvta_generic_to_shared(VTH);
    uint32_t vtl_s = (uint32_t)__cvta_generic_to_shared(VTL);
    uint32_t ph_s  = (uint32_t)__cvta_generic_to_shared(PH);
    uint32_t pl_s  = (uint32_t)__cvta_generic_to_shared(PL);

    int w = tid >> 5, l = tid & 31;
    int g = l >> 2, l3 = l & 3;
    int mi = l >> 3, rr = l & 7;           // ldmatrix role: matrix index, row-in-matrix
    int wm = w >> 2, wn = w & 3;
    const float* mb = g_mb + (size_t)h * RROWS;

    // ldmatrix-invariant row indices
    int RP = wm * 16 + (mi & 1) * 8 + rr;  // P row for AV A-frags
    int nV = wn * 8 + rr;                  // V row (c) for AV B-frags
    uint32_t offP_base = (uint32_t)(RP * 512);
    uint32_t offV_base = (uint32_t)(nV * 512);
    int RPx = RP & 7, nVx = nV & 7;

    for (int c0 = 0; c0 < 256; c0 += 64) {
        // ---- scores: 16x64 warp tile over 64x256, k=32 (2 ksteps), 3-term split ----
        float acc[8][4];
        #pragma unroll
        for (int nf = 0; nf < 8; nf++)
            #pragma unroll
            for (int j = 0; j < 4; j++) acc[nf][j] = 0.0f;

        int r0 = c0 + wm * 16 + g, r1 = r0 + 8;
        int RA = c0 + wm * 16 + (mi & 1) * 8 + rr;   // K row for A-frags

        #pragma unroll
        for (int ks = 0; ks < 2; ks++) {
            uint32_t ah[4], al[4];
            {
                int gA = ks * 2 + (mi >> 1);
                uint32_t offA = RA * 64 + ((gA ^ (RA & 3)) << 4);
                LDSM_X4(ah[0], ah[1], ah[2], ah[3], kh_s + offA);
                LDSM_X4(al[0], al[1], al[2], al[3], kl_s + offA);
            }
            #pragma unroll
            for (int np = 0; np < 4; np++) {
                int nB = wn * 64 + np * 16 + (mi >> 1) * 8 + rr;
                int gB = ks * 2 + (mi & 1);
                uint32_t offB = nB * 64 + ((gB ^ (nB & 3)) << 4);
                uint32_t b0h, b1h, b2h, b3h, b0l, b1l, b2l, b3l;
                LDSM_X4(b0h, b1h, b2h, b3h, qh_s + offB);
                LDSM_X4(b0l, b1l, b2l, b3l, ql_s + offB);
                uint32_t bhA[2] = {b0h, b1h}, bhB[2] = {b2h, b3h};
                uint32_t blA[2] = {b0l, b1l}, blB[2] = {b2l, b3l};
                MMA_BF16(acc[np * 2],     ah, bhA);
                MMA_BF16(acc[np * 2],     ah, blA);
                MMA_BF16(acc[np * 2],     al, bhA);
                MMA_BF16(acc[np * 2 + 1], ah, bhB);
                MMA_BF16(acc[np * 2 + 1], ah, blB);
                MMA_BF16(acc[np * 2 + 1], al, bhB);
            }
        }

        // ---- add mask+bias ----
        #pragma unroll
        for (int nf = 0; nf < 8; nf++) {
            int vi = wn * 64 + nf * 8 + l3 * 2;
            float2 m0 = __ldg((const float2*)&mb[(size_t)r0 * 256 + vi]);
            float2 m1 = __ldg((const float2*)&mb[(size_t)r1 * 256 + vi]);
            acc[nf][0] += m0.x; acc[nf][1] += m0.y;
            acc[nf][2] += m1.x; acc[nf][3] += m1.y;
        }

        // ---- softmax (cross-warp over 4 column warps) ----
        int lrA = wm * 16 + g, lrB = lrA + 8;
        float mA = -1e30f, mB = -1e30f;
        #pragma unroll
        for (int nf = 0; nf < 8; nf++) {
            mA = fmaxf(mA, fmaxf(acc[nf][0], acc[nf][1]));
            mB = fmaxf(mB, fmaxf(acc[nf][2], acc[nf][3]));
        }
        mA = fmaxf(mA, __shfl_xor_sync(0xffffffffu, mA, 1));
        mA = fmaxf(mA, __shfl_xor_sync(0xffffffffu, mA, 2));
        mB = fmaxf(mB, __shfl_xor_sync(0xffffffffu, mB, 1));
        mB = fmaxf(mB, __shfl_xor_sync(0xffffffffu, mB, 2));
        if (l3 == 0) { rmax[lrA * 4 + wn] = mA; rmax[lrB * 4 + wn] = mB; }
        __syncthreads();
        mA = fmaxf(fmaxf(rmax[lrA*4+0], rmax[lrA*4+1]), fmaxf(rmax[lrA*4+2], rmax[lrA*4+3]));
        mB = fmaxf(fmaxf(rmax[lrB*4+0], rmax[lrB*4+1]), fmaxf(rmax[lrB*4+2], rmax[lrB*4+3]));

        float sA = 0.0f, sB = 0.0f;
        #pragma unroll
        for (int nf = 0; nf < 8; nf++) {
            acc[nf][0] = __expf(acc[nf][0] - mA); sA += acc[nf][0];
            acc[nf][1] = __expf(acc[nf][1] - mA); sA += acc[nf][1];
            acc[nf][2] = __expf(acc[nf][2] - mB); sB += acc[nf][2];
            acc[nf][3] = __expf(acc[nf][3] - mB); sB += acc[nf][3];
        }
        sA += __shfl_xor_sync(0xffffffffu, sA, 1);
        sA += __shfl_xor_sync(0xffffffffu, sA, 2);
        sB += __shfl_xor_sync(0xffffffffu, sB, 1);
        sB += __shfl_xor_sync(0xffffffffu, sB, 2);
        if (l3 == 0) { rsum[lrA * 4 + wn] = sA; rsum[lrB * 4 + wn] = sB; }
        __syncthreads();
        float invA = 1.0f / (rsum[lrA*4+0] + rsum[lrA*4+1] + rsum[lrA*4+2] + rsum[lrA*4+3]);
        float invB = 1.0f / (rsum[lrB*4+0] + rsum[lrB*4+1] + rsum[lrB*4+2] + rsum[lrB*4+3]);

        // ---- write P (bf16 hi/lo) to smem in mma-A layout ----
        #pragma unroll
        for (int nf = 0; nf < 8; nf++) {
            int gr = wn * 8 + nf;
            float pa0 = acc[nf][0] * invA, pa1 = acc[nf][1] * invA;
            float pb0 = acc[nf][2] * invB, pb1 = acc[nf][3] * invB;
            __nv_bfloat162 hA = __floats2bfloat162_rn(pa0, pa1);
            __nv_bfloat162 lA = __floats2bfloat162_rn(
                pa0 - __bfloat162float(__low2bfloat16(hA)),
                pa1 - __bfloat162float(__high2bfloat16(hA)));
            __nv_bfloat162 hB = __floats2bfloat162_rn(pb0, pb1);
            __nv_bfloat162 lB = __floats2bfloat162_rn(
                pb0 - __bfloat162float(__low2bfloat16(hB)),
                pb1 - __bfloat162float(__high2bfloat16(hB)));
            int offA = lrA * 512 + ((gr ^ (lrA & 7)) << 4) + l3 * 4;
            int offB = lrB * 512 + ((gr ^ (lrB & 7)) << 4) + l3 * 4;
            *(uint32_t*)(PH + offA) = *(uint32_t*)&hA;
            *(uint32_t*)(PL + offA) = *(uint32_t*)&lA;
            *(uint32_t*)(PH + offB) = *(uint32_t*)&hB;
            *(uint32_t*)(PL + offB) = *(uint32_t*)&lB;
        }
        __syncthreads();

        // ---- AV: 16x8 warp tile over 64x32, k=256 (16 ksteps), 3-term split ----
        float o[4] = {0.0f, 0.0f, 0.0f, 0.0f};
        #pragma unroll
        for (int ks2 = 0; ks2 < 16; ks2 += 2) {
            // V B-frags for ks2 and ks2+1 in one x4 (matrices = granules 4*ks2'..+3)
            uint32_t vh0, vh1, vh2, vh3, vl0, vl1, vl2, vl3;
            {
                int gV = ks2 * 2 + mi;
                uint32_t offV = offV_base + ((gV ^ nVx) << 4);
                LDSM_X4(vh0, vh1, vh2, vh3, vth_s + offV);
                LDSM_X4(vl0, vl1, vl2, vl3, vtl_s + offV);
            }
            #pragma unroll
            for (int sub = 0; sub < 2; sub++) {
                int ks = ks2 + sub;
                uint32_t ph[4], pl[4];
                int gP = ks * 2 + (mi >> 1);
                uint32_t offP = offP_base + ((gP ^ RPx) << 4);
                LDSM_X4(ph[0], ph[1], ph[2], ph[3], ph_s + offP);
                LDSM_X4(pl[0], pl[1], pl[2], pl[3], pl_s + offP);
                uint32_t bh[2], bl[2];
                if (sub == 0) { bh[0] = vh0; bh[1] = vh1; bl[0] = vl0; bl[1] = vl1; }
                else          { bh[0] = vh2; bh[1] = vh3; bl[0] = vl2; bl[1] = vl3; }
                MMA_BF16(o, ph, bh);
                MMA_BF16(o, ph, bl);
                MMA_BF16(o, pl, bh);
            }
        }

        // ---- gate with fu, store ----
        {
            int cc = wn * 8 + l3 * 2;
            size_t iA = base + (size_t)r0 * EDIM + cc;
            size_t iB = base + (size_t)r1 * EDIM + cc;
            float2 fA = *(const float2*)&g_fu[iA];
            float2 fB = *(const float2*)&g_fu[iB];
            *(float2*)&g_ao[iA] = make_float2(o[0] * fA.x, o[1] * fA.y);
            *(float2*)&g_ao[iB] = make_float2(o[2] * fB.x, o[3] * fB.y);
        }
        __syncthreads();
    }
}

// ---------------- host launch ----------------
extern "C" void kernel_launch(void* const* d_in, const int* in_sizes, int n_in,
                              void* d_out, int out_size)
{
    const float* pair_rep = (const float*)d_in[0];
    const float* mask     = (const float*)d_in[1];
    const float* gamma    = (const float*)d_in[2];
    const float* beta     = (const float*)d_in[3];
    const float* Wq       = (const float*)d_in[4];
    const float* Wk       = (const float*)d_in[5];
    const float* Wv       = (const float*)d_in[6];
    const float* Wb       = (const float*)d_in[7];
    const float* Wfu      = (const float*)d_in[8];
    const float* bfu      = (const float*)d_in[9];
    const float* Wo       = (const float*)d_in[10];
    const float* bo       = (const float*)d_in[11];
    float* out = (float*)d_out;

    const int GEMM_SMEM = 128 * 1024;
    const int ATTN_SMEM = 165888;   // 162 KB
    cudaFuncSetAttribute(gemm_proj_kernel, cudaFuncAttributeMaxDynamicSharedMemorySize, GEMM_SMEM);
    cudaFuncSetAttribute(gemm_out_kernel,  cudaFuncAttributeMaxDynamicSharedMemorySize, GEMM_SMEM);
    cudaFuncSetAttribute(attn_kernel,      cudaFuncAttributeMaxDynamicSharedMemorySize, ATTN_SMEM);

    pack_w_kernel<<<(512 * 128 + 128 * 128) / 256, 256>>>(Wq, Wk, Wv, Wfu, Wo);
    ln_kernel<<<RROWS, 128>>>(pair_rep, mask, gamma, beta, Wb);
    gemm_proj_kernel<<<RROWS / 128, 512, GEMM_SMEM>>>(bfu);
    attn_kernel<<<LSEQ * NH, 512, ATTN_SMEM>>>();
    gemm_out_kernel<<<RROWS / 128, 512, GEMM_SMEM>>>(bo, out);
}

// round 12
// speedup vs baseline: 1.9999x; 1.0047x over previous
#include <cuda_runtime.h>
#include <cuda_bf16.h>
#include <stdint.h>
#include <math.h>

#define LSEQ 256
#define EDIM 128
#define NH 4
#define CD 32
#define RROWS (LSEQ*LSEQ)   // 65536

// ---------------- scratch (device globals; no allocs allowed) ----------------
__device__ float g_x [RROWS*EDIM];
__device__ float g_q [RROWS*EDIM];   // pre-scaled by C^-0.5  (the "v-indexed" operand)
__device__ float g_k [RROWS*EDIM];   // the "q-indexed" operand
__device__ float g_v [RROWS*EDIM];
__device__ float g_fu[RROWS*EDIM];   // sigmoid(x@Wfu + bfu)
__device__ float g_mb[NH*RROWS];     // mb[h][q*256+v] = mask[q,v] + bias[q,v,h]
__device__ float g_ao[RROWS*EDIM];   // gated attention output
// packed+transposed+bf16-split weights: [n][k] layout (col-major B for mma)
__device__ __nv_bfloat16 g_Wt_hi [512*128];
__device__ __nv_bfloat16 g_Wt_lo [512*128];
__device__ __nv_bfloat16 g_Wot_hi[128*128];
__device__ __nv_bfloat16 g_Wot_lo[128*128];

// ---------------- mma / ldmatrix helpers ----------------
#define MMA_BF16(d, a, b) \
    asm volatile("mma.sync.aligned.m16n8k16.row.col.f32.bf16.bf16.f32 " \
        "{%0,%1,%2,%3}, {%4,%5,%6,%7}, {%8,%9}, {%0,%1,%2,%3};" \
        : "+f"(d[0]), "+f"(d[1]), "+f"(d[2]), "+f"(d[3]) \
        : "r"(a[0]), "r"(a[1]), "r"(a[2]), "r"(a[3]), "r"(b[0]), "r"(b[1]))

#define LDSM_X4(d0, d1, d2, d3, a) \
    asm volatile("ldmatrix.sync.aligned.m8n8.x4.shared.b16 {%0,%1,%2,%3}, [%4];" \
        : "=r"(d0), "=r"(d1), "=r"(d2), "=r"(d3) : "r"(a))

__device__ __forceinline__ uint32_t pack_bf2(float a, float b)
{
    __nv_bfloat162 t = __floats2bfloat162_rn(a, b);
    return *(uint32_t*)&t;
}
__device__ __forceinline__ uint32_t pack_bf2_res(float a, float b, uint32_t hi)
{
    __nv_bfloat162 h = *(__nv_bfloat162*)&hi;
    __nv_bfloat162 t = __floats2bfloat162_rn(
        a - __bfloat162float(__low2bfloat16(h)),
        b - __bfloat162float(__high2bfloat16(h)));
    return *(uint32_t*)&t;
}

// ---------------- kernel: pack + transpose + bf16-split weights ----------------
__global__ void pack_w_kernel(const float* __restrict__ Wq, const float* __restrict__ Wk,
                              const float* __restrict__ Wv, const float* __restrict__ Wfu,
                              const float* __restrict__ Wo)
{
    int idx = blockIdx.x * blockDim.x + threadIdx.x;
    if (idx < 512 * 128) {
        int n = idx >> 7, k = idx & 127;
        const float* src = (n < 128) ? Wq : (n < 256) ? Wk : (n < 384) ? Wv : Wfu;
        float v = src[k * 128 + (n & 127)];
        __nv_bfloat16 h = __float2bfloat16_rn(v);
        g_Wt_hi[idx] = h;
        g_Wt_lo[idx] = __float2bfloat16_rn(v - __bfloat162float(h));
    } else {
        int j = idx - 512 * 128;
        int n = j >> 7, k = j & 127;
        float v = Wo[k * 128 + n];
        __nv_bfloat16 h = __float2bfloat16_rn(v);
        g_Wot_hi[j] = h;
        g_Wot_lo[j] = __float2bfloat16_rn(v - __bfloat162float(h));
    }
}

// ---------------- kernel: layernorm + pair_bias(+mask) ----------------
__global__ void __launch_bounds__(128) ln_kernel(
    const float* __restrict__ pr, const float* __restrict__ mask,
    const float* __restrict__ gamma, const float* __restrict__ beta,
    const float* __restrict__ Wb)
{
    int r = blockIdx.x;
    int t = threadIdx.x;
    float v = pr[(size_t)r * EDIM + t];

    float s = v, s2 = v * v;
    #pragma unroll
    for (int o = 16; o; o >>= 1) {
        s  += __shfl_xor_sync(0xffffffffu, s,  o);
        s2 += __shfl_xor_sync(0xffffffffu, s2, o);
    }
    __shared__ float sh[8];
    int w = t >> 5, lane = t & 31;
    if (lane == 0) { sh[w] = s; sh[4 + w] = s2; }
    __syncthreads();
    s  = sh[0] + sh[1] + sh[2] + sh[3];
    s2 = sh[4] + sh[5] + sh[6] + sh[7];
    float mu  = s * (1.0f / EDIM);
    float var = s2 * (1.0f / EDIM) - mu * mu;
    float x = (v - mu) * rsqrtf(var + 1e-5f) * gamma[t] + beta[t];
    g_x[(size_t)r * EDIM + t] = x;

    float b0 = x * Wb[t * 4 + 0];
    float b1 = x * Wb[t * 4 + 1];
    float b2 = x * Wb[t * 4 + 2];
    float b3 = x * Wb[t * 4 + 3];
    #pragma unroll
    for (int o = 16; o; o >>= 1) {
        b0 += __shfl_xor_sync(0xffffffffu, b0, o);
        b1 += __shfl_xor_sync(0xffffffffu, b1, o);
        b2 += __shfl_xor_sync(0xffffffffu, b2, o);
        b3 += __shfl_xor_sync(0xffffffffu, b3, o);
    }
    __shared__ float shb[16];
    if (lane == 0) { shb[w*4+0]=b0; shb[w*4+1]=b1; shb[w*4+2]=b2; shb[w*4+3]=b3; }
    __syncthreads();
    if (t < 4) {
        float b = shb[t] + shb[4 + t] + shb[8 + t] + shb[12 + t];
        g_mb[t * RROWS + r] = mask[r] + b;
    }
}

// ---------------- conversion helper: 8 floats -> hi/lo bf16 granules ----------------
__device__ __forceinline__ void split8(const float* fs, uint4& hi, uint4& lo)
{
    uint32_t h[4], l[4];
    #pragma unroll
    for (int j = 0; j < 4; j++) {
        __nv_bfloat162 h2 = __floats2bfloat162_rn(fs[2*j], fs[2*j+1]);
        float r0 = fs[2*j]   - __bfloat162float(__low2bfloat16(h2));
        float r1 = fs[2*j+1] - __bfloat162float(__high2bfloat16(h2));
        __nv_bfloat162 l2 = __floats2bfloat162_rn(r0, r1);
        h[j] = *(uint32_t*)&h2;
        l[j] = *(uint32_t*)&l2;
    }
    hi = make_uint4(h[0], h[1], h[2], h[3]);
    lo = make_uint4(l[0], l[1], l[2], l[3]);
}

// swizzled byte offset for row r (256B pitch), 16B granule c
#define SWOFF(r, c) ((r) * 256 + ((((c) ^ ((r) & 7))) << 4))

// ---------------- kernel: projection GEMM via bf16-split tensor cores ----------------
__global__ void __launch_bounds__(512, 1) gemm_proj_kernel(const float* __restrict__ bfu)
{
    extern __shared__ char smem[];
    char* As_hi = smem;
    char* As_lo = smem + 32768;
    char* Bs_hi = smem + 65536;
    char* Bs_lo = smem + 98304;

    int m0 = blockIdx.x * 128;
    int tid = threadIdx.x;
    int cg = tid & 15, rb = tid >> 4;

    #pragma unroll
    for (int i = 0; i < 4; i++) {
        int r = rb + i * 32;
        const float* src = &g_x[(size_t)(m0 + r) * EDIM + cg * 8];
        float4 f0 = *(const float4*)src;
        float4 f1 = *(const float4*)(src + 4);
        float fs[8] = {f0.x,f0.y,f0.z,f0.w,f1.x,f1.y,f1.z,f1.w};
        uint4 hi, lo;
        split8(fs, hi, lo);
        int off = SWOFF(r, cg);
        *(uint4*)(As_hi + off) = hi;
        *(uint4*)(As_lo + off) = lo;
    }

    int w = tid >> 5, l = tid & 31;
    int mw = (w & 3) * 32, nw = (w >> 2) * 32;
    int g = l >> 2, c4 = (l & 3) * 4;
    const float qscale = 0.17677669529663687f;

    for (int nt = 0; nt < 4; nt++) {
        __syncthreads();
        #pragma unroll
        for (int i = 0; i < 4; i++) {
            int r = rb + i * 32;
            int off = SWOFF(r, cg);
            size_t gi = (size_t)(nt * 128 + r) * 128 + cg * 8;
            *(uint4*)(Bs_hi + off) = *(const uint4*)(g_Wt_hi + gi);
            *(uint4*)(Bs_lo + off) = *(const uint4*)(g_Wt_lo + gi);
        }
        __syncthreads();

        float acc[2][4][4];
        #pragma unroll
        for (int mt = 0; mt < 2; mt++)
            #pragma unroll
            for (int n4 = 0; n4 < 4; n4++)
                #pragma unroll
                for (int j = 0; j < 4; j++) acc[mt][n4][j] = 0.0f;

        #pragma unroll
        for (int ks = 0; ks < 8; ks++) {
            uint32_t ah[2][4], al[2][4], bh[4][2], bl[4][2];
            #pragma unroll
            for (int mt = 0; mt < 2; mt++) {
                int r0 = mw + mt * 16 + g, r1 = r0 + 8;
                int ga = ks * 2, gb = ks * 2 + 1;
                int o0 = SWOFF(r0, ga) + c4, o1 = SWOFF(r1, ga) + c4;
                int o2 = SWOFF(r0, gb) + c4, o3 = SWOFF(r1, gb) + c4;
                ah[mt][0] = *(uint32_t*)(As_hi + o0); ah[mt][1] = *(uint32_t*)(As_hi + o1);
                ah[mt][2] = *(uint32_t*)(As_hi + o2); ah[mt][3] = *(uint32_t*)(As_hi + o3);
                al[mt][0] = *(uint32_t*)(As_lo + o0); al[mt][1] = *(uint32_t*)(As_lo + o1);
                al[mt][2] = *(uint32_t*)(As_lo + o2); al[mt][3] = *(uint32_t*)(As_lo + o3);
            }
            #pragma unroll
            for (int n4 = 0; n4 < 4; n4++) {
                int n = nw + n4 * 8 + g;
                int o0 = SWOFF(n, ks * 2) + c4, o1 = SWOFF(n, ks * 2 + 1) + c4;
                bh[n4][0] = *(uint32_t*)(Bs_hi + o0); bh[n4][1] = *(uint32_t*)(Bs_hi + o1);
                bl[n4][0] = *(uint32_t*)(Bs_lo + o0); bl[n4][1] = *(uint32_t*)(Bs_lo + o1);
            }
            #pragma unroll
            for (int mt = 0; mt < 2; mt++)
                #pragma unroll
                for (int n4 = 0; n4 < 4; n4++) {
                    MMA_BF16(acc[mt][n4], ah[mt], bh[n4]);
                    MMA_BF16(acc[mt][n4], ah[mt], bl[n4]);
                    MMA_BF16(acc[mt][n4], al[mt], bh[n4]);
                }
        }

        float* dst = (nt == 0) ? g_q : (nt == 1) ? g_k : (nt == 2) ? g_v : g_fu;
        #pragma unroll
        for (int mt = 0; mt < 2; mt++)
            #pragma unroll
            for (int n4 = 0; n4 < 4; n4++) {
                int m = m0 + mw + mt * 16 + g;
                int ncol = nw + n4 * 8 + (l & 3) * 2;
                float v0 = acc[mt][n4][0], v1 = acc[mt][n4][1];
                float v2 = acc[mt][n4][2], v3 = acc[mt][n4][3];
                if (nt == 0) { v0 *= qscale; v1 *= qscale; v2 *= qscale; v3 *= qscale; }
                if (nt == 3) {
                    float bf0 = bfu[ncol], bf1 = bfu[ncol + 1];
                    v0 = 1.0f / (1.0f + __expf(-(v0 + bf0)));
                    v1 = 1.0f / (1.0f + __expf(-(v1 + bf1)));
                    v2 = 1.0f / (1.0f + __expf(-(v2 + bf0)));
                    v3 = 1.0f / (1.0f + __expf(-(v3 + bf1)));
                }
                *(float2*)&dst[(size_t)m * EDIM + ncol]       = make_float2(v0, v1);
                *(float2*)&dst[(size_t)(m + 8) * EDIM + ncol] = make_float2(v2, v3);
            }
    }
}

// ---------------- kernel: output GEMM via bf16-split tensor cores ----------------
__global__ void __launch_bounds__(512, 1) gemm_out_kernel(
    const float* __restrict__ bo, float* __restrict__ out)
{
    extern __shared__ char smem[];
    char* As_hi = smem;
    char* As_lo = smem + 32768;
    char* Bs_hi = smem + 65536;
    char* Bs_lo = smem + 98304;

    int m0 = blockIdx.x * 128;
    int tid = threadIdx.x;
    int cg = tid & 15, rb = tid >> 4;

    #pragma unroll
    for (int i = 0; i < 4; i++) {
        int r = rb + i * 32;
        const float* src = &g_ao[(size_t)(m0 + r) * EDIM + cg * 8];
        float4 f0 = *(const float4*)src;
        float4 f1 = *(const float4*)(src + 4);
        float fs[8] = {f0.x,f0.y,f0.z,f0.w,f1.x,f1.y,f1.z,f1.w};
        uint4 hi, lo;
        split8(fs, hi, lo);
        int off = SWOFF(r, cg);
        *(uint4*)(As_hi + off) = hi;
        *(uint4*)(As_lo + off) = lo;

        size_t gi = (size_t)r * 128 + cg * 8;
        *(uint4*)(Bs_hi + off) = *(const uint4*)(g_Wot_hi + gi);
        *(uint4*)(Bs_lo + off) = *(const uint4*)(g_Wot_lo + gi);
    }
    __syncthreads();

    int w = tid >> 5, l = tid & 31;
    int mw = (w & 3) * 32, nw = (w >> 2) * 32;
    int g = l >> 2, c4 = (l & 3) * 4;

    float acc[2][4][4];
    #pragma unroll
    for (int mt = 0; mt < 2; mt++)
        #pragma unroll
        for (int n4 = 0; n4 < 4; n4++)
            #pragma unroll
            for (int j = 0; j < 4; j++) acc[mt][n4][j] = 0.0f;

    #pragma unroll
    for (int ks = 0; ks < 8; ks++) {
        uint32_t ah[2][4], al[2][4], bh[4][2], bl[4][2];
        #pragma unroll
        for (int mt = 0; mt < 2; mt++) {
            int r0 = mw + mt * 16 + g, r1 = r0 + 8;
            int ga = ks * 2, gb = ks * 2 + 1;
            int o0 = SWOFF(r0, ga) + c4, o1 = SWOFF(r1, ga) + c4;
            int o2 = SWOFF(r0, gb) + c4, o3 = SWOFF(r1, gb) + c4;
            ah[mt][0] = *(uint32_t*)(As_hi + o0); ah[mt][1] = *(uint32_t*)(As_hi + o1);
            ah[mt][2] = *(uint32_t*)(As_hi + o2); ah[mt][3] = *(uint32_t*)(As_hi + o3);
            al[mt][0] = *(uint32_t*)(As_lo + o0); al[mt][1] = *(uint32_t*)(As_lo + o1);
            al[mt][2] = *(uint32_t*)(As_lo + o2); al[mt][3] = *(uint32_t*)(As_lo + o3);
        }
        #pragma unroll
        for (int n4 = 0; n4 < 4; n4++) {
            int n = nw + n4 * 8 + g;
            int o0 = SWOFF(n, ks * 2) + c4, o1 = SWOFF(n, ks * 2 + 1) + c4;
            bh[n4][0] = *(uint32_t*)(Bs_hi + o0); bh[n4][1] = *(uint32_t*)(Bs_hi + o1);
            bl[n4][0] = *(uint32_t*)(Bs_lo + o0); bl[n4][1] = *(uint32_t*)(Bs_lo + o1);
        }
        #pragma unroll
        for (int mt = 0; mt < 2; mt++)
            #pragma unroll
            for (int n4 = 0; n4 < 4; n4++) {
                MMA_BF16(acc[mt][n4], ah[mt], bh[n4]);
                MMA_BF16(acc[mt][n4], ah[mt], bl[n4]);
                MMA_BF16(acc[mt][n4], al[mt], bh[n4]);
            }
    }

    #pragma unroll
    for (int mt = 0; mt < 2; mt++)
        #pragma unroll
        for (int n4 = 0; n4 < 4; n4++) {
            int m = m0 + mw + mt * 16 + g;
            int ncol = nw + n4 * 8 + (l & 3) * 2;
            float b0 = bo[ncol], b1 = bo[ncol + 1];
            *(float2*)&out[(size_t)m * EDIM + ncol] =
                make_float2(acc[mt][n4][0] + b0, acc[mt][n4][1] + b1);
            *(float2*)&out[(size_t)(m + 8) * EDIM + ncol] =
                make_float2(acc[mt][n4][2] + b0, acc[mt][n4][3] + b1);
        }
}

// ---------------- kernel: tensor-core attention, P-in-registers AV ----------------
// smem: K/Q hi/lo [256][32] (64B pitch, granule^(r&3)), Vt hi/lo [32][256]
// (512B pitch, granule^(c&7)), OB partial-out [4 wn][64][34] fp32 (padded),
// rmax/rsum [64][4]. ~132 KB.
__global__ void __launch_bounds__(512, 1) attn_kernel()
{
    extern __shared__ char sm[];
    char* KH  = sm;
    char* KL  = sm + 16384;
    char* QH  = sm + 32768;
    char* QL  = sm + 49152;
    char* VTH = sm + 65536;
    char* VTL = sm + 81920;
    float* OB   = (float*)(sm + 98304);    // [4][64][34] = 34816 B
    float* rmax = (float*)(sm + 133120);   // [64][4]
    float* rsum = (float*)(sm + 134144);   // [64][4]

    int s = blockIdx.x >> 2;
    int h = blockIdx.x & 3;
    int tid = threadIdx.x;
    size_t base = (size_t)s * 256 * EDIM + h * CD;

    // prep K/Q: bf16 hi/lo split, [r][32] 64B pitch, granule swizzle gr^(r&3)
    {
        int r = tid & 255;
        const float* src = ((tid < 256) ? g_k : g_q) + base + (size_t)r * EDIM;
        char* DH = (tid < 256) ? KH : QH;
        char* DL = (tid < 256) ? KL : QL;
        #pragma unroll
        for (int w16 = 0; w16 < 16; w16++) {
            float2 f = *(const float2*)(src + w16 * 2);
            __nv_bfloat162 hi2 = __floats2bfloat162_rn(f.x, f.y);
            float rx = f.x - __bfloat162float(__low2bfloat16(hi2));
            float ry = f.y - __bfloat162float(__high2bfloat16(hi2));
            __nv_bfloat162 lo2 = __floats2bfloat162_rn(rx, ry);
            int gr = w16 >> 2;
            int off = r * 64 + ((gr ^ (r & 3)) << 4) + (w16 & 3) * 4;
            *(uint32_t*)(DH + off) = *(uint32_t*)&hi2;
            *(uint32_t*)(DL + off) = *(uint32_t*)&lo2;
        }
    }
    // prep Vt: [c][v] bf16 hi/lo, 512B pitch, granule swizzle gr^(c&7)
    {
        int r = tid & 255, half = tid >> 8;
        const float* src = g_v + base + (size_t)r * EDIM + half * 16;
        #pragma unroll
        for (int j4 = 0; j4 < 4; j4++) {
            float4 f = *(const float4*)(src + j4 * 4);
            float vals[4] = {f.x, f.y, f.z, f.w};
            #pragma unroll
            for (int jj = 0; jj < 4; jj++) {
                int c = half * 16 + j4 * 4 + jj;
                float v = vals[jj];
                __nv_bfloat16 hb = __float2bfloat16_rn(v);
                __nv_bfloat16 lb = __float2bfloat16_rn(v - __bfloat162float(hb));
                int off = c * 512 + (((r >> 3) ^ (c & 7)) << 4) + ((r >> 1) & 3) * 4 + (r & 1) * 2;
                *(__nv_bfloat16*)(VTH + off) = hb;
                *(__nv_bfloat16*)(VTL + off) = lb;
            }
        }
    }
    __syncthreads();

    uint32_t kh_s  = (uint32_t)__cvta_generic_to_shared(KH);
    uint32_t kl_s  = (uint32_t)__cvta_generic_to_shared(KL);
    uint32_t qh_s  = (uint32_t)__cvta_generic_to_shared(QH);
    uint32_t ql_s  = (uint32_t)__cvta_generic_to_shared(QL);
    uint32_t vth_s = (uint32_t)__cvta_generic_to_shared(VTH);
    uint32_t vtl_s = (uint32_t)__cvta_generic_to_shared(VTL);

    int w = tid >> 5, l = tid & 31;
    int g = l >> 2, l3 = l & 3;
    int mi = l >> 3, rr = l & 7;
    int wm = w >> 2, wn = w & 3;
    const float* mb = g_mb + (size_t)h * RROWS;

    for (int c0 = 0; c0 < 256; c0 += 64) {
        // ---- scores: 16x64 warp tile over 64x256, k=32, 3-term split ----
        float acc[8][4];
        #pragma unroll
        for (int nf = 0; nf < 8; nf++)
            #pragma unroll
            for (int j = 0; j < 4; j++) acc[nf][j] = 0.0f;

        int r0 = c0 + wm * 16 + g, r1 = r0 + 8;
        int RA = c0 + wm * 16 + (mi & 1) * 8 + rr;

        #pragma unroll
        for (int ks = 0; ks < 2; ks++) {
            uint32_t ah[4], al[4];
            {
                int gA = ks * 2 + (mi >> 1);
                uint32_t offA = RA * 64 + ((gA ^ (RA & 3)) << 4);
                LDSM_X4(ah[0], ah[1], ah[2], ah[3], kh_s + offA);
                LDSM_X4(al[0], al[1], al[2], al[3], kl_s + offA);
            }
            #pragma unroll
            for (int np = 0; np < 4; np++) {
                int nB = wn * 64 + np * 16 + (mi >> 1) * 8 + rr;
                int gB = ks * 2 + (mi & 1);
                uint32_t offB = nB * 64 + ((gB ^ (nB & 3)) << 4);
                uint32_t b0h, b1h, b2h, b3h, b0l, b1l, b2l, b3l;
                LDSM_X4(b0h, b1h, b2h, b3h, qh_s + offB);
                LDSM_X4(b0l, b1l, b2l, b3l, ql_s + offB);
                uint32_t bhA[2] = {b0h, b1h}, bhB[2] = {b2h, b3h};
                uint32_t blA[2] = {b0l, b1l}, blB[2] = {b2l, b3l};
                MMA_BF16(acc[np * 2],     ah, bhA);
                MMA_BF16(acc[np * 2],     ah, blA);
                MMA_BF16(acc[np * 2],     al, bhA);
                MMA_BF16(acc[np * 2 + 1], ah, bhB);
                MMA_BF16(acc[np * 2 + 1], ah, blB);
                MMA_BF16(acc[np * 2 + 1], al, bhB);
            }
        }

        // ---- add mask+bias ----
        #pragma unroll
        for (int nf = 0; nf < 8; nf++) {
            int vi = wn * 64 + nf * 8 + l3 * 2;
            float2 m0 = __ldg((const float2*)&mb[(size_t)r0 * 256 + vi]);
            float2 m1 = __ldg((const float2*)&mb[(size_t)r1 * 256 + vi]);
            acc[nf][0] += m0.x; acc[nf][1] += m0.y;
            acc[nf][2] += m1.x; acc[nf][3] += m1.y;
        }

        // ---- global row max (one cross-warp sync) ----
        int lrA = wm * 16 + g, lrB = lrA + 8;
        float mA = -1e30f, mB = -1e30f;
        #pragma unroll
        for (int nf = 0; nf < 8; nf++) {
            mA = fmaxf(mA, fmaxf(acc[nf][0], acc[nf][1]));
            mB = fmaxf(mB, fmaxf(acc[nf][2], acc[nf][3]));
        }
        mA = fmaxf(mA, __shfl_xor_sync(0xffffffffu, mA, 1));
        mA = fmaxf(mA, __shfl_xor_sync(0xffffffffu, mA, 2));
        mB = fmaxf(mB, __shfl_xor_sync(0xffffffffu, mB, 1));
        mB = fmaxf(mB, __shfl_xor_sync(0xffffffffu, mB, 2));
        if (l3 == 0) { rmax[lrA * 4 + wn] = mA; rmax[lrB * 4 + wn] = mB; }
        __syncthreads();
        mA = fmaxf(fmaxf(rmax[lrA*4+0], rmax[lrA*4+1]), fmaxf(rmax[lrA*4+2], rmax[lrA*4+3]));
        mB = fmaxf(fmaxf(rmax[lrB*4+0], rmax[lrB*4+1]), fmaxf(rmax[lrB*4+2], rmax[lrB*4+3]));

        // ---- exp (unnormalized); per-warp partial row sums to rsum ----
        float sA = 0.0f, sB = 0.0f;
        #pragma unroll
        for (int nf = 0; nf < 8; nf++) {
            acc[nf][0] = __expf(acc[nf][0] - mA); sA += acc[nf][0];
            acc[nf][1] = __expf(acc[nf][1] - mA); sA += acc[nf][1];
            acc[nf][2] = __expf(acc[nf][2] - mB); sB += acc[nf][2];
            acc[nf][3] = __expf(acc[nf][3] - mB); sB += acc[nf][3];
        }
        sA += __shfl_xor_sync(0xffffffffu, sA, 1);
        sA += __shfl_xor_sync(0xffffffffu, sA, 2);
        sB += __shfl_xor_sync(0xffffffffu, sB, 1);
        sB += __shfl_xor_sync(0xffffffffu, sB, 2);
        if (l3 == 0) { rsum[lrA * 4 + wn] = sA; rsum[lrB * 4 + wn] = sB; }

        // ---- AV over this warp's own 64-key range; P stays in registers ----
        float o[4][4];
        #pragma unroll
        for (int nt = 0; nt < 4; nt++)
            #pragma unroll
            for (int j = 0; j < 4; j++) o[nt][j] = 0.0f;

        #pragma unroll
        for (int ks = 0; ks < 4; ks++) {
            // pack P A-frags (C-frag layout == A-frag layout)
            uint32_t ph[4], pl[4];
            ph[0] = pack_bf2(acc[2*ks][0],   acc[2*ks][1]);
            ph[1] = pack_bf2(acc[2*ks][2],   acc[2*ks][3]);
            ph[2] = pack_bf2(acc[2*ks+1][0], acc[2*ks+1][1]);
            ph[3] = pack_bf2(acc[2*ks+1][2], acc[2*ks+1][3]);
            pl[0] = pack_bf2_res(acc[2*ks][0],   acc[2*ks][1],   ph[0]);
            pl[1] = pack_bf2_res(acc[2*ks][2],   acc[2*ks][3],   ph[1]);
            pl[2] = pack_bf2_res(acc[2*ks+1][0], acc[2*ks+1][1], ph[2]);
            pl[3] = pack_bf2_res(acc[2*ks+1][2], acc[2*ks+1][3], ph[3]);

            // V B-frags: nt pair {0,1} and {2,3}, k granules wn*8+ks*2 {+0,+1}
            uint32_t bh[4][2], bl[4][2];
            #pragma unroll
            for (int c01 = 0; c01 < 2; c01++) {
                int row = c01 * 16 + (mi & 1) * 8 + rr;
                int gv = wn * 8 + ks * 2 + (mi >> 1);
                uint32_t offV = row * 512 + ((gv ^ (row & 7)) << 4);
                uint32_t d0, d1, d2, d3;
                LDSM_X4(d0, d1, d2, d3, vth_s + offV);
                bh[c01*2+0][0] = d0; bh[c01*2+0][1] = d2;
                bh[c01*2+1][0] = d1; bh[c01*2+1][1] = d3;
                LDSM_X4(d0, d1, d2, d3, vtl_s + offV);
                bl[c01*2+0][0] = d0; bl[c01*2+0][1] = d2;
                bl[c01*2+1][0] = d1; bl[c01*2+1][1] = d3;
            }
            #pragma unroll
            for (int nt = 0; nt < 4; nt++) {
                MMA_BF16(o[nt], ph, bh[nt]);
                MMA_BF16(o[nt], ph, bl[nt]);
                MMA_BF16(o[nt], pl, bh[nt]);
            }
        }

        // ---- write partial out to OB[wn] ----
        {
            float* obw = OB + wn * 2176;   // 64*34
            #pragma unroll
            for (int nt = 0; nt < 4; nt++) {
                *(float2*)&obw[lrA * 34 + nt * 8 + l3 * 2] = make_float2(o[nt][0], o[nt][1]);
                *(float2*)&obw[lrB * 34 + nt * 8 + l3 * 2] = make_float2(o[nt][2], o[nt][3]);
            }
        }
        __syncthreads();

        // ---- reduce 4 partials, normalize, gate with fu, store ----
        {
            float invA = 1.0f / (rsum[lrA*4+0] + rsum[lrA*4+1] + rsum[lrA*4+2] + rsum[lrA*4+3]);
            float invB = 1.0f / (rsum[lrB*4+0] + rsum[lrB*4+1] + rsum[lrB*4+2] + rsum[lrB*4+3]);
            int cc = wn * 8 + l3 * 2;
            float2 vA = make_float2(0.0f, 0.0f), vB = make_float2(0.0f, 0.0f);
            #pragma unroll
            for (int j = 0; j < 4; j++) {
                float2 pA = *(float2*)&OB[j * 2176 + lrA * 34 + cc];
                float2 pB = *(float2*)&OB[j * 2176 + lrB * 34 + cc];
                vA.x += pA.x; vA.y += pA.y;
                vB.x += pB.x; vB.y += pB.y;
            }
            size_t iA = base + (size_t)r0 * EDIM + cc;
            size_t iB = base + (size_t)r1 * EDIM + cc;
            float2 fA = *(const float2*)&g_fu[iA];
            float2 fB = *(const float2*)&g_fu[iB];
            *(float2*)&g_ao[iA] = make_float2(vA.x * invA * fA.x, vA.y * invA * fA.y);
            *(float2*)&g_ao[iB] = make_float2(vB.x * invB * fB.x, vB.y * invB * fB.y);
        }
        __syncthreads();
    }
}

// ---------------- host launch ----------------
extern "C" void kernel_launch(void* const* d_in, const int* in_sizes, int n_in,
                              void* d_out, int out_size)
{
    const float* pair_rep = (const float*)d_in[0];
    const float* mask     = (const float*)d_in[1];
    const float* gamma    = (const float*)d_in[2];
    const float* beta     = (const float*)d_in[3];
    const float* Wq       = (const float*)d_in[4];
    const float* Wk       = (const float*)d_in[5];
    const float* Wv       = (const float*)d_in[6];
    const float* Wb       = (const float*)d_in[7];
    const float* Wfu      = (const float*)d_in[8];
    const float* bfu      = (const float*)d_in[9];
    const float* Wo       = (const float*)d_in[10];
    const float* bo       = (const float*)d_in[11];
    float* out = (float*)d_out;

    const int GEMM_SMEM = 128 * 1024;
    const int ATTN_SMEM = 135168;   // 132 KB
    cudaFuncSetAttribute(gemm_proj_kernel, cudaFuncAttributeMaxDynamicSharedMemorySize, GEMM_SMEM);
    cudaFuncSetAttribute(gemm_out_kernel,  cudaFuncAttributeMaxDynamicSharedMemorySize, GEMM_SMEM);
    cudaFuncSetAttribute(attn_kernel,      cudaFuncAttributeMaxDynamicSharedMemorySize, ATTN_SMEM);

    pack_w_kernel<<<(512 * 128 + 128 * 128) / 256, 256>>>(Wq, Wk, Wv, Wfu, Wo);
    ln_kernel<<<RROWS, 128>>>(pair_rep, mask, gamma, beta, Wb);
    gemm_proj_kernel<<<RROWS / 128, 512, GEMM_SMEM>>>(bfu);
    attn_kernel<<<LSEQ * NH, 512, ATTN_SMEM>>>();
    gemm_out_kernel<<<RROWS / 128, 512, GEMM_SMEM>>>(bo, out);
}

// round 14
// speedup vs baseline: 2.2206x; 1.1104x over previous
#include <cuda_runtime.h>
#include <cuda_bf16.h>
#include <stdint.h>
#include <math.h>

#define LSEQ 256
#define EDIM 128
#define NH 4
#define CD 32
#define RROWS (LSEQ*LSEQ)   // 65536

// ---------------- scratch (device globals; no allocs allowed) ----------------
__device__ float g_x [RROWS*EDIM];
__device__ float g_q [RROWS*EDIM];   // pre-scaled by C^-0.5  (the "v-indexed" operand)
__device__ float g_k [RROWS*EDIM];   // the "q-indexed" operand
__device__ float g_v [RROWS*EDIM];
__device__ float g_fu[RROWS*EDIM];   // sigmoid(x@Wfu + bfu)
__device__ float g_mb[NH*RROWS];     // mb[h][q*256+v] = mask[q,v] + bias[q,v,h]
__device__ float g_ao[RROWS*EDIM];   // gated attention output
// packed+transposed+bf16-split weights: [n][k] layout (col-major B for mma)
__device__ __nv_bfloat16 g_Wt_hi [512*128];
__device__ __nv_bfloat16 g_Wt_lo [512*128];
__device__ __nv_bfloat16 g_Wot_hi[128*128];
__device__ __nv_bfloat16 g_Wot_lo[128*128];

// ---------------- mma / ldmatrix helpers ----------------
#define MMA_BF16(d, a, b) \
    asm volatile("mma.sync.aligned.m16n8k16.row.col.f32.bf16.bf16.f32 " \
        "{%0,%1,%2,%3}, {%4,%5,%6,%7}, {%8,%9}, {%0,%1,%2,%3};" \
        : "+f"(d[0]), "+f"(d[1]), "+f"(d[2]), "+f"(d[3]) \
        : "r"(a[0]), "r"(a[1]), "r"(a[2]), "r"(a[3]), "r"(b[0]), "r"(b[1]))

#define LDSM_X4(d0, d1, d2, d3, a) \
    asm volatile("ldmatrix.sync.aligned.m8n8.x4.shared.b16 {%0,%1,%2,%3}, [%4];" \
        : "=r"(d0), "=r"(d1), "=r"(d2), "=r"(d3) : "r"(a))

#define LDSM_X4_T(d0, d1, d2, d3, a) \
    asm volatile("ldmatrix.sync.aligned.m8n8.x4.trans.shared.b16 {%0,%1,%2,%3}, [%4];" \
        : "=r"(d0), "=r"(d1), "=r"(d2), "=r"(d3) : "r"(a))

__device__ __forceinline__ uint32_t pack_bf2(float a, float b)
{
    __nv_bfloat162 t = __floats2bfloat162_rn(a, b);
    return *(uint32_t*)&t;
}
__device__ __forceinline__ uint32_t pack_bf2_res(float a, float b, uint32_t hi)
{
    __nv_bfloat162 h = *(__nv_bfloat162*)&hi;
    __nv_bfloat162 t = __floats2bfloat162_rn(
        a - __bfloat162float(__low2bfloat16(h)),
        b - __bfloat162float(__high2bfloat16(h)));
    return *(uint32_t*)&t;
}

// ---------------- kernel: pack + transpose + bf16-split weights ----------------
__global__ void pack_w_kernel(const float* __restrict__ Wq, const float* __restrict__ Wk,
                              const float* __restrict__ Wv, const float* __restrict__ Wfu,
                              const float* __restrict__ Wo)
{
    int idx = blockIdx.x * blockDim.x + threadIdx.x;
    if (idx < 512 * 128) {
        int n = idx >> 7, k = idx & 127;
        const float* src = (n < 128) ? Wq : (n < 256) ? Wk : (n < 384) ? Wv : Wfu;
        float v = src[k * 128 + (n & 127)];
        __nv_bfloat16 h = __float2bfloat16_rn(v);
        g_Wt_hi[idx] = h;
        g_Wt_lo[idx] = __float2bfloat16_rn(v - __bfloat162float(h));
    } else {
        int j = idx - 512 * 128;
        int n = j >> 7, k = j & 127;
        float v = Wo[k * 128 + n];
        __nv_bfloat16 h = __float2bfloat16_rn(v);
        g_Wot_hi[j] = h;
        g_Wot_lo[j] = __float2bfloat16_rn(v - __bfloat162float(h));
    }
}

// ---------------- kernel: layernorm + pair_bias(+mask) ----------------
__global__ void __launch_bounds__(128) ln_kernel(
    const float* __restrict__ pr, const float* __restrict__ mask,
    const float* __restrict__ gamma, const float* __restrict__ beta,
    const float* __restrict__ Wb)
{
    int r = blockIdx.x;
    int t = threadIdx.x;
    float v = pr[(size_t)r * EDIM + t];

    float s = v, s2 = v * v;
    #pragma unroll
    for (int o = 16; o; o >>= 1) {
        s  += __shfl_xor_sync(0xffffffffu, s,  o);
        s2 += __shfl_xor_sync(0xffffffffu, s2, o);
    }
    __shared__ float sh[8];
    int w = t >> 5, lane = t & 31;
    if (lane == 0) { sh[w] = s; sh[4 + w] = s2; }
    __syncthreads();
    s  = sh[0] + sh[1] + sh[2] + sh[3];
    s2 = sh[4] + sh[5] + sh[6] + sh[7];
    float mu  = s * (1.0f / EDIM);
    float var = s2 * (1.0f / EDIM) - mu * mu;
    float x = (v - mu) * rsqrtf(var + 1e-5f) * gamma[t] + beta[t];
    g_x[(size_t)r * EDIM + t] = x;

    float b0 = x * Wb[t * 4 + 0];
    float b1 = x * Wb[t * 4 + 1];
    float b2 = x * Wb[t * 4 + 2];
    float b3 = x * Wb[t * 4 + 3];
    #pragma unroll
    for (int o = 16; o; o >>= 1) {
        b0 += __shfl_xor_sync(0xffffffffu, b0, o);
        b1 += __shfl_xor_sync(0xffffffffu, b1, o);
        b2 += __shfl_xor_sync(0xffffffffu, b2, o);
        b3 += __shfl_xor_sync(0xffffffffu, b3, o);
    }
    __shared__ float shb[16];
    if (lane == 0) { shb[w*4+0]=b0; shb[w*4+1]=b1; shb[w*4+2]=b2; shb[w*4+3]=b3; }
    __syncthreads();
    if (t < 4) {
        float b = shb[t] + shb[4 + t] + shb[8 + t] + shb[12 + t];
        g_mb[t * RROWS + r] = mask[r] + b;
    }
}

// ---------------- conversion helper: 8 floats -> hi/lo bf16 granules ----------------
__device__ __forceinline__ void split8(const float* fs, uint4& hi, uint4& lo)
{
    uint32_t h[4], l[4];
    #pragma unroll
    for (int j = 0; j < 4; j++) {
        __nv_bfloat162 h2 = __floats2bfloat162_rn(fs[2*j], fs[2*j+1]);
        float r0 = fs[2*j]   - __bfloat162float(__low2bfloat16(h2));
        float r1 = fs[2*j+1] - __bfloat162float(__high2bfloat16(h2));
        __nv_bfloat162 l2 = __floats2bfloat162_rn(r0, r1);
        h[j] = *(uint32_t*)&h2;
        l[j] = *(uint32_t*)&l2;
    }
    hi = make_uint4(h[0], h[1], h[2], h[3]);
    lo = make_uint4(l[0], l[1], l[2], l[3]);
}

// swizzled byte offset for row r (256B pitch), 16B granule c
#define SWOFF(r, c) ((r) * 256 + ((((c) ^ ((r) & 7))) << 4))

// ---------------- kernel: projection GEMM via bf16-split tensor cores ----------------
__global__ void __launch_bounds__(512, 1) gemm_proj_kernel(const float* __restrict__ bfu)
{
    extern __shared__ char smem[];
    char* As_hi = smem;
    char* As_lo = smem + 32768;
    char* Bs_hi = smem + 65536;
    char* Bs_lo = smem + 98304;

    int m0 = blockIdx.x * 128;
    int tid = threadIdx.x;
    int cg = tid & 15, rb = tid >> 4;

    #pragma unroll
    for (int i = 0; i < 4; i++) {
        int r = rb + i * 32;
        const float* src = &g_x[(size_t)(m0 + r) * EDIM + cg * 8];
        float4 f0 = *(const float4*)src;
        float4 f1 = *(const float4*)(src + 4);
        float fs[8] = {f0.x,f0.y,f0.z,f0.w,f1.x,f1.y,f1.z,f1.w};
        uint4 hi, lo;
        split8(fs, hi, lo);
        int off = SWOFF(r, cg);
        *(uint4*)(As_hi + off) = hi;
        *(uint4*)(As_lo + off) = lo;
    }

    int w = tid >> 5, l = tid & 31;
    int mw = (w & 3) * 32, nw = (w >> 2) * 32;
    int g = l >> 2, c4 = (l & 3) * 4;
    const float qscale = 0.17677669529663687f;

    for (int nt = 0; nt < 4; nt++) {
        __syncthreads();
        #pragma unroll
        for (int i = 0; i < 4; i++) {
            int r = rb + i * 32;
            int off = SWOFF(r, cg);
            size_t gi = (size_t)(nt * 128 + r) * 128 + cg * 8;
            *(uint4*)(Bs_hi + off) = *(const uint4*)(g_Wt_hi + gi);
            *(uint4*)(Bs_lo + off) = *(const uint4*)(g_Wt_lo + gi);
        }
        __syncthreads();

        float acc[2][4][4];
        #pragma unroll
        for (int mt = 0; mt < 2; mt++)
            #pragma unroll
            for (int n4 = 0; n4 < 4; n4++)
                #pragma unroll
                for (int j = 0; j < 4; j++) acc[mt][n4][j] = 0.0f;

        #pragma unroll
        for (int ks = 0; ks < 8; ks++) {
            uint32_t ah[2][4], al[2][4], bh[4][2], bl[4][2];
            #pragma unroll
            for (int mt = 0; mt < 2; mt++) {
                int r0 = mw + mt * 16 + g, r1 = r0 + 8;
                int ga = ks * 2, gb = ks * 2 + 1;
                int o0 = SWOFF(r0, ga) + c4, o1 = SWOFF(r1, ga) + c4;
                int o2 = SWOFF(r0, gb) + c4, o3 = SWOFF(r1, gb) + c4;
                ah[mt][0] = *(uint32_t*)(As_hi + o0); ah[mt][1] = *(uint32_t*)(As_hi + o1);
                ah[mt][2] = *(uint32_t*)(As_hi + o2); ah[mt][3] = *(uint32_t*)(As_hi + o3);
                al[mt][0] = *(uint32_t*)(As_lo + o0); al[mt][1] = *(uint32_t*)(As_lo + o1);
                al[mt][2] = *(uint32_t*)(As_lo + o2); al[mt][3] = *(uint32_t*)(As_lo + o3);
            }
            #pragma unroll
            for (int n4 = 0; n4 < 4; n4++) {
                int n = nw + n4 * 8 + g;
                int o0 = SWOFF(n, ks * 2) + c4, o1 = SWOFF(n, ks * 2 + 1) + c4;
                bh[n4][0] = *(uint32_t*)(Bs_hi + o0); bh[n4][1] = *(uint32_t*)(Bs_hi + o1);
                bl[n4][0] = *(uint32_t*)(Bs_lo + o0); bl[n4][1] = *(uint32_t*)(Bs_lo + o1);
            }
            #pragma unroll
            for (int mt = 0; mt < 2; mt++)
                #pragma unroll
                for (int n4 = 0; n4 < 4; n4++) {
                    MMA_BF16(acc[mt][n4], ah[mt], bh[n4]);
                    MMA_BF16(acc[mt][n4], ah[mt], bl[n4]);
                    MMA_BF16(acc[mt][n4], al[mt], bh[n4]);
                }
        }

        float* dst = (nt == 0) ? g_q : (nt == 1) ? g_k : (nt == 2) ? g_v : g_fu;
        #pragma unroll
        for (int mt = 0; mt < 2; mt++)
            #pragma unroll
            for (int n4 = 0; n4 < 4; n4++) {
                int m = m0 + mw + mt * 16 + g;
                int ncol = nw + n4 * 8 + (l & 3) * 2;
                float v0 = acc[mt][n4][0], v1 = acc[mt][n4][1];
                float v2 = acc[mt][n4][2], v3 = acc[mt][n4][3];
                if (nt == 0) { v0 *= qscale; v1 *= qscale; v2 *= qscale; v3 *= qscale; }
                if (nt == 3) {
                    float bf0 = bfu[ncol], bf1 = bfu[ncol + 1];
                    v0 = 1.0f / (1.0f + __expf(-(v0 + bf0)));
                    v1 = 1.0f / (1.0f + __expf(-(v1 + bf1)));
                    v2 = 1.0f / (1.0f + __expf(-(v2 + bf0)));
                    v3 = 1.0f / (1.0f + __expf(-(v3 + bf1)));
                }
                *(float2*)&dst[(size_t)m * EDIM + ncol]       = make_float2(v0, v1);
                *(float2*)&dst[(size_t)(m + 8) * EDIM + ncol] = make_float2(v2, v3);
            }
    }
}

// ---------------- kernel: output GEMM via bf16-split tensor cores ----------------
__global__ void __launch_bounds__(512, 1) gemm_out_kernel(
    const float* __restrict__ bo, float* __restrict__ out)
{
    extern __shared__ char smem[];
    char* As_hi = smem;
    char* As_lo = smem + 32768;
    char* Bs_hi = smem + 65536;
    char* Bs_lo = smem + 98304;

    int m0 = blockIdx.x * 128;
    int tid = threadIdx.x;
    int cg = tid & 15, rb = tid >> 4;

    #pragma unroll
    for (int i = 0; i < 4; i++) {
        int r = rb + i * 32;
        const float* src = &g_ao[(size_t)(m0 + r) * EDIM + cg * 8];
        float4 f0 = *(const float4*)src;
        float4 f1 = *(const float4*)(src + 4);
        float fs[8] = {f0.x,f0.y,f0.z,f0.w,f1.x,f1.y,f1.z,f1.w};
        uint4 hi, lo;
        split8(fs, hi, lo);
        int off = SWOFF(r, cg);
        *(uint4*)(As_hi + off) = hi;
        *(uint4*)(As_lo + off) = lo;

        size_t gi = (size_t)r * 128 + cg * 8;
        *(uint4*)(Bs_hi + off) = *(const uint4*)(g_Wot_hi + gi);
        *(uint4*)(Bs_lo + off) = *(const uint4*)(g_Wot_lo + gi);
    }
    __syncthreads();

    int w = tid >> 5, l = tid & 31;
    int mw = (w & 3) * 32, nw = (w >> 2) * 32;
    int g = l >> 2, c4 = (l & 3) * 4;

    float acc[2][4][4];
    #pragma unroll
    for (int mt = 0; mt < 2; mt++)
        #pragma unroll
        for (int n4 = 0; n4 < 4; n4++)
            #pragma unroll
            for (int j = 0; j < 4; j++) acc[mt][n4][j] = 0.0f;

    #pragma unroll
    for (int ks = 0; ks < 8; ks++) {
        uint32_t ah[2][4], al[2][4], bh[4][2], bl[4][2];
        #pragma unroll
        for (int mt = 0; mt < 2; mt++) {
            int r0 = mw + mt * 16 + g, r1 = r0 + 8;
            int ga = ks * 2, gb = ks * 2 + 1;
            int o0 = SWOFF(r0, ga) + c4, o1 = SWOFF(r1, ga) + c4;
            int o2 = SWOFF(r0, gb) + c4, o3 = SWOFF(r1, gb) + c4;
            ah[mt][0] = *(uint32_t*)(As_hi + o0); ah[mt][1] = *(uint32_t*)(As_hi + o1);
            ah[mt][2] = *(uint32_t*)(As_hi + o2); ah[mt][3] = *(uint32_t*)(As_hi + o3);
            al[mt][0] = *(uint32_t*)(As_lo + o0); al[mt][1] = *(uint32_t*)(As_lo + o1);
            al[mt][2] = *(uint32_t*)(As_lo + o2); al[mt][3] = *(uint32_t*)(As_lo + o3);
        }
        #pragma unroll
        for (int n4 = 0; n4 < 4; n4++) {
            int n = nw + n4 * 8 + g;
            int o0 = SWOFF(n, ks * 2) + c4, o1 = SWOFF(n, ks * 2 + 1) + c4;
            bh[n4][0] = *(uint32_t*)(Bs_hi + o0); bh[n4][1] = *(uint32_t*)(Bs_hi + o1);
            bl[n4][0] = *(uint32_t*)(Bs_lo + o0); bl[n4][1] = *(uint32_t*)(Bs_lo + o1);
        }
        #pragma unroll
        for (int mt = 0; mt < 2; mt++)
            #pragma unroll
            for (int n4 = 0; n4 < 4; n4++) {
                MMA_BF16(acc[mt][n4], ah[mt], bh[n4]);
                MMA_BF16(acc[mt][n4], ah[mt], bl[n4]);
                MMA_BF16(acc[mt][n4], al[mt], bh[n4]);
            }
    }

    #pragma unroll
    for (int mt = 0; mt < 2; mt++)
        #pragma unroll
        for (int n4 = 0; n4 < 4; n4++) {
            int m = m0 + mw + mt * 16 + g;
            int ncol = nw + n4 * 8 + (l & 3) * 2;
            float b0 = bo[ncol], b1 = bo[ncol + 1];
            *(float2*)&out[(size_t)m * EDIM + ncol] =
                make_float2(acc[mt][n4][0] + b0, acc[mt][n4][1] + b1);
            *(float2*)&out[(size_t)(m + 8) * EDIM + ncol] =
                make_float2(acc[mt][n4][2] + b0, acc[mt][n4][3] + b1);
        }
}

// ---------------- kernel: tensor-core attention, conflict-free prep + trans-V ----------------
// smem: K/Q/V hi/lo row-major [256][32] bf16 (64B pitch, granule^(r&3)) = 96 KB,
// OB partial-out [4][64][34] fp32, rmax/rsum [64][4]. ~132 KB.
__global__ void __launch_bounds__(512, 1) attn_kernel()
{
    extern __shared__ char sm[];
    char* KH = sm;
    char* KL = sm + 16384;
    char* QH = sm + 32768;
    char* QL = sm + 49152;
    char* VH = sm + 65536;
    char* VL = sm + 81920;
    float* OB   = (float*)(sm + 98304);    // [4][64][34]
    float* rmax = (float*)(sm + 133120);   // [64][4]
    float* rsum = (float*)(sm + 134144);   // [64][4]

    int s = blockIdx.x >> 2;
    int h = blockIdx.x & 3;
    int tid = threadIdx.x;
    size_t base = (size_t)s * 256 * EDIM + h * CD;

    // prep K/Q/V: bf16 hi/lo, uint4 granule stores (conflict-free), 64B pitch.
    // slot = tid + i*512: i∈{0,1}->K, {2,3}->Q, {4,5}->V; row = (slot%1024)>>2, g = slot&3
    #pragma unroll
    for (int i = 0; i < 6; i++) {
        int slot = tid + i * 512;
        int within = slot & 1023;
        int r = within >> 2, gg = within & 3;
        const float* srcb = (i < 2) ? g_k : (i < 4) ? g_q : g_v;
        char* DH = (i < 2) ? KH : (i < 4) ? QH : VH;
        char* DL = (i < 2) ? KL : (i < 4) ? QL : VL;
        const float* src = srcb + base + (size_t)r * EDIM + gg * 8;
        float4 f0 = *(const float4*)src;
        float4 f1 = *(const float4*)(src + 4);
        float fs[8] = {f0.x,f0.y,f0.z,f0.w,f1.x,f1.y,f1.z,f1.w};
        uint4 hi, lo;
        split8(fs, hi, lo);
        int off = r * 64 + ((gg ^ (r & 3)) << 4);
        *(uint4*)(DH + off) = hi;
        *(uint4*)(DL + off) = lo;
    }
    __syncthreads();

    uint32_t kh_s = (uint32_t)__cvta_generic_to_shared(KH);
    uint32_t kl_s = (uint32_t)__cvta_generic_to_shared(KL);
    uint32_t qh_s = (uint32_t)__cvta_generic_to_shared(QH);
    uint32_t ql_s = (uint32_t)__cvta_generic_to_shared(QL);
    uint32_t vh_s = (uint32_t)__cvta_generic_to_shared(VH);
    uint32_t vl_s = (uint32_t)__cvta_generic_to_shared(VL);

    int w = tid >> 5, l = tid & 31;
    int g = l >> 2, l3 = l & 3;
    int mi = l >> 3, rr = l & 7;
    int wm = w >> 2, wn = w & 3;
    const float* mb = g_mb + (size_t)h * RROWS;

    for (int c0 = 0; c0 < 256; c0 += 64) {
        // ---- scores: 16x64 warp tile over 64x256, k=32, 3-term split ----
        float acc[8][4];
        #pragma unroll
        for (int nf = 0; nf < 8; nf++)
            #pragma unroll
            for (int j = 0; j < 4; j++) acc[nf][j] = 0.0f;

        int r0 = c0 + wm * 16 + g, r1 = r0 + 8;
        int RA = c0 + wm * 16 + (mi & 1) * 8 + rr;

        #pragma unroll
        for (int ks = 0; ks < 2; ks++) {
            uint32_t ah[4], al[4];
            {
                int gA = ks * 2 + (mi >> 1);
                uint32_t offA = RA * 64 + ((gA ^ (RA & 3)) << 4);
                LDSM_X4(ah[0], ah[1], ah[2], ah[3], kh_s + offA);
                LDSM_X4(al[0], al[1], al[2], al[3], kl_s + offA);
            }
            #pragma unroll
            for (int np = 0; np < 4; np++) {
                int nB = wn * 64 + np * 16 + (mi >> 1) * 8 + rr;
                int gB = ks * 2 + (mi & 1);
                uint32_t offB = nB * 64 + ((gB ^ (nB & 3)) << 4);
                uint32_t b0h, b1h, b2h, b3h, b0l, b1l, b2l, b3l;
                LDSM_X4(b0h, b1h, b2h, b3h, qh_s + offB);
                LDSM_X4(b0l, b1l, b2l, b3l, ql_s + offB);
                uint32_t bhA[2] = {b0h, b1h}, bhB[2] = {b2h, b3h};
                uint32_t blA[2] = {b0l, b1l}, blB[2] = {b2l, b3l};
                MMA_BF16(acc[np * 2],     ah, bhA);
                MMA_BF16(acc[np * 2],     ah, blA);
                MMA_BF16(acc[np * 2],     al, bhA);
                MMA_BF16(acc[np * 2 + 1], ah, bhB);
                MMA_BF16(acc[np * 2 + 1], ah, blB);
                MMA_BF16(acc[np * 2 + 1], al, bhB);
            }
        }

        // ---- add mask+bias ----
        #pragma unroll
        for (int nf = 0; nf < 8; nf++) {
            int vi = wn * 64 + nf * 8 + l3 * 2;
            float2 m0 = __ldg((const float2*)&mb[(size_t)r0 * 256 + vi]);
            float2 m1 = __ldg((const float2*)&mb[(size_t)r1 * 256 + vi]);
            acc[nf][0] += m0.x; acc[nf][1] += m0.y;
            acc[nf][2] += m1.x; acc[nf][3] += m1.y;
        }

        // ---- global row max (one cross-warp sync) ----
        int lrA = wm * 16 + g, lrB = lrA + 8;
        float mA = -1e30f, mB = -1e30f;
        #pragma unroll
        for (int nf = 0; nf < 8; nf++) {
            mA = fmaxf(mA, fmaxf(acc[nf][0], acc[nf][1]));
            mB = fmaxf(mB, fmaxf(acc[nf][2], acc[nf][3]));
        }
        mA = fmaxf(mA, __shfl_xor_sync(0xffffffffu, mA, 1));
        mA = fmaxf(mA, __shfl_xor_sync(0xffffffffu, mA, 2));
        mB = fmaxf(mB, __shfl_xor_sync(0xffffffffu, mB, 1));
        mB = fmaxf(mB, __shfl_xor_sync(0xffffffffu, mB, 2));
        if (l3 == 0) { rmax[lrA * 4 + wn] = mA; rmax[lrB * 4 + wn] = mB; }
        __syncthreads();
        mA = fmaxf(fmaxf(rmax[lrA*4+0], rmax[lrA*4+1]), fmaxf(rmax[lrA*4+2], rmax[lrA*4+3]));
        mB = fmaxf(fmaxf(rmax[lrB*4+0], rmax[lrB*4+1]), fmaxf(rmax[lrB*4+2], rmax[lrB*4+3]));

        // ---- exp (unnormalized); per-warp partial row sums ----
        float sA = 0.0f, sB = 0.0f;
        #pragma unroll
        for (int nf = 0; nf < 8; nf++) {
            acc[nf][0] = __expf(acc[nf][0] - mA); sA += acc[nf][0];
            acc[nf][1] = __expf(acc[nf][1] - mA); sA += acc[nf][1];
            acc[nf][2] = __expf(acc[nf][2] - mB); sB += acc[nf][2];
            acc[nf][3] = __expf(acc[nf][3] - mB); sB += acc[nf][3];
        }
        sA += __shfl_xor_sync(0xffffffffu, sA, 1);
        sA += __shfl_xor_sync(0xffffffffu, sA, 2);
        sB += __shfl_xor_sync(0xffffffffu, sB, 1);
        sB += __shfl_xor_sync(0xffffffffu, sB, 2);
        if (l3 == 0) { rsum[lrA * 4 + wn] = sA; rsum[lrB * 4 + wn] = sB; }

        // ---- AV over this warp's own 64-key range; P in registers, V via ldmatrix.trans ----
        float o[4][4];
        #pragma unroll
        for (int nt = 0; nt < 4; nt++)
            #pragma unroll
            for (int j = 0; j < 4; j++) o[nt][j] = 0.0f;

        #pragma unroll
        for (int ks = 0; ks < 4; ks++) {
            uint32_t ph[4], pl[4];
            ph[0] = pack_bf2(acc[2*ks][0],   acc[2*ks][1]);
            ph[1] = pack_bf2(acc[2*ks][2],   acc[2*ks][3]);
            ph[2] = pack_bf2(acc[2*ks+1][0], acc[2*ks+1][1]);
            ph[3] = pack_bf2(acc[2*ks+1][2], acc[2*ks+1][3]);
            pl[0] = pack_bf2_res(acc[2*ks][0],   acc[2*ks][1],   ph[0]);
            pl[1] = pack_bf2_res(acc[2*ks][2],   acc[2*ks][3],   ph[1]);
            pl[2] = pack_bf2_res(acc[2*ks+1][0], acc[2*ks+1][1], ph[2]);
            pl[3] = pack_bf2_res(acc[2*ks+1][2], acc[2*ks+1][3], ph[3]);

            // V B-frags via ldmatrix.trans on row-major V:
            // matrices: {rows vi0..+7, vi0+8..+15} x granules {2pp, 2pp+1}
            int vi0 = wn * 64 + ks * 16;
            uint32_t bh[4][2], bl[4][2];
            #pragma unroll
            for (int pp = 0; pp < 2; pp++) {
                int row = vi0 + (mi & 1) * 8 + rr;
                int gg = pp * 2 + (mi >> 1);
                uint32_t offV = row * 64 + ((gg ^ (row & 3)) << 4);
                uint32_t d0, d1, d2, d3;
                LDSM_X4_T(d0, d1, d2, d3, vh_s + offV);
                bh[pp*2+0][0] = d0; bh[pp*2+0][1] = d1;
                bh[pp*2+1][0] = d2; bh[pp*2+1][1] = d3;
                LDSM_X4_T(d0, d1, d2, d3, vl_s + offV);
                bl[pp*2+0][0] = d0; bl[pp*2+0][1] = d1;
                bl[pp*2+1][0] = d2; bl[pp*2+1][1] = d3;
            }
            #pragma unroll
            for (int nt = 0; nt < 4; nt++) {
                MMA_BF16(o[nt], ph, bh[nt]);
                MMA_BF16(o[nt], ph, bl[nt]);
                MMA_BF16(o[nt], pl, bh[nt]);
            }
        }

        // ---- write partial out to OB[wn] ----
        {
            float* obw = OB + wn * 2176;   // 64*34
            #pragma unroll
            for (int nt = 0; nt < 4; nt++) {
                *(float2*)&obw[lrA * 34 + nt * 8 + l3 * 2] = make_float2(o[nt][0], o[nt][1]);
                *(float2*)&obw[lrB * 34 + nt * 8 + l3 * 2] = make_float2(o[nt][2], o[nt][3]);
            }
        }
        __syncthreads();

        // ---- reduce 4 partials, normalize, gate with fu, store ----
        {
            float invA = 1.0f / (rsum[lrA*4+0] + rsum[lrA*4+1] + rsum[lrA*4+2] + rsum[lrA*4+3]);
            float invB = 1.0f / (rsum[lrB*4+0] + rsum[lrB*4+1] + rsum[lrB*4+2] + rsum[lrB*4+3]);
            int cc = wn * 8 + l3 * 2;
            float2 vA = make_float2(0.0f, 0.0f), vB = make_float2(0.0f, 0.0f);
            #pragma unroll
            for (int j = 0; j < 4; j++) {
                float2 pA = *(float2*)&OB[j * 2176 + lrA * 34 + cc];
                float2 pB = *(float2*)&OB[j * 2176 + lrB * 34 + cc];
                vA.x += pA.x; vA.y += pA.y;
                vB.x += pB.x; vB.y += pB.y;
            }
            size_t iA = base + (size_t)r0 * EDIM + cc;
            size_t iB = base + (size_t)r1 * EDIM + cc;
            float2 fA = *(const float2*)&g_fu[iA];
            float2 fB = *(const float2*)&g_fu[iB];
            *(float2*)&g_ao[iA] = make_float2(vA.x * invA * fA.x, vA.y * invA * fA.y);
            *(float2*)&g_ao[iB] = make_float2(vB.x * invB * fB.x, vB.y * invB * fB.y);
        }
        __syncthreads();
    }
}

// ---------------- host launch ----------------
extern "C" void kernel_launch(void* const* d_in, const int* in_sizes, int n_in,
                              void* d_out, int out_size)
{
    const float* pair_rep = (const float*)d_in[0];
    const float* mask     = (const float*)d_in[1];
    const float* gamma    = (const float*)d_in[2];
    const float* beta     = (const float*)d_in[3];
    const float* Wq       = (const float*)d_in[4];
    const float* Wk       = (const float*)d_in[5];
    const float* Wv       = (const float*)d_in[6];
    const float* Wb       = (const float*)d_in[7];
    const float* Wfu      = (const float*)d_in[8];
    const float* bfu      = (const float*)d_in[9];
    const float* Wo       = (const float*)d_in[10];
    const float* bo       = (const float*)d_in[11];
    float* out = (float*)d_out;

    const int GEMM_SMEM = 128 * 1024;
    const int ATTN_SMEM = 135168;   // 132 KB
    cudaFuncSetAttribute(gemm_proj_kernel, cudaFuncAttributeMaxDynamicSharedMemorySize, GEMM_SMEM);
    cudaFuncSetAttribute(gemm_out_kernel,  cudaFuncAttributeMaxDynamicSharedMemorySize, GEMM_SMEM);
    cudaFuncSetAttribute(attn_kernel,      cudaFuncAttributeMaxDynamicSharedMemorySize, ATTN_SMEM);

    pack_w_kernel<<<(512 * 128 + 128 * 128) / 256, 256>>>(Wq, Wk, Wv, Wfu, Wo);
    ln_kernel<<<RROWS, 128>>>(pair_rep, mask, gamma, beta, Wb);
    gemm_proj_kernel<<<RROWS / 128, 512, GEMM_SMEM>>>(bfu);
    attn_kernel<<<LSEQ * NH, 512, ATTN_SMEM>>>();
    gemm_out_kernel<<<RROWS / 128, 512, GEMM_SMEM>>>(bo, out);
}

// round 15
// speedup vs baseline: 2.2703x; 1.0224x over previous
#include <cuda_runtime.h>
#include <cuda_bf16.h>
#include <stdint.h>
#include <math.h>

#define LSEQ 256
#define EDIM 128
#define NH 4
#define CD 32
#define RROWS (LSEQ*LSEQ)   // 65536

// ---------------- scratch (device globals; no allocs allowed) ----------------
__device__ float g_q [RROWS*EDIM];   // pre-scaled by C^-0.5  (the "v-indexed" operand)
__device__ float g_k [RROWS*EDIM];   // the "q-indexed" operand
__device__ float g_v [RROWS*EDIM];
__device__ float g_fu[RROWS*EDIM];   // sigmoid(x@Wfu + bfu)
__device__ float g_mb[NH*RROWS];     // mb[h][q*256+v] = mask[q,v] + bias[q,v,h]
__device__ float g_ao[RROWS*EDIM];   // gated attention output
// packed+transposed+bf16-split weights: [n][k] layout (col-major B for mma)
__device__ __nv_bfloat16 g_Wt_hi [512*128];
__device__ __nv_bfloat16 g_Wt_lo [512*128];
__device__ __nv_bfloat16 g_Wot_hi[128*128];
__device__ __nv_bfloat16 g_Wot_lo[128*128];

// ---------------- mma / ldmatrix helpers ----------------
#define MMA_BF16(d, a, b) \
    asm volatile("mma.sync.aligned.m16n8k16.row.col.f32.bf16.bf16.f32 " \
        "{%0,%1,%2,%3}, {%4,%5,%6,%7}, {%8,%9}, {%0,%1,%2,%3};" \
        : "+f"(d[0]), "+f"(d[1]), "+f"(d[2]), "+f"(d[3]) \
        : "r"(a[0]), "r"(a[1]), "r"(a[2]), "r"(a[3]), "r"(b[0]), "r"(b[1]))

#define LDSM_X4(d0, d1, d2, d3, a) \
    asm volatile("ldmatrix.sync.aligned.m8n8.x4.shared.b16 {%0,%1,%2,%3}, [%4];" \
        : "=r"(d0), "=r"(d1), "=r"(d2), "=r"(d3) : "r"(a))

#define LDSM_X4_T(d0, d1, d2, d3, a) \
    asm volatile("ldmatrix.sync.aligned.m8n8.x4.trans.shared.b16 {%0,%1,%2,%3}, [%4];" \
        : "=r"(d0), "=r"(d1), "=r"(d2), "=r"(d3) : "r"(a))

__device__ __forceinline__ uint32_t pack_bf2(float a, float b)
{
    __nv_bfloat162 t = __floats2bfloat162_rn(a, b);
    return *(uint32_t*)&t;
}
__device__ __forceinline__ uint32_t pack_bf2_res(float a, float b, uint32_t hi)
{
    __nv_bfloat162 h = *(__nv_bfloat162*)&hi;
    __nv_bfloat162 t = __floats2bfloat162_rn(
        a - __bfloat162float(__low2bfloat16(h)),
        b - __bfloat162float(__high2bfloat16(h)));
    return *(uint32_t*)&t;
}

// ---------------- kernel: pack + transpose + bf16-split weights ----------------
__global__ void pack_w_kernel(const float* __restrict__ Wq, const float* __restrict__ Wk,
                              const float* __restrict__ Wv, const float* __restrict__ Wfu,
                              const float* __restrict__ Wo)
{
    int idx = blockIdx.x * blockDim.x + threadIdx.x;
    if (idx < 512 * 128) {
        int n = idx >> 7, k = idx & 127;
        const float* src = (n < 128) ? Wq : (n < 256) ? Wk : (n < 384) ? Wv : Wfu;
        float v = src[k * 128 + (n & 127)];
        __nv_bfloat16 h = __float2bfloat16_rn(v);
        g_Wt_hi[idx] = h;
        g_Wt_lo[idx] = __float2bfloat16_rn(v - __bfloat162float(h));
    } else {
        int j = idx - 512 * 128;
        int n = j >> 7, k = j & 127;
        float v = Wo[k * 128 + n];
        __nv_bfloat16 h = __float2bfloat16_rn(v);
        g_Wot_hi[j] = h;
        g_Wot_lo[j] = __float2bfloat16_rn(v - __bfloat162float(h));
    }
}

// ---------------- conversion helper: 8 floats -> hi/lo bf16 granules ----------------
__device__ __forceinline__ void split8(const float* fs, uint4& hi, uint4& lo)
{
    uint32_t h[4], l[4];
    #pragma unroll
    for (int j = 0; j < 4; j++) {
        __nv_bfloat162 h2 = __floats2bfloat162_rn(fs[2*j], fs[2*j+1]);
        float r0 = fs[2*j]   - __bfloat162float(__low2bfloat16(h2));
        float r1 = fs[2*j+1] - __bfloat162float(__high2bfloat16(h2));
        __nv_bfloat162 l2 = __floats2bfloat162_rn(r0, r1);
        h[j] = *(uint32_t*)&h2;
        l[j] = *(uint32_t*)&l2;
    }
    hi = make_uint4(h[0], h[1], h[2], h[3]);
    lo = make_uint4(l[0], l[1], l[2], l[3]);
}

// swizzled byte offset for row r (256B pitch), 16B granule c
#define SWOFF(r, c) ((r) * 256 + ((((c) ^ ((r) & 7))) << 4))

// ---------------- kernel: fused LN + pair_bias + projection GEMM ----------------
// LN computed inline on the A tile (pair_rep rows); mb = mask + x@Wb written here.
// 512 thr / 16 warps; warp tile 32x32; K=128 in smem; loops 4 n-tiles (q,k,v,fu).
__global__ void __launch_bounds__(512, 1) gemm_proj_kernel(
    const float* __restrict__ pr, const float* __restrict__ mask,
    const float* __restrict__ gamma, const float* __restrict__ beta,
    const float* __restrict__ Wb, const float* __restrict__ bfu)
{
    extern __shared__ char smem[];
    char* As_hi = smem;
    char* As_lo = smem + 32768;
    char* Bs_hi = smem + 65536;
    char* Bs_lo = smem + 98304;

    int m0 = blockIdx.x * 128;
    int tid = threadIdx.x;
    int cg = tid & 15, rb = tid >> 4;

    // per-thread gamma/beta/Wb slices for cols cg*8..cg*8+7
    float4 gm0 = __ldg((const float4*)&gamma[cg * 8]);
    float4 gm1 = __ldg((const float4*)&gamma[cg * 8 + 4]);
    float4 bt0 = __ldg((const float4*)&beta [cg * 8]);
    float4 bt1 = __ldg((const float4*)&beta [cg * 8 + 4]);
    float gms[8] = {gm0.x,gm0.y,gm0.z,gm0.w,gm1.x,gm1.y,gm1.z,gm1.w};
    float bts[8] = {bt0.x,bt0.y,bt0.z,bt0.w,bt1.x,bt1.y,bt1.z,bt1.w};

    // LN + bias + split per row (4 rows per thread-group of 16 lanes)
    #pragma unroll
    for (int i = 0; i < 4; i++) {
        int r = rb + i * 32;
        const float* src = &pr[(size_t)(m0 + r) * EDIM + cg * 8];
        float4 f0 = *(const float4*)src;
        float4 f1 = *(const float4*)(src + 4);
        float fs[8] = {f0.x,f0.y,f0.z,f0.w,f1.x,f1.y,f1.z,f1.w};

        // mean/var over the 16-lane group (lanes stay within half-warp)
        float s = 0.0f, s2 = 0.0f;
        #pragma unroll
        for (int j = 0; j < 8; j++) { s += fs[j]; s2 += fs[j] * fs[j]; }
        #pragma unroll
        for (int o = 8; o; o >>= 1) {
            s  += __shfl_xor_sync(0xffffffffu, s,  o);
            s2 += __shfl_xor_sync(0xffffffffu, s2, o);
        }
        float mu  = s * (1.0f / EDIM);
        float var = s2 * (1.0f / EDIM) - mu * mu;
        float inv = rsqrtf(var + 1e-5f);

        float b0 = 0.0f, b1 = 0.0f, b2 = 0.0f, b3 = 0.0f;
        #pragma unroll
        for (int j = 0; j < 8; j++) {
            fs[j] = (fs[j] - mu) * inv * gms[j] + bts[j];
            int c = cg * 8 + j;
            b0 += fs[j] * __ldg(&Wb[c * 4 + 0]);
            b1 += fs[j] * __ldg(&Wb[c * 4 + 1]);
            b2 += fs[j] * __ldg(&Wb[c * 4 + 2]);
            b3 += fs[j] * __ldg(&Wb[c * 4 + 3]);
        }
        #pragma unroll
        for (int o = 8; o; o >>= 1) {
            b0 += __shfl_xor_sync(0xffffffffu, b0, o);
            b1 += __shfl_xor_sync(0xffffffffu, b1, o);
            b2 += __shfl_xor_sync(0xffffffffu, b2, o);
            b3 += __shfl_xor_sync(0xffffffffu, b3, o);
        }
        if (cg == 0) {
            int gr = m0 + r;
            float mk = __ldg(&mask[gr]);
            g_mb[0 * RROWS + gr] = mk + b0;
            g_mb[1 * RROWS + gr] = mk + b1;
            g_mb[2 * RROWS + gr] = mk + b2;
            g_mb[3 * RROWS + gr] = mk + b3;
        }

        uint4 hi, lo;
        split8(fs, hi, lo);
        int off = SWOFF(r, cg);
        *(uint4*)(As_hi + off) = hi;
        *(uint4*)(As_lo + off) = lo;
    }

    int w = tid >> 5, l = tid & 31;
    int mw = (w & 3) * 32, nw = (w >> 2) * 32;
    int g = l >> 2, c4 = (l & 3) * 4;
    const float qscale = 0.17677669529663687f;

    for (int nt = 0; nt < 4; nt++) {
        __syncthreads();
        #pragma unroll
        for (int i = 0; i < 4; i++) {
            int r = rb + i * 32;
            int off = SWOFF(r, cg);
            size_t gi = (size_t)(nt * 128 + r) * 128 + cg * 8;
            *(uint4*)(Bs_hi + off) = *(const uint4*)(g_Wt_hi + gi);
            *(uint4*)(Bs_lo + off) = *(const uint4*)(g_Wt_lo + gi);
        }
        __syncthreads();

        float acc[2][4][4];
        #pragma unroll
        for (int mt = 0; mt < 2; mt++)
            #pragma unroll
            for (int n4 = 0; n4 < 4; n4++)
                #pragma unroll
                for (int j = 0; j < 4; j++) acc[mt][n4][j] = 0.0f;

        #pragma unroll
        for (int ks = 0; ks < 8; ks++) {
            uint32_t ah[2][4], al[2][4], bh[4][2], bl[4][2];
            #pragma unroll
            for (int mt = 0; mt < 2; mt++) {
                int r0 = mw + mt * 16 + g, r1 = r0 + 8;
                int ga = ks * 2, gb = ks * 2 + 1;
                int o0 = SWOFF(r0, ga) + c4, o1 = SWOFF(r1, ga) + c4;
                int o2 = SWOFF(r0, gb) + c4, o3 = SWOFF(r1, gb) + c4;
                ah[mt][0] = *(uint32_t*)(As_hi + o0); ah[mt][1] = *(uint32_t*)(As_hi + o1);
                ah[mt][2] = *(uint32_t*)(As_hi + o2); ah[mt][3] = *(uint32_t*)(As_hi + o3);
                al[mt][0] = *(uint32_t*)(As_lo + o0); al[mt][1] = *(uint32_t*)(As_lo + o1);
                al[mt][2] = *(uint32_t*)(As_lo + o2); al[mt][3] = *(uint32_t*)(As_lo + o3);
            }
            #pragma unroll
            for (int n4 = 0; n4 < 4; n4++) {
                int n = nw + n4 * 8 + g;
                int o0 = SWOFF(n, ks * 2) + c4, o1 = SWOFF(n, ks * 2 + 1) + c4;
                bh[n4][0] = *(uint32_t*)(Bs_hi + o0); bh[n4][1] = *(uint32_t*)(Bs_hi + o1);
                bl[n4][0] = *(uint32_t*)(Bs_lo + o0); bl[n4][1] = *(uint32_t*)(Bs_lo + o1);
            }
            #pragma unroll
            for (int mt = 0; mt < 2; mt++)
                #pragma unroll
                for (int n4 = 0; n4 < 4; n4++) {
                    MMA_BF16(acc[mt][n4], ah[mt], bh[n4]);
                    MMA_BF16(acc[mt][n4], ah[mt], bl[n4]);
                    MMA_BF16(acc[mt][n4], al[mt], bh[n4]);
                }
        }

        float* dst = (nt == 0) ? g_q : (nt == 1) ? g_k : (nt == 2) ? g_v : g_fu;
        #pragma unroll
        for (int mt = 0; mt < 2; mt++)
            #pragma unroll
            for (int n4 = 0; n4 < 4; n4++) {
                int m = m0 + mw + mt * 16 + g;
                int ncol = nw + n4 * 8 + (l & 3) * 2;
                float v0 = acc[mt][n4][0], v1 = acc[mt][n4][1];
                float v2 = acc[mt][n4][2], v3 = acc[mt][n4][3];
                if (nt == 0) { v0 *= qscale; v1 *= qscale; v2 *= qscale; v3 *= qscale; }
                if (nt == 3) {
                    float bf0 = bfu[ncol], bf1 = bfu[ncol + 1];
                    v0 = 1.0f / (1.0f + __expf(-(v0 + bf0)));
                    v1 = 1.0f / (1.0f + __expf(-(v1 + bf1)));
                    v2 = 1.0f / (1.0f + __expf(-(v2 + bf0)));
                    v3 = 1.0f / (1.0f + __expf(-(v3 + bf1)));
                }
                *(float2*)&dst[(size_t)m * EDIM + ncol]       = make_float2(v0, v1);
                *(float2*)&dst[(size_t)(m + 8) * EDIM + ncol] = make_float2(v2, v3);
            }
    }
}

// ---------------- kernel: output GEMM via bf16-split tensor cores ----------------
__global__ void __launch_bounds__(512, 1) gemm_out_kernel(
    const float* __restrict__ bo, float* __restrict__ out)
{
    extern __shared__ char smem[];
    char* As_hi = smem;
    char* As_lo = smem + 32768;
    char* Bs_hi = smem + 65536;
    char* Bs_lo = smem + 98304;

    int m0 = blockIdx.x * 128;
    int tid = threadIdx.x;
    int cg = tid & 15, rb = tid >> 4;

    #pragma unroll
    for (int i = 0; i < 4; i++) {
        int r = rb + i * 32;
        const float* src = &g_ao[(size_t)(m0 + r) * EDIM + cg * 8];
        float4 f0 = *(const float4*)src;
        float4 f1 = *(const float4*)(src + 4);
        float fs[8] = {f0.x,f0.y,f0.z,f0.w,f1.x,f1.y,f1.z,f1.w};
        uint4 hi, lo;
        split8(fs, hi, lo);
        int off = SWOFF(r, cg);
        *(uint4*)(As_hi + off) = hi;
        *(uint4*)(As_lo + off) = lo;

        size_t gi = (size_t)r * 128 + cg * 8;
        *(uint4*)(Bs_hi + off) = *(const uint4*)(g_Wot_hi + gi);
        *(uint4*)(Bs_lo + off) = *(const uint4*)(g_Wot_lo + gi);
    }
    __syncthreads();

    int w = tid >> 5, l = tid & 31;
    int mw = (w & 3) * 32, nw = (w >> 2) * 32;
    int g = l >> 2, c4 = (l & 3) * 4;

    float acc[2][4][4];
    #pragma unroll
    for (int mt = 0; mt < 2; mt++)
        #pragma unroll
        for (int n4 = 0; n4 < 4; n4++)
            #pragma unroll
            for (int j = 0; j < 4; j++) acc[mt][n4][j] = 0.0f;

    #pragma unroll
    for (int ks = 0; ks < 8; ks++) {
        uint32_t ah[2][4], al[2][4], bh[4][2], bl[4][2];
        #pragma unroll
        for (int mt = 0; mt < 2; mt++) {
            int r0 = mw + mt * 16 + g, r1 = r0 + 8;
            int ga = ks * 2, gb = ks * 2 + 1;
            int o0 = SWOFF(r0, ga) + c4, o1 = SWOFF(r1, ga) + c4;
            int o2 = SWOFF(r0, gb) + c4, o3 = SWOFF(r1, gb) + c4;
            ah[mt][0] = *(uint32_t*)(As_hi + o0); ah[mt][1] = *(uint32_t*)(As_hi + o1);
            ah[mt][2] = *(uint32_t*)(As_hi + o2); ah[mt][3] = *(uint32_t*)(As_hi + o3);
            al[mt][0] = *(uint32_t*)(As_lo + o0); al[mt][1] = *(uint32_t*)(As_lo + o1);
            al[mt][2] = *(uint32_t*)(As_lo + o2); al[mt][3] = *(uint32_t*)(As_lo + o3);
        }
        #pragma unroll
        for (int n4 = 0; n4 < 4; n4++) {
            int n = nw + n4 * 8 + g;
            int o0 = SWOFF(n, ks * 2) + c4, o1 = SWOFF(n, ks * 2 + 1) + c4;
            bh[n4][0] = *(uint32_t*)(Bs_hi + o0); bh[n4][1] = *(uint32_t*)(Bs_hi + o1);
            bl[n4][0] = *(uint32_t*)(Bs_lo + o0); bl[n4][1] = *(uint32_t*)(Bs_lo + o1);
        }
        #pragma unroll
        for (int mt = 0; mt < 2; mt++)
            #pragma unroll
            for (int n4 = 0; n4 < 4; n4++) {
                MMA_BF16(acc[mt][n4], ah[mt], bh[n4]);
                MMA_BF16(acc[mt][n4], ah[mt], bl[n4]);
                MMA_BF16(acc[mt][n4], al[mt], bh[n4]);
            }
    }

    #pragma unroll
    for (int mt = 0; mt < 2; mt++)
        #pragma unroll
        for (int n4 = 0; n4 < 4; n4++) {
            int m = m0 + mw + mt * 16 + g;
            int ncol = nw + n4 * 8 + (l & 3) * 2;
            float b0 = bo[ncol], b1 = bo[ncol + 1];
            *(float2*)&out[(size_t)m * EDIM + ncol] =
                make_float2(acc[mt][n4][0] + b0, acc[mt][n4][1] + b1);
            *(float2*)&out[(size_t)(m + 8) * EDIM + ncol] =
                make_float2(acc[mt][n4][2] + b0, acc[mt][n4][3] + b1);
        }
}

// ---------------- kernel: tensor-core attention, conflict-free prep + trans-V ----------------
__global__ void __launch_bounds__(512, 1) attn_kernel()
{
    extern __shared__ char sm[];
    char* KH = sm;
    char* KL = sm + 16384;
    char* QH = sm + 32768;
    char* QL = sm + 49152;
    char* VH = sm + 65536;
    char* VL = sm + 81920;
    float* OB   = (float*)(sm + 98304);    // [4][64][34]
    float* rmax = (float*)(sm + 133120);   // [64][4]
    float* rsum = (float*)(sm + 134144);   // [64][4]

    int s = blockIdx.x >> 2;
    int h = blockIdx.x & 3;
    int tid = threadIdx.x;
    size_t base = (size_t)s * 256 * EDIM + h * CD;

    #pragma unroll
    for (int i = 0; i < 6; i++) {
        int slot = tid + i * 512;
        int within = slot & 1023;
        int r = within >> 2, gg = within & 3;
        const float* srcb = (i < 2) ? g_k : (i < 4) ? g_q : g_v;
        char* DH = (i < 2) ? KH : (i < 4) ? QH : VH;
        char* DL = (i < 2) ? KL : (i < 4) ? QL : VL;
        const float* src = srcb + base + (size_t)r * EDIM + gg * 8;
        float4 f0 = *(const float4*)src;
        float4 f1 = *(const float4*)(src + 4);
        float fs[8] = {f0.x,f0.y,f0.z,f0.w,f1.x,f1.y,f1.z,f1.w};
        uint4 hi, lo;
        split8(fs, hi, lo);
        int off = r * 64 + ((gg ^ (r & 3)) << 4);
        *(uint4*)(DH + off) = hi;
        *(uint4*)(DL + off) = lo;
    }
    __syncthreads();

    uint32_t kh_s = (uint32_t)__cvta_generic_to_shared(KH);
    uint32_t kl_s = (uint32_t)__cvta_generic_to_shared(KL);
    uint32_t qh_s = (uint32_t)__cvta_generic_to_shared(QH);
    uint32_t ql_s = (uint32_t)__cvta_generic_to_shared(QL);
    uint32_t vh_s = (uint32_t)__cvta_generic_to_shared(VH);
    uint32_t vl_s = (uint32_t)__cvta_generic_to_shared(VL);

    int w = tid >> 5, l = tid & 31;
    int g = l >> 2, l3 = l & 3;
    int mi = l >> 3, rr = l & 7;
    int wm = w >> 2, wn = w & 3;
    const float* mb = g_mb + (size_t)h * RROWS;

    for (int c0 = 0; c0 < 256; c0 += 64) {
        float acc[8][4];
        #pragma unroll
        for (int nf = 0; nf < 8; nf++)
            #pragma unroll
            for (int j = 0; j < 4; j++) acc[nf][j] = 0.0f;

        int r0 = c0 + wm * 16 + g, r1 = r0 + 8;
        int RA = c0 + wm * 16 + (mi & 1) * 8 + rr;

        #pragma unroll
        for (int ks = 0; ks < 2; ks++) {
            uint32_t ah[4], al[4];
            {
                int gA = ks * 2 + (mi >> 1);
                uint32_t offA = RA * 64 + ((gA ^ (RA & 3)) << 4);
                LDSM_X4(ah[0], ah[1], ah[2], ah[3], kh_s + offA);
                LDSM_X4(al[0], al[1], al[2], al[3], kl_s + offA);
            }
            #pragma unroll
            for (int np = 0; np < 4; np++) {
                int nB = wn * 64 + np * 16 + (mi >> 1) * 8 + rr;
                int gB = ks * 2 + (mi & 1);
                uint32_t offB = nB * 64 + ((gB ^ (nB & 3)) << 4);
                uint32_t b0h, b1h, b2h, b3h, b0l, b1l, b2l, b3l;
                LDSM_X4(b0h, b1h, b2h, b3h, qh_s + offB);
                LDSM_X4(b0l, b1l, b2l, b3l, ql_s + offB);
                uint32_t bhA[2] = {b0h, b1h}, bhB[2] = {b2h, b3h};
                uint32_t blA[2] = {b0l, b1l}, blB[2] = {b2l, b3l};
                MMA_BF16(acc[np * 2],     ah, bhA);
                MMA_BF16(acc[np * 2],     ah, blA);
                MMA_BF16(acc[np * 2],     al, bhA);
                MMA_BF16(acc[np * 2 + 1], ah, bhB);
                MMA_BF16(acc[np * 2 + 1], ah, blB);
                MMA_BF16(acc[np * 2 + 1], al, bhB);
            }
        }

        #pragma unroll
        for (int nf = 0; nf < 8; nf++) {
            int vi = wn * 64 + nf * 8 + l3 * 2;
            float2 m0 = __ldg((const float2*)&mb[(size_t)r0 * 256 + vi]);
            float2 m1 = __ldg((const float2*)&mb[(size_t)r1 * 256 + vi]);
            acc[nf][0] += m0.x; acc[nf][1] += m0.y;
            acc[nf][2] += m1.x; acc[nf][3] += m1.y;
        }

        int lrA = wm * 16 + g, lrB = lrA + 8;
        float mA = -1e30f, mB = -1e30f;
        #pragma unroll
        for (int nf = 0; nf < 8; nf++) {
            mA = fmaxf(mA, fmaxf(acc[nf][0], acc[nf][1]));
            mB = fmaxf(mB, fmaxf(acc[nf][2], acc[nf][3]));
        }
        mA = fmaxf(mA, __shfl_xor_sync(0xffffffffu, mA, 1));
        mA = fmaxf(mA, __shfl_xor_sync(0xffffffffu, mA, 2));
        mB = fmaxf(mB, __shfl_xor_sync(0xffffffffu, mB, 1));
        mB = fmaxf(mB, __shfl_xor_sync(0xffffffffu, mB, 2));
        if (l3 == 0) { rmax[lrA * 4 + wn] = mA; rmax[lrB * 4 + wn] = mB; }
        __syncthreads();
        mA = fmaxf(fmaxf(rmax[lrA*4+0], rmax[lrA*4+1]), fmaxf(rmax[lrA*4+2], rmax[lrA*4+3]));
        mB = fmaxf(fmaxf(rmax[lrB*4+0], rmax[lrB*4+1]), fmaxf(rmax[lrB*4+2], rmax[lrB*4+3]));

        float sA = 0.0f, sB = 0.0f;
        #pragma unroll
        for (int nf = 0; nf < 8; nf++) {
            acc[nf][0] = __expf(acc[nf][0] - mA); sA += acc[nf][0];
            acc[nf][1] = __expf(acc[nf][1] - mA); sA += acc[nf][1];
            acc[nf][2] = __expf(acc[nf][2] - mB); sB += acc[nf][2];
            acc[nf][3] = __expf(acc[nf][3] - mB); sB += acc[nf][3];
        }
        sA += __shfl_xor_sync(0xffffffffu, sA, 1);
        sA += __shfl_xor_sync(0xffffffffu, sA, 2);
        sB += __shfl_xor_sync(0xffffffffu, sB, 1);
        sB += __shfl_xor_sync(0xffffffffu, sB, 2);
        if (l3 == 0) { rsum[lrA * 4 + wn] = sA; rsum[lrB * 4 + wn] = sB; }

        float o[4][4];
        #pragma unroll
        for (int nt = 0; nt < 4; nt++)
            #pragma unroll
            for (int j = 0; j < 4; j++) o[nt][j] = 0.0f;

        #pragma unroll
        for (int ks = 0; ks < 4; ks++) {
            uint32_t ph[4], pl[4];
            ph[0] = pack_bf2(acc[2*ks][0],   acc[2*ks][1]);
            ph[1] = pack_bf2(acc[2*ks][2],   acc[2*ks][3]);
            ph[2] = pack_bf2(acc[2*ks+1][0], acc[2*ks+1][1]);
            ph[3] = pack_bf2(acc[2*ks+1][2], acc[2*ks+1][3]);
            pl[0] = pack_bf2_res(acc[2*ks][0],   acc[2*ks][1],   ph[0]);
            pl[1] = pack_bf2_res(acc[2*ks][2],   acc[2*ks][3],   ph[1]);
            pl[2] = pack_bf2_res(acc[2*ks+1][0], acc[2*ks+1][1], ph[2]);
            pl[3] = pack_bf2_res(acc[2*ks+1][2], acc[2*ks+1][3], ph[3]);

            int vi0 = wn * 64 + ks * 16;
            uint32_t bh[4][2], bl[4][2];
            #pragma unroll
            for (int pp = 0; pp < 2; pp++) {
                int row = vi0 + (mi & 1) * 8 + rr;
                int gg = pp * 2 + (mi >> 1);
                uint32_t offV = row * 64 + ((gg ^ (row & 3)) << 4);
                uint32_t d0, d1, d2, d3;
                LDSM_X4_T(d0, d1, d2, d3, vh_s + offV);
                bh[pp*2+0][0] = d0; bh[pp*2+0][1] = d1;
                bh[pp*2+1][0] = d2; bh[pp*2+1][1] = d3;
                LDSM_X4_T(d0, d1, d2, d3, vl_s + offV);
                bl[pp*2+0][0] = d0; bl[pp*2+0][1] = d1;
                bl[pp*2+1][0] = d2; bl[pp*2+1][1] = d3;
            }
            #pragma unroll
            for (int nt = 0; nt < 4; nt++) {
                MMA_BF16(o[nt], ph, bh[nt]);
                MMA_BF16(o[nt], ph, bl[nt]);
                MMA_BF16(o[nt], pl, bh[nt]);
            }
        }

        {
            float* obw = OB + wn * 2176;
            #pragma unroll
            for (int nt = 0; nt < 4; nt++) {
                *(float2*)&obw[lrA * 34 + nt * 8 + l3 * 2] = make_float2(o[nt][0], o[nt][1]);
                *(float2*)&obw[lrB * 34 + nt * 8 + l3 * 2] = make_float2(o[nt][2], o[nt][3]);
            }
        }
        __syncthreads();

        {
            float invA = 1.0f / (rsum[lrA*4+0] + rsum[lrA*4+1] + rsum[lrA*4+2] + rsum[lrA*4+3]);
            float invB = 1.0f / (rsum[lrB*4+0] + rsum[lrB*4+1] + rsum[lrB*4+2] + rsum[lrB*4+3]);
            int cc = wn * 8 + l3 * 2;
            float2 vA = make_float2(0.0f, 0.0f), vB = make_float2(0.0f, 0.0f);
            #pragma unroll
            for (int j = 0; j < 4; j++) {
                float2 pA = *(float2*)&OB[j * 2176 + lrA * 34 + cc];
                float2 pB = *(float2*)&OB[j * 2176 + lrB * 34 + cc];
                vA.x += pA.x; vA.y += pA.y;
                vB.x += pB.x; vB.y += pB.y;
            }
            size_t iA = base + (size_t)r0 * EDIM + cc;
            size_t iB = base + (size_t)r1 * EDIM + cc;
            float2 fA = *(const float2*)&g_fu[iA];
            float2 fB = *(const float2*)&g_fu[iB];
            *(float2*)&g_ao[iA] = make_float2(vA.x * invA * fA.x, vA.y * invA * fA.y);
            *(float2*)&g_ao[iB] = make_float2(vB.x * invB * fB.x, vB.y * invB * fB.y);
        }
        __syncthreads();
    }
}

// ---------------- host launch ----------------
extern "C" void kernel_launch(void* const* d_in, const int* in_sizes, int n_in,
                              void* d_out, int out_size)
{
    const float* pair_rep = (const float*)d_in[0];
    const float* mask     = (const float*)d_in[1];
    const float* gamma    = (const float*)d_in[2];
    const float* beta     = (const float*)d_in[3];
    const float* Wq       = (const float*)d_in[4];
    const float* Wk       = (const float*)d_in[5];
    const float* Wv       = (const float*)d_in[6];
    const float* Wb       = (const float*)d_in[7];
    const float* Wfu      = (const float*)d_in[8];
    const float* bfu      = (const float*)d_in[9];
    const float* Wo       = (const float*)d_in[10];
    const float* bo       = (const float*)d_in[11];
    float* out = (float*)d_out;

    const int GEMM_SMEM = 128 * 1024;
    const int ATTN_SMEM = 135168;   // 132 KB
    cudaFuncSetAttribute(gemm_proj_kernel, cudaFuncAttributeMaxDynamicSharedMemorySize, GEMM_SMEM);
    cudaFuncSetAttribute(gemm_out_kernel,  cudaFuncAttributeMaxDynamicSharedMemorySize, GEMM_SMEM);
    cudaFuncSetAttribute(attn_kernel,      cudaFuncAttributeMaxDynamicSharedMemorySize, ATTN_SMEM);

    pack_w_kernel<<<(512 * 128 + 128 * 128) / 256, 256>>>(Wq, Wk, Wv, Wfu, Wo);
    gemm_proj_kernel<<<RROWS / 128, 512, GEMM_SMEM>>>(pair_rep, mask, gamma, beta, Wb, bfu);
    attn_kernel<<<LSEQ * NH, 512, ATTN_SMEM>>>();
    gemm_out_kernel<<<RROWS / 128, 512, GEMM_SMEM>>>(bo, out);
}

// round 16
// speedup vs baseline: 2.3858x; 1.0509x over previous
#include <cuda_runtime.h>
#include <cuda_bf16.h>
#include <stdint.h>
#include <math.h>

#define LSEQ 256
#define EDIM 128
#define NH 4
#define CD 32
#define RROWS (LSEQ*LSEQ)   // 65536

// ---------------- scratch (device globals; no allocs allowed) ----------------
__device__ float g_q [RROWS*EDIM];   // pre-scaled by C^-0.5  (the "v-indexed" operand)
__device__ float g_k [RROWS*EDIM];   // the "q-indexed" operand
__device__ float g_v [RROWS*EDIM];
__device__ float g_fu[RROWS*EDIM];   // sigmoid(x@Wfu + bfu)
__device__ float g_mb[NH*RROWS];     // mb[h][q*256+v] = mask[q,v] + bias[q,v,h]
__device__ float g_ao[RROWS*EDIM];   // gated attention output
// packed+transposed+bf16-split weights: [n][k] layout (col-major B for mma)
__device__ __nv_bfloat16 g_Wt_hi [512*128];
__device__ __nv_bfloat16 g_Wt_lo [512*128];
__device__ __nv_bfloat16 g_Wot_hi[128*128];
__device__ __nv_bfloat16 g_Wot_lo[128*128];

// ---------------- mma / ldmatrix helpers ----------------
#define MMA_BF16(d, a, b) \
    asm volatile("mma.sync.aligned.m16n8k16.row.col.f32.bf16.bf16.f32 " \
        "{%0,%1,%2,%3}, {%4,%5,%6,%7}, {%8,%9}, {%0,%1,%2,%3};" \
        : "+f"(d[0]), "+f"(d[1]), "+f"(d[2]), "+f"(d[3]) \
        : "r"(a[0]), "r"(a[1]), "r"(a[2]), "r"(a[3]), "r"(b[0]), "r"(b[1]))

#define LDSM_X4(d0, d1, d2, d3, a) \
    asm volatile("ldmatrix.sync.aligned.m8n8.x4.shared.b16 {%0,%1,%2,%3}, [%4];" \
        : "=r"(d0), "=r"(d1), "=r"(d2), "=r"(d3) : "r"(a))

#define LDSM_X4_T(d0, d1, d2, d3, a) \
    asm volatile("ldmatrix.sync.aligned.m8n8.x4.trans.shared.b16 {%0,%1,%2,%3}, [%4];" \
        : "=r"(d0), "=r"(d1), "=r"(d2), "=r"(d3) : "r"(a))

__device__ __forceinline__ uint32_t pack_bf2(float a, float b)
{
    __nv_bfloat162 t = __floats2bfloat162_rn(a, b);
    return *(uint32_t*)&t;
}
__device__ __forceinline__ uint32_t pack_bf2_res(float a, float b, uint32_t hi)
{
    __nv_bfloat162 h = *(__nv_bfloat162*)&hi;
    __nv_bfloat162 t = __floats2bfloat162_rn(
        a - __bfloat162float(__low2bfloat16(h)),
        b - __bfloat162float(__high2bfloat16(h)));
    return *(uint32_t*)&t;
}

// attn tile swizzle: row r (64B pitch), 16B granule g.
// slot(r) = (r&1)*4 + (g ^ ((r>>1)&3)) is a bijection over r mod 8 ->
// every 8-row x 16B ldmatrix access is conflict-free.
#define ASW(r, g) ((r) * 64 + ((((g) ^ (((r) >> 1) & 3))) << 4))

// ---------------- kernel: pack + transpose + bf16-split weights ----------------
__global__ void pack_w_kernel(const float* __restrict__ Wq, const float* __restrict__ Wk,
                              const float* __restrict__ Wv, const float* __restrict__ Wfu,
                              const float* __restrict__ Wo)
{
    int idx = blockIdx.x * blockDim.x + threadIdx.x;
    if (idx < 512 * 128) {
        int n = idx >> 7, k = idx & 127;
        const float* src = (n < 128) ? Wq : (n < 256) ? Wk : (n < 384) ? Wv : Wfu;
        float v = src[k * 128 + (n & 127)];
        __nv_bfloat16 h = __float2bfloat16_rn(v);
        g_Wt_hi[idx] = h;
        g_Wt_lo[idx] = __float2bfloat16_rn(v - __bfloat162float(h));
    } else {
        int j = idx - 512 * 128;
        int n = j >> 7, k = j & 127;
        float v = Wo[k * 128 + n];
        __nv_bfloat16 h = __float2bfloat16_rn(v);
        g_Wot_hi[j] = h;
        g_Wot_lo[j] = __float2bfloat16_rn(v - __bfloat162float(h));
    }
}

// ---------------- conversion helper: 8 floats -> hi/lo bf16 granules ----------------
__device__ __forceinline__ void split8(const float* fs, uint4& hi, uint4& lo)
{
    uint32_t h[4], l[4];
    #pragma unroll
    for (int j = 0; j < 4; j++) {
        __nv_bfloat162 h2 = __floats2bfloat162_rn(fs[2*j], fs[2*j+1]);
        float r0 = fs[2*j]   - __bfloat162float(__low2bfloat16(h2));
        float r1 = fs[2*j+1] - __bfloat162float(__high2bfloat16(h2));
        __nv_bfloat162 l2 = __floats2bfloat162_rn(r0, r1);
        h[j] = *(uint32_t*)&h2;
        l[j] = *(uint32_t*)&l2;
    }
    hi = make_uint4(h[0], h[1], h[2], h[3]);
    lo = make_uint4(l[0], l[1], l[2], l[3]);
}

// swizzled byte offset for row r (256B pitch), 16B granule c  (gemm kernels)
#define SWOFF(r, c) ((r) * 256 + ((((c) ^ ((r) & 7))) << 4))

// ---------------- kernel: fused LN + pair_bias + projection GEMM ----------------
__global__ void __launch_bounds__(512, 1) gemm_proj_kernel(
    const float* __restrict__ pr, const float* __restrict__ mask,
    const float* __restrict__ gamma, const float* __restrict__ beta,
    const float* __restrict__ Wb, const float* __restrict__ bfu)
{
    extern __shared__ char smem[];
    char* As_hi = smem;
    char* As_lo = smem + 32768;
    char* Bs_hi = smem + 65536;
    char* Bs_lo = smem + 98304;

    int m0 = blockIdx.x * 128;
    int tid = threadIdx.x;
    int cg = tid & 15, rb = tid >> 4;

    float4 gm0 = __ldg((const float4*)&gamma[cg * 8]);
    float4 gm1 = __ldg((const float4*)&gamma[cg * 8 + 4]);
    float4 bt0 = __ldg((const float4*)&beta [cg * 8]);
    float4 bt1 = __ldg((const float4*)&beta [cg * 8 + 4]);
    float gms[8] = {gm0.x,gm0.y,gm0.z,gm0.w,gm1.x,gm1.y,gm1.z,gm1.w};
    float bts[8] = {bt0.x,bt0.y,bt0.z,bt0.w,bt1.x,bt1.y,bt1.z,bt1.w};

    #pragma unroll
    for (int i = 0; i < 4; i++) {
        int r = rb + i * 32;
        const float* src = &pr[(size_t)(m0 + r) * EDIM + cg * 8];
        float4 f0 = *(const float4*)src;
        float4 f1 = *(const float4*)(src + 4);
        float fs[8] = {f0.x,f0.y,f0.z,f0.w,f1.x,f1.y,f1.z,f1.w};

        float s = 0.0f, s2 = 0.0f;
        #pragma unroll
        for (int j = 0; j < 8; j++) { s += fs[j]; s2 += fs[j] * fs[j]; }
        #pragma unroll
        for (int o = 8; o; o >>= 1) {
            s  += __shfl_xor_sync(0xffffffffu, s,  o);
            s2 += __shfl_xor_sync(0xffffffffu, s2, o);
        }
        float mu  = s * (1.0f / EDIM);
        float var = s2 * (1.0f / EDIM) - mu * mu;
        float inv = rsqrtf(var + 1e-5f);

        float b0 = 0.0f, b1 = 0.0f, b2 = 0.0f, b3 = 0.0f;
        #pragma unroll
        for (int j = 0; j < 8; j++) {
            fs[j] = (fs[j] - mu) * inv * gms[j] + bts[j];
            int c = cg * 8 + j;
            b0 += fs[j] * __ldg(&Wb[c * 4 + 0]);
            b1 += fs[j] * __ldg(&Wb[c * 4 + 1]);
            b2 += fs[j] * __ldg(&Wb[c * 4 + 2]);
            b3 += fs[j] * __ldg(&Wb[c * 4 + 3]);
        }
        #pragma unroll
        for (int o = 8; o; o >>= 1) {
            b0 += __shfl_xor_sync(0xffffffffu, b0, o);
            b1 += __shfl_xor_sync(0xffffffffu, b1, o);
            b2 += __shfl_xor_sync(0xffffffffu, b2, o);
            b3 += __shfl_xor_sync(0xffffffffu, b3, o);
        }
        if (cg == 0) {
            int gr = m0 + r;
            float mk = __ldg(&mask[gr]);
            g_mb[0 * RROWS + gr] = mk + b0;
            g_mb[1 * RROWS + gr] = mk + b1;
            g_mb[2 * RROWS + gr] = mk + b2;
            g_mb[3 * RROWS + gr] = mk + b3;
        }

        uint4 hi, lo;
        split8(fs, hi, lo);
        int off = SWOFF(r, cg);
        *(uint4*)(As_hi + off) = hi;
        *(uint4*)(As_lo + off) = lo;
    }

    int w = tid >> 5, l = tid & 31;
    int mw = (w & 3) * 32, nw = (w >> 2) * 32;
    int g = l >> 2, c4 = (l & 3) * 4;
    const float qscale = 0.17677669529663687f;

    for (int nt = 0; nt < 4; nt++) {
        __syncthreads();
        #pragma unroll
        for (int i = 0; i < 4; i++) {
            int r = rb + i * 32;
            int off = SWOFF(r, cg);
            size_t gi = (size_t)(nt * 128 + r) * 128 + cg * 8;
            *(uint4*)(Bs_hi + off) = *(const uint4*)(g_Wt_hi + gi);
            *(uint4*)(Bs_lo + off) = *(const uint4*)(g_Wt_lo + gi);
        }
        __syncthreads();

        float acc[2][4][4];
        #pragma unroll
        for (int mt = 0; mt < 2; mt++)
            #pragma unroll
            for (int n4 = 0; n4 < 4; n4++)
                #pragma unroll
                for (int j = 0; j < 4; j++) acc[mt][n4][j] = 0.0f;

        #pragma unroll
        for (int ks = 0; ks < 8; ks++) {
            uint32_t ah[2][4], al[2][4], bh[4][2], bl[4][2];
            #pragma unroll
            for (int mt = 0; mt < 2; mt++) {
                int r0 = mw + mt * 16 + g, r1 = r0 + 8;
                int ga = ks * 2, gb = ks * 2 + 1;
                int o0 = SWOFF(r0, ga) + c4, o1 = SWOFF(r1, ga) + c4;
                int o2 = SWOFF(r0, gb) + c4, o3 = SWOFF(r1, gb) + c4;
                ah[mt][0] = *(uint32_t*)(As_hi + o0); ah[mt][1] = *(uint32_t*)(As_hi + o1);
                ah[mt][2] = *(uint32_t*)(As_hi + o2); ah[mt][3] = *(uint32_t*)(As_hi + o3);
                al[mt][0] = *(uint32_t*)(As_lo + o0); al[mt][1] = *(uint32_t*)(As_lo + o1);
                al[mt][2] = *(uint32_t*)(As_lo + o2); al[mt][3] = *(uint32_t*)(As_lo + o3);
            }
            #pragma unroll
            for (int n4 = 0; n4 < 4; n4++) {
                int n = nw + n4 * 8 + g;
                int o0 = SWOFF(n, ks * 2) + c4, o1 = SWOFF(n, ks * 2 + 1) + c4;
                bh[n4][0] = *(uint32_t*)(Bs_hi + o0); bh[n4][1] = *(uint32_t*)(Bs_hi + o1);
                bl[n4][0] = *(uint32_t*)(Bs_lo + o0); bl[n4][1] = *(uint32_t*)(Bs_lo + o1);
            }
            #pragma unroll
            for (int mt = 0; mt < 2; mt++)
                #pragma unroll
                for (int n4 = 0; n4 < 4; n4++) {
                    MMA_BF16(acc[mt][n4], ah[mt], bh[n4]);
                    MMA_BF16(acc[mt][n4], ah[mt], bl[n4]);
                    MMA_BF16(acc[mt][n4], al[mt], bh[n4]);
                }
        }

        float* dst = (nt == 0) ? g_q : (nt == 1) ? g_k : (nt == 2) ? g_v : g_fu;
        #pragma unroll
        for (int mt = 0; mt < 2; mt++)
            #pragma unroll
            for (int n4 = 0; n4 < 4; n4++) {
                int m = m0 + mw + mt * 16 + g;
                int ncol = nw + n4 * 8 + (l & 3) * 2;
                float v0 = acc[mt][n4][0], v1 = acc[mt][n4][1];
                float v2 = acc[mt][n4][2], v3 = acc[mt][n4][3];
                if (nt == 0) { v0 *= qscale; v1 *= qscale; v2 *= qscale; v3 *= qscale; }
                if (nt == 3) {
                    float bf0 = bfu[ncol], bf1 = bfu[ncol + 1];
                    v0 = 1.0f / (1.0f + __expf(-(v0 + bf0)));
                    v1 = 1.0f / (1.0f + __expf(-(v1 + bf1)));
                    v2 = 1.0f / (1.0f + __expf(-(v2 + bf0)));
                    v3 = 1.0f / (1.0f + __expf(-(v3 + bf1)));
                }
                *(float2*)&dst[(size_t)m * EDIM + ncol]       = make_float2(v0, v1);
                *(float2*)&dst[(size_t)(m + 8) * EDIM + ncol] = make_float2(v2, v3);
            }
    }
}

// ---------------- kernel: output GEMM via bf16-split tensor cores ----------------
__global__ void __launch_bounds__(512, 1) gemm_out_kernel(
    const float* __restrict__ bo, float* __restrict__ out)
{
    extern __shared__ char smem[];
    char* As_hi = smem;
    char* As_lo = smem + 32768;
    char* Bs_hi = smem + 65536;
    char* Bs_lo = smem + 98304;

    int m0 = blockIdx.x * 128;
    int tid = threadIdx.x;
    int cg = tid & 15, rb = tid >> 4;

    #pragma unroll
    for (int i = 0; i < 4; i++) {
        int r = rb + i * 32;
        const float* src = &g_ao[(size_t)(m0 + r) * EDIM + cg * 8];
        float4 f0 = *(const float4*)src;
        float4 f1 = *(const float4*)(src + 4);
        float fs[8] = {f0.x,f0.y,f0.z,f0.w,f1.x,f1.y,f1.z,f1.w};
        uint4 hi, lo;
        split8(fs, hi, lo);
        int off = SWOFF(r, cg);
        *(uint4*)(As_hi + off) = hi;
        *(uint4*)(As_lo + off) = lo;

        size_t gi = (size_t)r * 128 + cg * 8;
        *(uint4*)(Bs_hi + off) = *(const uint4*)(g_Wot_hi + gi);
        *(uint4*)(Bs_lo + off) = *(const uint4*)(g_Wot_lo + gi);
    }
    __syncthreads();

    int w = tid >> 5, l = tid & 31;
    int mw = (w & 3) * 32, nw = (w >> 2) * 32;
    int g = l >> 2, c4 = (l & 3) * 4;

    float acc[2][4][4];
    #pragma unroll
    for (int mt = 0; mt < 2; mt++)
        #pragma unroll
        for (int n4 = 0; n4 < 4; n4++)
            #pragma unroll
            for (int j = 0; j < 4; j++) acc[mt][n4][j] = 0.0f;

    #pragma unroll
    for (int ks = 0; ks < 8; ks++) {
        uint32_t ah[2][4], al[2][4], bh[4][2], bl[4][2];
        #pragma unroll
        for (int mt = 0; mt < 2; mt++) {
            int r0 = mw + mt * 16 + g, r1 = r0 + 8;
            int ga = ks * 2, gb = ks * 2 + 1;
            int o0 = SWOFF(r0, ga) + c4, o1 = SWOFF(r1, ga) + c4;
            int o2 = SWOFF(r0, gb) + c4, o3 = SWOFF(r1, gb) + c4;
            ah[mt][0] = *(uint32_t*)(As_hi + o0); ah[mt][1] = *(uint32_t*)(As_hi + o1);
            ah[mt][2] = *(uint32_t*)(As_hi + o2); ah[mt][3] = *(uint32_t*)(As_hi + o3);
            al[mt][0] = *(uint32_t*)(As_lo + o0); al[mt][1] = *(uint32_t*)(As_lo + o1);
            al[mt][2] = *(uint32_t*)(As_lo + o2); al[mt][3] = *(uint32_t*)(As_lo + o3);
        }
        #pragma unroll
        for (int n4 = 0; n4 < 4; n4++) {
            int n = nw + n4 * 8 + g;
            int o0 = SWOFF(n, ks * 2) + c4, o1 = SWOFF(n, ks * 2 + 1) + c4;
            bh[n4][0] = *(uint32_t*)(Bs_hi + o0); bh[n4][1] = *(uint32_t*)(Bs_hi + o1);
            bl[n4][0] = *(uint32_t*)(Bs_lo + o0); bl[n4][1] = *(uint32_t*)(Bs_lo + o1);
        }
        #pragma unroll
        for (int mt = 0; mt < 2; mt++)
            #pragma unroll
            for (int n4 = 0; n4 < 4; n4++) {
                MMA_BF16(acc[mt][n4], ah[mt], bh[n4]);
                MMA_BF16(acc[mt][n4], ah[mt], bl[n4]);
                MMA_BF16(acc[mt][n4], al[mt], bh[n4]);
            }
    }

    #pragma unroll
    for (int mt = 0; mt < 2; mt++)
        #pragma unroll
        for (int n4 = 0; n4 < 4; n4++) {
            int m = m0 + mw + mt * 16 + g;
            int ncol = nw + n4 * 8 + (l & 3) * 2;
            float b0 = bo[ncol], b1 = bo[ncol + 1];
            *(float2*)&out[(size_t)m * EDIM + ncol] =
                make_float2(acc[mt][n4][0] + b0, acc[mt][n4][1] + b1);
            *(float2*)&out[(size_t)(m + 8) * EDIM + ncol] =
                make_float2(acc[mt][n4][2] + b0, acc[mt][n4][3] + b1);
        }
}

// ---------------- kernel: tensor-core attention, conflict-free ldmatrix swizzle ----------------
__global__ void __launch_bounds__(512, 1) attn_kernel()
{
    extern __shared__ char sm[];
    char* KH = sm;
    char* KL = sm + 16384;
    char* QH = sm + 32768;
    char* QL = sm + 49152;
    char* VH = sm + 65536;
    char* VL = sm + 81920;
    float* OB   = (float*)(sm + 98304);    // [4][64][34]
    float* rmax = (float*)(sm + 133120);   // [64][4]
    float* rsum = (float*)(sm + 134144);   // [64][4]

    int s = blockIdx.x >> 2;
    int h = blockIdx.x & 3;
    int tid = threadIdx.x;
    size_t base = (size_t)s * 256 * EDIM + h * CD;

    #pragma unroll
    for (int i = 0; i < 6; i++) {
        int slot = tid + i * 512;
        int within = slot & 1023;
        int r = within >> 2, gg = within & 3;
        const float* srcb = (i < 2) ? g_k : (i < 4) ? g_q : g_v;
        char* DH = (i < 2) ? KH : (i < 4) ? QH : VH;
        char* DL = (i < 2) ? KL : (i < 4) ? QL : VL;
        const float* src = srcb + base + (size_t)r * EDIM + gg * 8;
        float4 f0 = *(const float4*)src;
        float4 f1 = *(const float4*)(src + 4);
        float fs[8] = {f0.x,f0.y,f0.z,f0.w,f1.x,f1.y,f1.z,f1.w};
        uint4 hi, lo;
        split8(fs, hi, lo);
        int off = ASW(r, gg);
        *(uint4*)(DH + off) = hi;
        *(uint4*)(DL + off) = lo;
    }
    __syncthreads();

    uint32_t kh_s = (uint32_t)__cvta_generic_to_shared(KH);
    uint32_t kl_s = (uint32_t)__cvta_generic_to_shared(KL);
    uint32_t qh_s = (uint32_t)__cvta_generic_to_shared(QH);
    uint32_t ql_s = (uint32_t)__cvta_generic_to_shared(QL);
    uint32_t vh_s = (uint32_t)__cvta_generic_to_shared(VH);
    uint32_t vl_s = (uint32_t)__cvta_generic_to_shared(VL);

    int w = tid >> 5, l = tid & 31;
    int g = l >> 2, l3 = l & 3;
    int mi = l >> 3, rr = l & 7;
    int wm = w >> 2, wn = w & 3;
    const float* mb = g_mb + (size_t)h * RROWS;

    for (int c0 = 0; c0 < 256; c0 += 64) {
        float acc[8][4];
        #pragma unroll
        for (int nf = 0; nf < 8; nf++)
            #pragma unroll
            for (int j = 0; j < 4; j++) acc[nf][j] = 0.0f;

        int r0 = c0 + wm * 16 + g, r1 = r0 + 8;
        int RA = c0 + wm * 16 + (mi & 1) * 8 + rr;

        #pragma unroll
        for (int ks = 0; ks < 2; ks++) {
            uint32_t ah[4], al[4];
            {
                int gA = ks * 2 + (mi >> 1);
                uint32_t offA = ASW(RA, gA);
                LDSM_X4(ah[0], ah[1], ah[2], ah[3], kh_s + offA);
                LDSM_X4(al[0], al[1], al[2], al[3], kl_s + offA);
            }
            #pragma unroll
            for (int np = 0; np < 4; np++) {
                int nB = wn * 64 + np * 16 + (mi >> 1) * 8 + rr;
                int gB = ks * 2 + (mi & 1);
                uint32_t offB = ASW(nB, gB);
                uint32_t b0h, b1h, b2h, b3h, b0l, b1l, b2l, b3l;
                LDSM_X4(b0h, b1h, b2h, b3h, qh_s + offB);
                LDSM_X4(b0l, b1l, b2l, b3l, ql_s + offB);
                uint32_t bhA[2] = {b0h, b1h}, bhB[2] = {b2h, b3h};
                uint32_t blA[2] = {b0l, b1l}, blB[2] = {b2l, b3l};
                MMA_BF16(acc[np * 2],     ah, bhA);
                MMA_BF16(acc[np * 2],     ah, blA);
                MMA_BF16(acc[np * 2],     al, bhA);
                MMA_BF16(acc[np * 2 + 1], ah, bhB);
                MMA_BF16(acc[np * 2 + 1], ah, blB);
                MMA_BF16(acc[np * 2 + 1], al, bhB);
            }
        }

        #pragma unroll
        for (int nf = 0; nf < 8; nf++) {
            int vi = wn * 64 + nf * 8 + l3 * 2;
            float2 m0 = __ldg((const float2*)&mb[(size_t)r0 * 256 + vi]);
            float2 m1 = __ldg((const float2*)&mb[(size_t)r1 * 256 + vi]);
            acc[nf][0] += m0.x; acc[nf][1] += m0.y;
            acc[nf][2] += m1.x; acc[nf][3] += m1.y;
        }

        int lrA = wm * 16 + g, lrB = lrA + 8;
        float mA = -1e30f, mB = -1e30f;
        #pragma unroll
        for (int nf = 0; nf < 8; nf++) {
            mA = fmaxf(mA, fmaxf(acc[nf][0], acc[nf][1]));
            mB = fmaxf(mB, fmaxf(acc[nf][2], acc[nf][3]));
        }
        mA = fmaxf(mA, __shfl_xor_sync(0xffffffffu, mA, 1));
        mA = fmaxf(mA, __shfl_xor_sync(0xffffffffu, mA, 2));
        mB = fmaxf(mB, __shfl_xor_sync(0xffffffffu, mB, 1));
        mB = fmaxf(mB, __shfl_xor_sync(0xffffffffu, mB, 2));
        if (l3 == 0) { rmax[lrA * 4 + wn] = mA; rmax[lrB * 4 + wn] = mB; }
        __syncthreads();
        mA = fmaxf(fmaxf(rmax[lrA*4+0], rmax[lrA*4+1]), fmaxf(rmax[lrA*4+2], rmax[lrA*4+3]));
        mB = fmaxf(fmaxf(rmax[lrB*4+0], rmax[lrB*4+1]), fmaxf(rmax[lrB*4+2], rmax[lrB*4+3]));

        float sA = 0.0f, sB = 0.0f;
        #pragma unroll
        for (int nf = 0; nf < 8; nf++) {
            acc[nf][0] = __expf(acc[nf][0] - mA); sA += acc[nf][0];
            acc[nf][1] = __expf(acc[nf][1] - mA); sA += acc[nf][1];
            acc[nf][2] = __expf(acc[nf][2] - mB); sB += acc[nf][2];
            acc[nf][3] = __expf(acc[nf][3] - mB); sB += acc[nf][3];
        }
        sA += __shfl_xor_sync(0xffffffffu, sA, 1);
        sA += __shfl_xor_sync(0xffffffffu, sA, 2);
        sB += __shfl_xor_sync(0xffffffffu, sB, 1);
        sB += __shfl_xor_sync(0xffffffffu, sB, 2);
        if (l3 == 0) { rsum[lrA * 4 + wn] = sA; rsum[lrB * 4 + wn] = sB; }

        float o[4][4];
        #pragma unroll
        for (int nt = 0; nt < 4; nt++)
            #pragma unroll
            for (int j = 0; j < 4; j++) o[nt][j] = 0.0f;

        #pragma unroll
        for (int ks = 0; ks < 4; ks++) {
            uint32_t ph[4], pl[4];
            ph[0] = pack_bf2(acc[2*ks][0],   acc[2*ks][1]);
            ph[1] = pack_bf2(acc[2*ks][2],   acc[2*ks][3]);
            ph[2] = pack_bf2(acc[2*ks+1][0], acc[2*ks+1][1]);
            ph[3] = pack_bf2(acc[2*ks+1][2], acc[2*ks+1][3]);
            pl[0] = pack_bf2_res(acc[2*ks][0],   acc[2*ks][1],   ph[0]);
            pl[1] = pack_bf2_res(acc[2*ks][2],   acc[2*ks][3],   ph[1]);
            pl[2] = pack_bf2_res(acc[2*ks+1][0], acc[2*ks+1][1], ph[2]);
            pl[3] = pack_bf2_res(acc[2*ks+1][2], acc[2*ks+1][3], ph[3]);

            int vi0 = wn * 64 + ks * 16;
            uint32_t bh[4][2], bl[4][2];
            #pragma unroll
            for (int pp = 0; pp < 2; pp++) {
                int row = vi0 + (mi & 1) * 8 + rr;
                int gg = pp * 2 + (mi >> 1);
                uint32_t offV = ASW(row, gg);
                uint32_t d0, d1, d2, d3;
                LDSM_X4_T(d0, d1, d2, d3, vh_s + offV);
                bh[pp*2+0][0] = d0; bh[pp*2+0][1] = d1;
                bh[pp*2+1][0] = d2; bh[pp*2+1][1] = d3;
                LDSM_X4_T(d0, d1, d2, d3, vl_s + offV);
                bl[pp*2+0][0] = d0; bl[pp*2+0][1] = d1;
                bl[pp*2+1][0] = d2; bl[pp*2+1][1] = d3;
            }
            #pragma unroll
            for (int nt = 0; nt < 4; nt++) {
                MMA_BF16(o[nt], ph, bh[nt]);
                MMA_BF16(o[nt], ph, bl[nt]);
                MMA_BF16(o[nt], pl, bh[nt]);
            }
        }

        {
            float* obw = OB + wn * 2176;
            #pragma unroll
            for (int nt = 0; nt < 4; nt++) {
                *(float2*)&obw[lrA * 34 + nt * 8 + l3 * 2] = make_float2(o[nt][0], o[nt][1]);
                *(float2*)&obw[lrB * 34 + nt * 8 + l3 * 2] = make_float2(o[nt][2], o[nt][3]);
            }
        }
        __syncthreads();

        {
            float invA = 1.0f / (rsum[lrA*4+0] + rsum[lrA*4+1] + rsum[lrA*4+2] + rsum[lrA*4+3]);
            float invB = 1.0f / (rsum[lrB*4+0] + rsum[lrB*4+1] + rsum[lrB*4+2] + rsum[lrB*4+3]);
            int cc = wn * 8 + l3 * 2;
            float2 vA = make_float2(0.0f, 0.0f), vB = make_float2(0.0f, 0.0f);
            #pragma unroll
            for (int j = 0; j < 4; j++) {
                float2 pA = *(float2*)&OB[j * 2176 + lrA * 34 + cc];
                float2 pB = *(float2*)&OB[j * 2176 + lrB * 34 + cc];
                vA.x += pA.x; vA.y += pA.y;
                vB.x += pB.x; vB.y += pB.y;
            }
            size_t iA = base + (size_t)r0 * EDIM + cc;
            size_t iB = base + (size_t)r1 * EDIM + cc;
            float2 fA = *(const float2*)&g_fu[iA];
            float2 fB = *(const float2*)&g_fu[iB];
            *(float2*)&g_ao[iA] = make_float2(vA.x * invA * fA.x, vA.y * invA * fA.y);
            *(float2*)&g_ao[iB] = make_float2(vB.x * invB * fB.x, vB.y * invB * fB.y);
        }
        __syncthreads();
    }
}

// ---------------- host launch ----------------
extern "C" void kernel_launch(void* const* d_in, const int* in_sizes, int n_in,
                              void* d_out, int out_size)
{
    const float* pair_rep = (const float*)d_in[0];
    const float* mask     = (const float*)d_in[1];
    const float* gamma    = (const float*)d_in[2];
    const float* beta     = (const float*)d_in[3];
    const float* Wq       = (const float*)d_in[4];
    const float* Wk       = (const float*)d_in[5];
    const float* Wv       = (const float*)d_in[6];
    const float* Wb       = (const float*)d_in[7];
    const float* Wfu      = (const float*)d_in[8];
    const float* bfu      = (const float*)d_in[9];
    const float* Wo       = (const float*)d_in[10];
    const float* bo       = (const float*)d_in[11];
    float* out = (float*)d_out;

    const int GEMM_SMEM = 128 * 1024;
    const int ATTN_SMEM = 135168;   // 132 KB
    cudaFuncSetAttribute(gemm_proj_kernel, cudaFuncAttributeMaxDynamicSharedMemorySize, GEMM_SMEM);
    cudaFuncSetAttribute(gemm_out_kernel,  cudaFuncAttributeMaxDynamicSharedMemorySize, GEMM_SMEM);
    cudaFuncSetAttribute(attn_kernel,      cudaFuncAttributeMaxDynamicSharedMemorySize, ATTN_SMEM);

    pack_w_kernel<<<(512 * 128 + 128 * 128) / 256, 256>>>(Wq, Wk, Wv, Wfu, Wo);
    gemm_proj_kernel<<<RROWS / 128, 512, GEMM_SMEM>>>(pair_rep, mask, gamma, beta, Wb, bfu);
    attn_kernel<<<LSEQ * NH, 512, ATTN_SMEM>>>();
    gemm_out_kernel<<<RROWS / 128, 512, GEMM_SMEM>>>(bo, out);
}

// round 17
// speedup vs baseline: 2.5522x; 1.0697x over previous
#include <cuda_runtime.h>
#include <cuda_bf16.h>
#include <stdint.h>
#include <math.h>

#define LSEQ 256
#define EDIM 128
#define NH 4
#define CD 32
#define RROWS (LSEQ*LSEQ)   // 65536

// ---------------- scratch (device globals; no allocs allowed) ----------------
__device__ float g_q [RROWS*EDIM];   // pre-scaled by C^-0.5  (the "v-indexed" operand)
__device__ float g_k [RROWS*EDIM];   // the "q-indexed" operand
__device__ float g_v [RROWS*EDIM];
__device__ float g_fu[RROWS*EDIM];   // sigmoid(x@Wfu + bfu)
__device__ float g_mb[NH*RROWS];     // mb[h][q*256+v] = mask[q,v] + bias[q,v,h]
__device__ float g_ao[RROWS*EDIM];   // gated attention output
// packed+transposed+bf16-split weights: [n][k] layout (col-major B for mma)
__device__ __nv_bfloat16 g_Wt_hi [512*128];
__device__ __nv_bfloat16 g_Wt_lo [512*128];
__device__ __nv_bfloat16 g_Wot_hi[128*128];
__device__ __nv_bfloat16 g_Wot_lo[128*128];

// ---------------- mma / ldmatrix helpers ----------------
#define MMA_BF16(d, a, b) \
    asm volatile("mma.sync.aligned.m16n8k16.row.col.f32.bf16.bf16.f32 " \
        "{%0,%1,%2,%3}, {%4,%5,%6,%7}, {%8,%9}, {%0,%1,%2,%3};" \
        : "+f"(d[0]), "+f"(d[1]), "+f"(d[2]), "+f"(d[3]) \
        : "r"(a[0]), "r"(a[1]), "r"(a[2]), "r"(a[3]), "r"(b[0]), "r"(b[1]))

#define LDSM_X4(d0, d1, d2, d3, a) \
    asm volatile("ldmatrix.sync.aligned.m8n8.x4.shared.b16 {%0,%1,%2,%3}, [%4];" \
        : "=r"(d0), "=r"(d1), "=r"(d2), "=r"(d3) : "r"(a))

#define LDSM_X4_T(d0, d1, d2, d3, a) \
    asm volatile("ldmatrix.sync.aligned.m8n8.x4.trans.shared.b16 {%0,%1,%2,%3}, [%4];" \
        : "=r"(d0), "=r"(d1), "=r"(d2), "=r"(d3) : "r"(a))

// named barrier scoped to a 128-thread wm-group
#define GROUP_BAR(id) \
    asm volatile("bar.sync %0, 128;" :: "r"(id) : "memory")

__device__ __forceinline__ uint32_t pack_bf2(float a, float b)
{
    __nv_bfloat162 t = __floats2bfloat162_rn(a, b);
    return *(uint32_t*)&t;
}
__device__ __forceinline__ uint32_t pack_bf2_res(float a, float b, uint32_t hi)
{
    __nv_bfloat162 h = *(__nv_bfloat162*)&hi;
    __nv_bfloat162 t = __floats2bfloat162_rn(
        a - __bfloat162float(__low2bfloat16(h)),
        b - __bfloat162float(__high2bfloat16(h)));
    return *(uint32_t*)&t;
}

// attn tile swizzle: row r (64B pitch), 16B granule g.
// slot(r) = (r&1)*4 + (g ^ ((r>>1)&3)) is a bijection over r mod 8 ->
// every 8-row x 16B ldmatrix access is conflict-free.
#define ASW(r, g) ((r) * 64 + ((((g) ^ (((r) >> 1) & 3))) << 4))

// ---------------- kernel: pack + transpose + bf16-split weights ----------------
__global__ void pack_w_kernel(const float* __restrict__ Wq, const float* __restrict__ Wk,
                              const float* __restrict__ Wv, const float* __restrict__ Wfu,
                              const float* __restrict__ Wo)
{
    int idx = blockIdx.x * blockDim.x + threadIdx.x;
    if (idx < 512 * 128) {
        int n = idx >> 7, k = idx & 127;
        const float* src = (n < 128) ? Wq : (n < 256) ? Wk : (n < 384) ? Wv : Wfu;
        float v = src[k * 128 + (n & 127)];
        __nv_bfloat16 h = __float2bfloat16_rn(v);
        g_Wt_hi[idx] = h;
        g_Wt_lo[idx] = __float2bfloat16_rn(v - __bfloat162float(h));
    } else {
        int j = idx - 512 * 128;
        int n = j >> 7, k = j & 127;
        float v = Wo[k * 128 + n];
        __nv_bfloat16 h = __float2bfloat16_rn(v);
        g_Wot_hi[j] = h;
        g_Wot_lo[j] = __float2bfloat16_rn(v - __bfloat162float(h));
    }
}

// ---------------- conversion helper: 8 floats -> hi/lo bf16 granules ----------------
__device__ __forceinline__ void split8(const float* fs, uint4& hi, uint4& lo)
{
    uint32_t h[4], l[4];
    #pragma unroll
    for (int j = 0; j < 4; j++) {
        __nv_bfloat162 h2 = __floats2bfloat162_rn(fs[2*j], fs[2*j+1]);
        float r0 = fs[2*j]   - __bfloat162float(__low2bfloat16(h2));
        float r1 = fs[2*j+1] - __bfloat162float(__high2bfloat16(h2));
        __nv_bfloat162 l2 = __floats2bfloat162_rn(r0, r1);
        h[j] = *(uint32_t*)&h2;
        l[j] = *(uint32_t*)&l2;
    }
    hi = make_uint4(h[0], h[1], h[2], h[3]);
    lo = make_uint4(l[0], l[1], l[2], l[3]);
}

// swizzled byte offset for row r (256B pitch), 16B granule c  (gemm kernels)
#define SWOFF(r, c) ((r) * 256 + ((((c) ^ ((r) & 7))) << 4))

// ---------------- kernel: fused LN + pair_bias + projection GEMM ----------------
__global__ void __launch_bounds__(512, 1) gemm_proj_kernel(
    const float* __restrict__ pr, const float* __restrict__ mask,
    const float* __restrict__ gamma, const float* __restrict__ beta,
    const float* __restrict__ Wb, const float* __restrict__ bfu)
{
    extern __shared__ char smem[];
    char* As_hi = smem;
    char* As_lo = smem + 32768;
    char* Bs_hi = smem + 65536;
    char* Bs_lo = smem + 98304;

    int m0 = blockIdx.x * 128;
    int tid = threadIdx.x;
    int cg = tid & 15, rb = tid >> 4;

    float4 gm0 = __ldg((const float4*)&gamma[cg * 8]);
    float4 gm1 = __ldg((const float4*)&gamma[cg * 8 + 4]);
    float4 bt0 = __ldg((const float4*)&beta [cg * 8]);
    float4 bt1 = __ldg((const float4*)&beta [cg * 8 + 4]);
    float gms[8] = {gm0.x,gm0.y,gm0.z,gm0.w,gm1.x,gm1.y,gm1.z,gm1.w};
    float bts[8] = {bt0.x,bt0.y,bt0.z,bt0.w,bt1.x,bt1.y,bt1.z,bt1.w};

    #pragma unroll
    for (int i = 0; i < 4; i++) {
        int r = rb + i * 32;
        const float* src = &pr[(size_t)(m0 + r) * EDIM + cg * 8];
        float4 f0 = *(const float4*)src;
        float4 f1 = *(const float4*)(src + 4);
        float fs[8] = {f0.x,f0.y,f0.z,f0.w,f1.x,f1.y,f1.z,f1.w};

        float s = 0.0f, s2 = 0.0f;
        #pragma unroll
        for (int j = 0; j < 8; j++) { s += fs[j]; s2 += fs[j] * fs[j]; }
        #pragma unroll
        for (int o = 8; o; o >>= 1) {
            s  += __shfl_xor_sync(0xffffffffu, s,  o);
            s2 += __shfl_xor_sync(0xffffffffu, s2, o);
        }
        float mu  = s * (1.0f / EDIM);
        float var = s2 * (1.0f / EDIM) - mu * mu;
        float inv = rsqrtf(var + 1e-5f);

        float b0 = 0.0f, b1 = 0.0f, b2 = 0.0f, b3 = 0.0f;
        #pragma unroll
        for (int j = 0; j < 8; j++) {
            fs[j] = (fs[j] - mu) * inv * gms[j] + bts[j];
            int c = cg * 8 + j;
            b0 += fs[j] * __ldg(&Wb[c * 4 + 0]);
            b1 += fs[j] * __ldg(&Wb[c * 4 + 1]);
            b2 += fs[j] * __ldg(&Wb[c * 4 + 2]);
            b3 += fs[j] * __ldg(&Wb[c * 4 + 3]);
        }
        #pragma unroll
        for (int o = 8; o; o >>= 1) {
            b0 += __shfl_xor_sync(0xffffffffu, b0, o);
            b1 += __shfl_xor_sync(0xffffffffu, b1, o);
            b2 += __shfl_xor_sync(0xffffffffu, b2, o);
            b3 += __shfl_xor_sync(0xffffffffu, b3, o);
        }
        if (cg == 0) {
            int gr = m0 + r;
            float mk = __ldg(&mask[gr]);
            g_mb[0 * RROWS + gr] = mk + b0;
            g_mb[1 * RROWS + gr] = mk + b1;
            g_mb[2 * RROWS + gr] = mk + b2;
            g_mb[3 * RROWS + gr] = mk + b3;
        }

        uint4 hi, lo;
        split8(fs, hi, lo);
        int off = SWOFF(r, cg);
        *(uint4*)(As_hi + off) = hi;
        *(uint4*)(As_lo + off) = lo;
    }

    int w = tid >> 5, l = tid & 31;
    int mw = (w & 3) * 32, nw = (w >> 2) * 32;
    int g = l >> 2, c4 = (l & 3) * 4;
    const float qscale = 0.17677669529663687f;

    for (int nt = 0; nt < 4; nt++) {
        __syncthreads();
        #pragma unroll
        for (int i = 0; i < 4; i++) {
            int r = rb + i * 32;
            int off = SWOFF(r, cg);
            size_t gi = (size_t)(nt * 128 + r) * 128 + cg * 8;
            *(uint4*)(Bs_hi + off) = *(const uint4*)(g_Wt_hi + gi);
            *(uint4*)(Bs_lo + off) = *(const uint4*)(g_Wt_lo + gi);
        }
        __syncthreads();

        float acc[2][4][4];
        #pragma unroll
        for (int mt = 0; mt < 2; mt++)
            #pragma unroll
            for (int n4 = 0; n4 < 4; n4++)
                #pragma unroll
                for (int j = 0; j < 4; j++) acc[mt][n4][j] = 0.0f;

        #pragma unroll
        for (int ks = 0; ks < 8; ks++) {
            uint32_t ah[2][4], al[2][4], bh[4][2], bl[4][2];
            #pragma unroll
            for (int mt = 0; mt < 2; mt++) {
                int r0 = mw + mt * 16 + g, r1 = r0 + 8;
                int ga = ks * 2, gb = ks * 2 + 1;
                int o0 = SWOFF(r0, ga) + c4, o1 = SWOFF(r1, ga) + c4;
                int o2 = SWOFF(r0, gb) + c4, o3 = SWOFF(r1, gb) + c4;
                ah[mt][0] = *(uint32_t*)(As_hi + o0); ah[mt][1] = *(uint32_t*)(As_hi + o1);
                ah[mt][2] = *(uint32_t*)(As_hi + o2); ah[mt][3] = *(uint32_t*)(As_hi + o3);
                al[mt][0] = *(uint32_t*)(As_lo + o0); al[mt][1] = *(uint32_t*)(As_lo + o1);
                al[mt][2] = *(uint32_t*)(As_lo + o2); al[mt][3] = *(uint32_t*)(As_lo + o3);
            }
            #pragma unroll
            for (int n4 = 0; n4 < 4; n4++) {
                int n = nw + n4 * 8 + g;
                int o0 = SWOFF(n, ks * 2) + c4, o1 = SWOFF(n, ks * 2 + 1) + c4;
                bh[n4][0] = *(uint32_t*)(Bs_hi + o0); bh[n4][1] = *(uint32_t*)(Bs_hi + o1);
                bl[n4][0] = *(uint32_t*)(Bs_lo + o0); bl[n4][1] = *(uint32_t*)(Bs_lo + o1);
            }
            #pragma unroll
            for (int mt = 0; mt < 2; mt++)
                #pragma unroll
                for (int n4 = 0; n4 < 4; n4++) {
                    MMA_BF16(acc[mt][n4], ah[mt], bh[n4]);
                    MMA_BF16(acc[mt][n4], ah[mt], bl[n4]);
                    MMA_BF16(acc[mt][n4], al[mt], bh[n4]);
                }
        }

        float* dst = (nt == 0) ? g_q : (nt == 1) ? g_k : (nt == 2) ? g_v : g_fu;
        #pragma unroll
        for (int mt = 0; mt < 2; mt++)
            #pragma unroll
            for (int n4 = 0; n4 < 4; n4++) {
                int m = m0 + mw + mt * 16 + g;
                int ncol = nw + n4 * 8 + (l & 3) * 2;
                float v0 = acc[mt][n4][0], v1 = acc[mt][n4][1];
                float v2 = acc[mt][n4][2], v3 = acc[mt][n4][3];
                if (nt == 0) { v0 *= qscale; v1 *= qscale; v2 *= qscale; v3 *= qscale; }
                if (nt == 3) {
                    float bf0 = bfu[ncol], bf1 = bfu[ncol + 1];
                    v0 = 1.0f / (1.0f + __expf(-(v0 + bf0)));
                    v1 = 1.0f / (1.0f + __expf(-(v1 + bf1)));
                    v2 = 1.0f / (1.0f + __expf(-(v2 + bf0)));
                    v3 = 1.0f / (1.0f + __expf(-(v3 + bf1)));
                }
                *(float2*)&dst[(size_t)m * EDIM + ncol]       = make_float2(v0, v1);
                *(float2*)&dst[(size_t)(m + 8) * EDIM + ncol] = make_float2(v2, v3);
            }
    }
}

// ---------------- kernel: output GEMM via bf16-split tensor cores ----------------
__global__ void __launch_bounds__(512, 1) gemm_out_kernel(
    const float* __restrict__ bo, float* __restrict__ out)
{
    extern __shared__ char smem[];
    char* As_hi = smem;
    char* As_lo = smem + 32768;
    char* Bs_hi = smem + 65536;
    char* Bs_lo = smem + 98304;

    int m0 = blockIdx.x * 128;
    int tid = threadIdx.x;
    int cg = tid & 15, rb = tid >> 4;

    #pragma unroll
    for (int i = 0; i < 4; i++) {
        int r = rb + i * 32;
        const float* src = &g_ao[(size_t)(m0 + r) * EDIM + cg * 8];
        float4 f0 = *(const float4*)src;
        float4 f1 = *(const float4*)(src + 4);
        float fs[8] = {f0.x,f0.y,f0.z,f0.w,f1.x,f1.y,f1.z,f1.w};
        uint4 hi, lo;
        split8(fs, hi, lo);
        int off = SWOFF(r, cg);
        *(uint4*)(As_hi + off) = hi;
        *(uint4*)(As_lo + off) = lo;

        size_t gi = (size_t)r * 128 + cg * 8;
        *(uint4*)(Bs_hi + off) = *(const uint4*)(g_Wot_hi + gi);
        *(uint4*)(Bs_lo + off) = *(const uint4*)(g_Wot_lo + gi);
    }
    __syncthreads();

    int w = tid >> 5, l = tid & 31;
    int mw = (w & 3) * 32, nw = (w >> 2) * 32;
    int g = l >> 2, c4 = (l & 3) * 4;

    float acc[2][4][4];
    #pragma unroll
    for (int mt = 0; mt < 2; mt++)
        #pragma unroll
        for (int n4 = 0; n4 < 4; n4++)
            #pragma unroll
            for (int j = 0; j < 4; j++) acc[mt][n4][j] = 0.0f;

    #pragma unroll
    for (int ks = 0; ks < 8; ks++) {
        uint32_t ah[2][4], al[2][4], bh[4][2], bl[4][2];
        #pragma unroll
        for (int mt = 0; mt < 2; mt++) {
            int r0 = mw + mt * 16 + g, r1 = r0 + 8;
            int ga = ks * 2, gb = ks * 2 + 1;
            int o0 = SWOFF(r0, ga) + c4, o1 = SWOFF(r1, ga) + c4;
            int o2 = SWOFF(r0, gb) + c4, o3 = SWOFF(r1, gb) + c4;
            ah[mt][0] = *(uint32_t*)(As_hi + o0); ah[mt][1] = *(uint32_t*)(As_hi + o1);
            ah[mt][2] = *(uint32_t*)(As_hi + o2); ah[mt][3] = *(uint32_t*)(As_hi + o3);
            al[mt][0] = *(uint32_t*)(As_lo + o0); al[mt][1] = *(uint32_t*)(As_lo + o1);
            al[mt][2] = *(uint32_t*)(As_lo + o2); al[mt][3] = *(uint32_t*)(As_lo + o3);
        }
        #pragma unroll
        for (int n4 = 0; n4 < 4; n4++) {
            int n = nw + n4 * 8 + g;
            int o0 = SWOFF(n, ks * 2) + c4, o1 = SWOFF(n, ks * 2 + 1) + c4;
            bh[n4][0] = *(uint32_t*)(Bs_hi + o0); bh[n4][1] = *(uint32_t*)(Bs_hi + o1);
            bl[n4][0] = *(uint32_t*)(Bs_lo + o0); bl[n4][1] = *(uint32_t*)(Bs_lo + o1);
        }
        #pragma unroll
        for (int mt = 0; mt < 2; mt++)
            #pragma unroll
            for (int n4 = 0; n4 < 4; n4++) {
                MMA_BF16(acc[mt][n4], ah[mt], bh[n4]);
                MMA_BF16(acc[mt][n4], ah[mt], bl[n4]);
                MMA_BF16(acc[mt][n4], al[mt], bh[n4]);
            }
    }

    #pragma unroll
    for (int mt = 0; mt < 2; mt++)
        #pragma unroll
        for (int n4 = 0; n4 < 4; n4++) {
            int m = m0 + mw + mt * 16 + g;
            int ncol = nw + n4 * 8 + (l & 3) * 2;
            float b0 = bo[ncol], b1 = bo[ncol + 1];
            *(float2*)&out[(size_t)m * EDIM + ncol] =
                make_float2(acc[mt][n4][0] + b0, acc[mt][n4][1] + b1);
            *(float2*)&out[(size_t)(m + 8) * EDIM + ncol] =
                make_float2(acc[mt][n4][2] + b0, acc[mt][n4][3] + b1);
        }
}

// ---------------- kernel: tensor-core attention, wm-group named barriers ----------------
__global__ void __launch_bounds__(512, 1) attn_kernel()
{
    extern __shared__ char sm[];
    char* KH = sm;
    char* KL = sm + 16384;
    char* QH = sm + 32768;
    char* QL = sm + 49152;
    char* VH = sm + 65536;
    char* VL = sm + 81920;
    float* OB   = (float*)(sm + 98304);    // [4][64][34]
    float* rmax = (float*)(sm + 133120);   // [64][4]
    float* rsum = (float*)(sm + 134144);   // [64][4]

    int s = blockIdx.x >> 2;
    int h = blockIdx.x & 3;
    int tid = threadIdx.x;
    size_t base = (size_t)s * 256 * EDIM + h * CD;

    #pragma unroll
    for (int i = 0; i < 6; i++) {
        int slot = tid + i * 512;
        int within = slot & 1023;
        int r = within >> 2, gg = within & 3;
        const float* srcb = (i < 2) ? g_k : (i < 4) ? g_q : g_v;
        char* DH = (i < 2) ? KH : (i < 4) ? QH : VH;
        char* DL = (i < 2) ? KL : (i < 4) ? QL : VL;
        const float* src = srcb + base + (size_t)r * EDIM + gg * 8;
        float4 f0 = *(const float4*)src;
        float4 f1 = *(const float4*)(src + 4);
        float fs[8] = {f0.x,f0.y,f0.z,f0.w,f1.x,f1.y,f1.z,f1.w};
        uint4 hi, lo;
        split8(fs, hi, lo);
        int off = ASW(r, gg);
        *(uint4*)(DH + off) = hi;
        *(uint4*)(DL + off) = lo;
    }
    __syncthreads();

    uint32_t kh_s = (uint32_t)__cvta_generic_to_shared(KH);
    uint32_t kl_s = (uint32_t)__cvta_generic_to_shared(KL);
    uint32_t qh_s = (uint32_t)__cvta_generic_to_shared(QH);
    uint32_t ql_s = (uint32_t)__cvta_generic_to_shared(QL);
    uint32_t vh_s = (uint32_t)__cvta_generic_to_shared(VH);
    uint32_t vl_s = (uint32_t)__cvta_generic_to_shared(VL);

    int w = tid >> 5, l = tid & 31;
    int g = l >> 2, l3 = l & 3;
    int mi = l >> 3, rr = l & 7;
    int wm = w >> 2, wn = w & 3;
    int gbar = 1 + wm;                 // named barrier id for this 128-thread wm-group
    const float* mb = g_mb + (size_t)h * RROWS;

    for (int c0 = 0; c0 < 256; c0 += 64) {
        float acc[8][4];
        #pragma unroll
        for (int nf = 0; nf < 8; nf++)
            #pragma unroll
            for (int j = 0; j < 4; j++) acc[nf][j] = 0.0f;

        int r0 = c0 + wm * 16 + g, r1 = r0 + 8;
        int RA = c0 + wm * 16 + (mi & 1) * 8 + rr;

        #pragma unroll
        for (int ks = 0; ks < 2; ks++) {
            uint32_t ah[4], al[4];
            {
                int gA = ks * 2 + (mi >> 1);
                uint32_t offA = ASW(RA, gA);
                LDSM_X4(ah[0], ah[1], ah[2], ah[3], kh_s + offA);
                LDSM_X4(al[0], al[1], al[2], al[3], kl_s + offA);
            }
            #pragma unroll
            for (int np = 0; np < 4; np++) {
                int nB = wn * 64 + np * 16 + (mi >> 1) * 8 + rr;
                int gB = ks * 2 + (mi & 1);
                uint32_t offB = ASW(nB, gB);
                uint32_t b0h, b1h, b2h, b3h, b0l, b1l, b2l, b3l;
                LDSM_X4(b0h, b1h, b2h, b3h, qh_s + offB);
                LDSM_X4(b0l, b1l, b2l, b3l, ql_s + offB);
                uint32_t bhA[2] = {b0h, b1h}, bhB[2] = {b2h, b3h};
                uint32_t blA[2] = {b0l, b1l}, blB[2] = {b2l, b3l};
                MMA_BF16(acc[np * 2],     ah, bhA);
                MMA_BF16(acc[np * 2],     ah, blA);
                MMA_BF16(acc[np * 2],     al, bhA);
                MMA_BF16(acc[np * 2 + 1], ah, bhB);
                MMA_BF16(acc[np * 2 + 1], ah, blB);
                MMA_BF16(acc[np * 2 + 1], al, bhB);
            }
        }

        #pragma unroll
        for (int nf = 0; nf < 8; nf++) {
            int vi = wn * 64 + nf * 8 + l3 * 2;
            float2 m0 = __ldg((const float2*)&mb[(size_t)r0 * 256 + vi]);
            float2 m1 = __ldg((const float2*)&mb[(size_t)r1 * 256 + vi]);
            acc[nf][0] += m0.x; acc[nf][1] += m0.y;
            acc[nf][2] += m1.x; acc[nf][3] += m1.y;
        }

        int lrA = wm * 16 + g, lrB = lrA + 8;
        float mA = -1e30f, mB = -1e30f;
        #pragma unroll
        for (int nf = 0; nf < 8; nf++) {
            mA = fmaxf(mA, fmaxf(acc[nf][0], acc[nf][1]));
            mB = fmaxf(mB, fmaxf(acc[nf][2], acc[nf][3]));
        }
        mA = fmaxf(mA, __shfl_xor_sync(0xffffffffu, mA, 1));
        mA = fmaxf(mA, __shfl_xor_sync(0xffffffffu, mA, 2));
        mB = fmaxf(mB, __shfl_xor_sync(0xffffffffu, mB, 1));
        mB = fmaxf(mB, __shfl_xor_sync(0xffffffffu, mB, 2));
        if (l3 == 0) { rmax[lrA * 4 + wn] = mA; rmax[lrB * 4 + wn] = mB; }
        GROUP_BAR(gbar);
        mA = fmaxf(fmaxf(rmax[lrA*4+0], rmax[lrA*4+1]), fmaxf(rmax[lrA*4+2], rmax[lrA*4+3]));
        mB = fmaxf(fmaxf(rmax[lrB*4+0], rmax[lrB*4+1]), fmaxf(rmax[lrB*4+2], rmax[lrB*4+3]));

        float sA = 0.0f, sB = 0.0f;
        #pragma unroll
        for (int nf = 0; nf < 8; nf++) {
            acc[nf][0] = __expf(acc[nf][0] - mA); sA += acc[nf][0];
            acc[nf][1] = __expf(acc[nf][1] - mA); sA += acc[nf][1];
            acc[nf][2] = __expf(acc[nf][2] - mB); sB += acc[nf][2];
            acc[nf][3] = __expf(acc[nf][3] - mB); sB += acc[nf][3];
        }
        sA += __shfl_xor_sync(0xffffffffu, sA, 1);
        sA += __shfl_xor_sync(0xffffffffu, sA, 2);
        sB += __shfl_xor_sync(0xffffffffu, sB, 1);
        sB += __shfl_xor_sync(0xffffffffu, sB, 2);
        if (l3 == 0) { rsum[lrA * 4 + wn] = sA; rsum[lrB * 4 + wn] = sB; }

        float o[4][4];
        #pragma unroll
        for (int nt = 0; nt < 4; nt++)
            #pragma unroll
            for (int j = 0; j < 4; j++) o[nt][j] = 0.0f;

        #pragma unroll
        for (int ks = 0; ks < 4; ks++) {
            uint32_t ph[4], pl[4];
            ph[0] = pack_bf2(acc[2*ks][0],   acc[2*ks][1]);
            ph[1] = pack_bf2(acc[2*ks][2],   acc[2*ks][3]);
            ph[2] = pack_bf2(acc[2*ks+1][0], acc[2*ks+1][1]);
            ph[3] = pack_bf2(acc[2*ks+1][2], acc[2*ks+1][3]);
            pl[0] = pack_bf2_res(acc[2*ks][0],   acc[2*ks][1],   ph[0]);
            pl[1] = pack_bf2_res(acc[2*ks][2],   acc[2*ks][3],   ph[1]);
            pl[2] = pack_bf2_res(acc[2*ks+1][0], acc[2*ks+1][1], ph[2]);
            pl[3] = pack_bf2_res(acc[2*ks+1][2], acc[2*ks+1][3], ph[3]);

            int vi0 = wn * 64 + ks * 16;
            uint32_t bh[4][2], bl[4][2];
            #pragma unroll
            for (int pp = 0; pp < 2; pp++) {
                int row = vi0 + (mi & 1) * 8 + rr;
                int gg = pp * 2 + (mi >> 1);
                uint32_t offV = ASW(row, gg);
                uint32_t d0, d1, d2, d3;
                LDSM_X4_T(d0, d1, d2, d3, vh_s + offV);
                bh[pp*2+0][0] = d0; bh[pp*2+0][1] = d1;
                bh[pp*2+1][0] = d2; bh[pp*2+1][1] = d3;
                LDSM_X4_T(d0, d1, d2, d3, vl_s + offV);
                bl[pp*2+0][0] = d0; bl[pp*2+0][1] = d1;
                bl[pp*2+1][0] = d2; bl[pp*2+1][1] = d3;
            }
            #pragma unroll
            for (int nt = 0; nt < 4; nt++) {
                MMA_BF16(o[nt], ph, bh[nt]);
                MMA_BF16(o[nt], ph, bl[nt]);
                MMA_BF16(o[nt], pl, bh[nt]);
            }
        }

        {
            float* obw = OB + wn * 2176;
            #pragma unroll
            for (int nt = 0; nt < 4; nt++) {
                *(float2*)&obw[lrA * 34 + nt * 8 + l3 * 2] = make_float2(o[nt][0], o[nt][1]);
                *(float2*)&obw[lrB * 34 + nt * 8 + l3 * 2] = make_float2(o[nt][2], o[nt][3]);
            }
        }
        GROUP_BAR(gbar);

        {
            float invA = 1.0f / (rsum[lrA*4+0] + rsum[lrA*4+1] + rsum[lrA*4+2] + rsum[lrA*4+3]);
            float invB = 1.0f / (rsum[lrB*4+0] + rsum[lrB*4+1] + rsum[lrB*4+2] + rsum[lrB*4+3]);
            int cc = wn * 8 + l3 * 2;
            float2 vA = make_float2(0.0f, 0.0f), vB = make_float2(0.0f, 0.0f);
            #pragma unroll
            for (int j = 0; j < 4; j++) {
                float2 pA = *(float2*)&OB[j * 2176 + lrA * 34 + cc];
                float2 pB = *(float2*)&OB[j * 2176 + lrB * 34 + cc];
                vA.x += pA.x; vA.y += pA.y;
                vB.x += pB.x; vB.y += pB.y;
            }
            size_t iA = base + (size_t)r0 * EDIM + cc;
            size_t iB = base + (size_t)r1 * EDIM + cc;
            float2 fA = *(const float2*)&g_fu[iA];
            float2 fB = *(const float2*)&g_fu[iB];
            *(float2*)&g_ao[iA] = make_float2(vA.x * invA * fA.x, vA.y * invA * fA.y);
            *(float2*)&g_ao[iB] = make_float2(vB.x * invB * fB.x, vB.y * invB * fB.y);
        }
        GROUP_BAR(gbar);
    }
}

// ---------------- host launch ----------------
extern "C" void kernel_launch(void* const* d_in, const int* in_sizes, int n_in,
                              void* d_out, int out_size)
{
    const float* pair_rep = (const float*)d_in[0];
    const float* mask     = (const float*)d_in[1];
    const float* gamma    = (const float*)d_in[2];
    const float* beta     = (const float*)d_in[3];
    const float* Wq       = (const float*)d_in[4];
    const float* Wk       = (const float*)d_in[5];
    const float* Wv       = (const float*)d_in[6];
    const float* Wb       = (const float*)d_in[7];
    const float* Wfu      = (const float*)d_in[8];
    const float* bfu      = (const float*)d_in[9];
    const float* Wo       = (const float*)d_in[10];
    const float* bo       = (const float*)d_in[11];
    float* out = (float*)d_out;

    const int GEMM_SMEM = 128 * 1024;
    const int ATTN_SMEM = 135168;   // 132 KB
    cudaFuncSetAttribute(gemm_proj_kernel, cudaFuncAttributeMaxDynamicSharedMemorySize, GEMM_SMEM);
    cudaFuncSetAttribute(gemm_out_kernel,  cudaFuncAttributeMaxDynamicSharedMemorySize, GEMM_SMEM);
    cudaFuncSetAttribute(attn_kernel,      cudaFuncAttributeMaxDynamicSharedMemorySize, ATTN_SMEM);

    pack_w_kernel<<<(512 * 128 + 128 * 128) / 256, 256>>>(Wq, Wk, Wv, Wfu, Wo);
    gemm_proj_kernel<<<RROWS / 128, 512, GEMM_SMEM>>>(pair_rep, mask, gamma, beta, Wb, bfu);
    attn_kernel<<<LSEQ * NH, 512, ATTN_SMEM>>>();
    gemm_out_kernel<<<RROWS / 128, 512, GEMM_SMEM>>>(bo, out);
}